// round 7
// baseline (speedup 1.0000x reference)
#include <cuda_runtime.h>
#include <cuda_bf16.h>
#include <cstdint>

#define B_     2
#define S_     2048
#define E_     256
#define H_     8
#define DH_    256
#define INNER_ 2048
#define QKVW_  (3*INNER_)   // 6144
#define DFF_   1024
#define BSZ    (B_*S_)
#define EPS_   1e-6f

typedef __nv_bfloat16 bf16;

// ---------------- device scratch ----------------
__device__ bf16  g_xh [(size_t)BSZ * E_];
__device__ bf16  g_xl [(size_t)BSZ * E_];
__device__ bf16  g_wqkvT_h[(size_t)QKVW_ * E_];   // packed [Wq;Wk;Wv]^T
__device__ bf16  g_wqkvT_l[(size_t)QKVW_ * E_];
__device__ bf16  g_woT_h[(size_t)E_ * INNER_];
__device__ bf16  g_woT_l[(size_t)E_ * INNER_];
__device__ bf16  g_w1T_h[(size_t)DFF_ * E_];
__device__ bf16  g_w1T_l[(size_t)DFF_ * E_];
__device__ bf16  g_w2T_h[(size_t)E_ * DFF_];
__device__ bf16  g_w2T_l[(size_t)E_ * DFF_];
__device__ bf16  g_qkvh[(size_t)BSZ * QKVW_];     // q|k|v packed, ld=6144
__device__ bf16  g_qkvl[(size_t)BSZ * QKVW_];
__device__ bf16  g_vth[(size_t)BSZ * INNER_];     // V^T per (b,h): [B*H][DH][S]
__device__ bf16  g_vtl[(size_t)BSZ * INNER_];
__device__ bf16  g_oh [(size_t)BSZ * INNER_];
__device__ bf16  g_ol [(size_t)BSZ * INNER_];
__device__ float g_t1 [(size_t)BSZ * E_];
__device__ float g_hf [(size_t)BSZ * E_];
__device__ bf16  g_hh [(size_t)BSZ * E_];
__device__ bf16  g_hl [(size_t)BSZ * E_];
__device__ bf16  g_ffh[(size_t)BSZ * DFF_];
__device__ bf16  g_ffl[(size_t)BSZ * DFF_];
__device__ float g_t2 [(size_t)BSZ * E_];

// ---------------- helpers ----------------
__device__ __forceinline__ uint32_t smem_u32(const void* p) {
    uint32_t a;
    asm("{ .reg .u64 t; cvta.to.shared.u64 t, %1; cvt.u32.u64 %0, t; }"
        : "=r"(a) : "l"(p));
    return a;
}
__device__ __forceinline__ void ldsm_x4(uint32_t* r, uint32_t a) {
    asm volatile("ldmatrix.sync.aligned.m8n8.x4.shared.b16 {%0,%1,%2,%3}, [%4];"
                 : "=r"(r[0]), "=r"(r[1]), "=r"(r[2]), "=r"(r[3]) : "r"(a));
}
__device__ __forceinline__ void mma16816(float* c, const uint32_t* a,
                                         uint32_t b0, uint32_t b1) {
    asm volatile(
        "mma.sync.aligned.m16n8k16.row.col.f32.bf16.bf16.f32 "
        "{%0,%1,%2,%3}, {%4,%5,%6,%7}, {%8,%9}, {%0,%1,%2,%3};"
        : "+f"(c[0]), "+f"(c[1]), "+f"(c[2]), "+f"(c[3])
        : "r"(a[0]), "r"(a[1]), "r"(a[2]), "r"(a[3]), "r"(b0), "r"(b1));
}
#define CP16(dst, src) \
    asm volatile("cp.async.cg.shared.global [%0], [%1], 16;" :: "r"(dst), "l"(src) : "memory")
#define CP_COMMIT  asm volatile("cp.async.commit_group;" ::: "memory")
#define CP_WAIT0   asm volatile("cp.async.wait_group 0;" ::: "memory")
#define CP_WAIT1   asm volatile("cp.async.wait_group 1;" ::: "memory")

__device__ __forceinline__ uint32_t packbf2(float x, float y) {
    __nv_bfloat162 t = __floats2bfloat162_rn(x, y);
    return *(uint32_t*)&t;
}

// ================= flash attention =================
// grid (S_/128, B_*H_), 256 thr (8 warps x m16). Q hi/lo resident,
// K and V both double-buffered at KVBLK=16, one cp.async group per iter.
#define QBLK   128
#define KVBLK  16
#define NKVT   (S_/KVBLK)      // 128
#define FO_QL  65536
#define FO_K   131072          // 2 slots x 16384 (hi 8192 | lo 8192)
#define FO_V   163840          // 2 slots x 16384
#define F_SMEM 196608

__global__ void __launch_bounds__(256)
flash_kernel(const bf16* __restrict__ qkvh, const bf16* __restrict__ qkvl,
             const bf16* __restrict__ vth_g, const bf16* __restrict__ vtl_g,
             bf16* __restrict__ oh_g, bf16* __restrict__ ol_g)
{
    extern __shared__ __align__(128) char sm[];
    const uint32_t sb = smem_u32(sm);
    const int tid = threadIdx.x, wid = tid >> 5, lane = tid & 31;
    const int bh = blockIdx.y;
    const int b = bh >> 3, hd = bh & 7;
    const int q0 = blockIdx.x * QBLK;

    // K tile loader: 1024 chunks (16 rows x 32 x hi/lo)
    auto load_k = [&](int kv0, uint32_t slot) {
        #pragma unroll
        for (int it = 0; it < 4; it++) {
            int c = tid + it * 256;
            int split = c >> 9; int cc = c & 511;
            int row = cc >> 5, kc = cc & 31;
            const bf16* src = qkvh + (split ? (size_t)BSZ * QKVW_ : 0)   // hi->qkvh, lo->qkvl
                ;
            // note: qkvl = qkvh + BSZ*QKVW_ only if contiguous; use explicit pointers instead
            src = (split ? qkvl : qkvh)
                + ((size_t)(b * S_ + kv0 + row) * QKVW_ + 2048 + hd * 256 + kc * 8);
            CP16(slot + split * 8192 + row * 512 + (uint32_t)((kc ^ (row & 7)) << 4), src);
        }
    };
    // V tile loader: 1024 chunks (256 rows x 2 x hi/lo)
    auto load_v = [&](int kv0, uint32_t slot) {
        #pragma unroll
        for (int it = 0; it < 4; it++) {
            int c = tid + it * 256;
            int split = c >> 9; int cc = c & 511;
            int row = cc >> 1, kc = cc & 1;
            const bf16* src = (split ? vtl_g : vth_g)
                + ((size_t)bh * DH_ * S_ + (size_t)row * S_ + kv0 + kc * 8);
            CP16(slot + split * 8192 + row * 32 + (uint32_t)((kc ^ ((row >> 2) & 1)) << 4), src);
        }
    };

    // ---- prologue: G0 = {Q, K0, V0}, G1 = {K1, V1} ----
    #pragma unroll
    for (int it = 0; it < 32; it++) {                 // Q: 8192 x 16B
        int c = tid + it * 256;
        int split = c >> 12; int cc = c & 4095;
        int row = cc >> 5, kc = cc & 31;
        const bf16* src = (split ? qkvl : qkvh)
            + ((size_t)(b * S_ + q0 + row) * QKVW_ + hd * 256 + kc * 8);
        CP16(sb + split * 65536 + row * 512 + (uint32_t)((kc ^ (row & 7)) << 4), src);
    }
    load_k(0, sb + FO_K);
    load_v(0, sb + FO_V);
    CP_COMMIT;
    load_k(KVBLK, sb + FO_K + 16384);
    load_v(KVBLK, sb + FO_V + 16384);
    CP_COMMIT;

    const int wm    = wid * 16;
    const int a_row = wm + (lane & 15);
    const uint32_t a_rowoff = (uint32_t)(a_row * 512);
    const int a_r7  = a_row & 7;
    const int a_hb  = lane >> 4;
    const int b_row = (lane & 7) + ((lane >> 4) & 1) * 8;
    const int b_kb  = (lane >> 3) & 1;
    const uint32_t koff_base = (uint32_t)(b_row * 512);
    const int k_r7  = b_row & 7;

    float o[32][4];
    #pragma unroll
    for (int i = 0; i < 32; i++) { o[i][0]=0.f; o[i][1]=0.f; o[i][2]=0.f; o[i][3]=0.f; }
    float m0 = -1e30f, m1 = -1e30f, l0 = 0.f, l1 = 0.f;

    for (int i = 0; i < NKVT; i++) {
        CP_WAIT1;                       // tiles for iter i are resident
        __syncthreads();
        const uint32_t kbs = sb + FO_K + (uint32_t)((i & 1) * 16384);
        const uint32_t vbs = sb + FO_V + (uint32_t)((i & 1) * 16384);

        // ==== S = (Qh+Ql)(Kh+Kl)^T  [m16 x 16] ====
        float s[2][4];
        s[0][0]=0.f; s[0][1]=0.f; s[0][2]=0.f; s[0][3]=0.f;
        s[1][0]=0.f; s[1][1]=0.f; s[1][2]=0.f; s[1][3]=0.f;
        #pragma unroll
        for (int ks = 0; ks < 16; ks++) {
            const uint32_t aq = a_rowoff + (uint32_t)(((2 * ks + a_hb) ^ a_r7) << 4);
            uint32_t ah4[4], al4[4], kh4[4], kl4[4];
            ldsm_x4(ah4, sb + aq);
            ldsm_x4(al4, sb + FO_QL + aq);
            const uint32_t ko = koff_base + (uint32_t)(((2 * ks + b_kb) ^ k_r7) << 4);
            ldsm_x4(kh4, kbs + ko);
            ldsm_x4(kl4, kbs + 8192 + ko);
            mma16816(s[0], ah4, kh4[0], kh4[1]);
            mma16816(s[1], ah4, kh4[2], kh4[3]);
            mma16816(s[0], ah4, kl4[0], kl4[1]);
            mma16816(s[1], ah4, kl4[2], kl4[3]);
            mma16816(s[0], al4, kh4[0], kh4[1]);
            mma16816(s[1], al4, kh4[2], kh4[3]);
        }

        // ==== online softmax (rows g=lane>>2, g+8) ====
        float mx0 = fmaxf(fmaxf(s[0][0], s[0][1]), fmaxf(s[1][0], s[1][1])) * 0.0625f;
        float mx1 = fmaxf(fmaxf(s[0][2], s[0][3]), fmaxf(s[1][2], s[1][3])) * 0.0625f;
        #pragma unroll
        for (int nt = 0; nt < 2; nt++) {
            s[nt][0] *= 0.0625f; s[nt][1] *= 0.0625f;
            s[nt][2] *= 0.0625f; s[nt][3] *= 0.0625f;
        }
        mx0 = fmaxf(mx0, __shfl_xor_sync(0xffffffffu, mx0, 1));
        mx0 = fmaxf(mx0, __shfl_xor_sync(0xffffffffu, mx0, 2));
        mx1 = fmaxf(mx1, __shfl_xor_sync(0xffffffffu, mx1, 1));
        mx1 = fmaxf(mx1, __shfl_xor_sync(0xffffffffu, mx1, 2));
        const float mn0 = fmaxf(m0, mx0), mn1 = fmaxf(m1, mx1);
        const float sc0 = __expf(m0 - mn0), sc1 = __expf(m1 - mn1);
        m0 = mn0; m1 = mn1;
        l0 *= sc0; l1 *= sc1;
        if (sc0 != 1.f || sc1 != 1.f) {
            #pragma unroll
            for (int nt = 0; nt < 32; nt++) {
                o[nt][0] *= sc0; o[nt][1] *= sc0;
                o[nt][2] *= sc1; o[nt][3] *= sc1;
            }
        }
        float rs0 = 0.f, rs1 = 0.f;
        #pragma unroll
        for (int nt = 0; nt < 2; nt++) {
            s[nt][0] = __expf(s[nt][0] - m0);
            s[nt][1] = __expf(s[nt][1] - m0);
            s[nt][2] = __expf(s[nt][2] - m1);
            s[nt][3] = __expf(s[nt][3] - m1);
            rs0 += s[nt][0] + s[nt][1];
            rs1 += s[nt][2] + s[nt][3];
        }
        rs0 += __shfl_xor_sync(0xffffffffu, rs0, 1);
        rs0 += __shfl_xor_sync(0xffffffffu, rs0, 2);
        rs1 += __shfl_xor_sync(0xffffffffu, rs1, 1);
        rs1 += __shfl_xor_sync(0xffffffffu, rs1, 2);
        l0 += rs0; l1 += rs1;

        // P -> bf16 hi/lo A-fragment (k16 = this KV tile)
        uint32_t pah[4], pal[4];
        pah[0] = packbf2(s[0][0], s[0][1]);
        pah[1] = packbf2(s[0][2], s[0][3]);
        pah[2] = packbf2(s[1][0], s[1][1]);
        pah[3] = packbf2(s[1][2], s[1][3]);
        {
            __nv_bfloat162 h0 = *(__nv_bfloat162*)&pah[0];
            __nv_bfloat162 h1 = *(__nv_bfloat162*)&pah[1];
            __nv_bfloat162 h2 = *(__nv_bfloat162*)&pah[2];
            __nv_bfloat162 h3 = *(__nv_bfloat162*)&pah[3];
            pal[0] = packbf2(s[0][0] - __bfloat162float(__low2bfloat16(h0)),
                             s[0][1] - __bfloat162float(__high2bfloat16(h0)));
            pal[1] = packbf2(s[0][2] - __bfloat162float(__low2bfloat16(h1)),
                             s[0][3] - __bfloat162float(__high2bfloat16(h1)));
            pal[2] = packbf2(s[1][0] - __bfloat162float(__low2bfloat16(h2)),
                             s[1][1] - __bfloat162float(__high2bfloat16(h2)));
            pal[3] = packbf2(s[1][2] - __bfloat162float(__low2bfloat16(h3)),
                             s[1][3] - __bfloat162float(__high2bfloat16(h3)));
        }

        // ==== O += P(hi/lo) @ V(hi/lo) over dh=256 ====
        #pragma unroll
        for (int g2 = 0; g2 < 16; g2++) {
            const int row = g2 * 16 + b_row;
            const uint32_t voff = (uint32_t)(row * 32 + ((b_kb ^ ((row >> 2) & 1)) << 4));
            uint32_t vh4[4], vl4[4];
            ldsm_x4(vh4, vbs + voff);
            mma16816(o[g2 * 2],     pah, vh4[0], vh4[1]);
            mma16816(o[g2 * 2 + 1], pah, vh4[2], vh4[3]);
            mma16816(o[g2 * 2],     pal, vh4[0], vh4[1]);
            mma16816(o[g2 * 2 + 1], pal, vh4[2], vh4[3]);
            ldsm_x4(vl4, vbs + 8192 + voff);
            mma16816(o[g2 * 2],     pah, vl4[0], vl4[1]);
            mma16816(o[g2 * 2 + 1], pah, vl4[2], vl4[3]);
        }
        __syncthreads();                // all warps done with slot (i&1)

        if (i + 2 < NKVT) {             // refill just-freed slots
            load_k((i + 2) * KVBLK, sb + FO_K + (uint32_t)((i & 1) * 16384));
            load_v((i + 2) * KVBLK, sb + FO_V + (uint32_t)((i & 1) * 16384));
            CP_COMMIT;
        }
    }

    // ==== normalize + split-store O ====
    const float inv0 = 1.f / l0, inv1 = 1.f / l1;
    const int g  = lane >> 2;
    const int t2 = (lane & 3) * 2;
    const size_t base0 = (size_t)(b * S_ + q0 + wm + g) * INNER_ + hd * 256 + t2;
    const size_t base1 = base0 + (size_t)8 * INNER_;
    #pragma unroll
    for (int nt = 0; nt < 32; nt++) {
        float v0 = o[nt][0] * inv0, v1 = o[nt][1] * inv0;
        float v2 = o[nt][2] * inv1, v3 = o[nt][3] * inv1;
        uint32_t h0 = packbf2(v0, v1);
        uint32_t h2 = packbf2(v2, v3);
        __nv_bfloat162 hh0 = *(__nv_bfloat162*)&h0;
        __nv_bfloat162 hh2 = *(__nv_bfloat162*)&h2;
        uint32_t lo0 = packbf2(v0 - __bfloat162float(__low2bfloat16(hh0)),
                               v1 - __bfloat162float(__high2bfloat16(hh0)));
        uint32_t lo2 = packbf2(v2 - __bfloat162float(__low2bfloat16(hh2)),
                               v3 - __bfloat162float(__high2bfloat16(hh2)));
        *(uint32_t*)&oh_g[base0 + (size_t)nt * 8] = h0;
        *(uint32_t*)&ol_g[base0 + (size_t)nt * 8] = lo0;
        *(uint32_t*)&oh_g[base1 + (size_t)nt * 8] = h2;
        *(uint32_t*)&ol_g[base1 + (size_t)nt * 8] = lo2;
    }
}

// ---------------- bf16x3 HMMA GEMM (verified round 4) ----------------
#define KB_   32
#define ASTR  80

template<int OUT_SPLIT>
__global__ void __launch_bounds__(256)
gemm_hmma3(const bf16* __restrict__ Ah, const bf16* __restrict__ Al, int lda,
           const bf16* __restrict__ Bh, const bf16* __restrict__ Bl, int ldb,
           float* __restrict__ Cf, bf16* __restrict__ Ch, bf16* __restrict__ Cl, int ldc,
           int K, int zdiv,
           long long sA1, long long sA2,
           long long sB1, long long sB2,
           long long sC1, long long sC2,
           const float* __restrict__ bias,
           const float* __restrict__ resid, int ldr,
           float alpha, int relu)
{
    __shared__ __align__(16) char sAh[128 * ASTR];
    __shared__ __align__(16) char sAl[128 * ASTR];
    __shared__ __align__(16) char sBh[128 * ASTR];
    __shared__ __align__(16) char sBl[128 * ASTR];

    const int z  = blockIdx.z;
    const int zq = z / zdiv, zr = z % zdiv;
    const long long aoff = (long long)zq * sA1 + (long long)zr * sA2;
    const long long boff = (long long)zq * sB1 + (long long)zr * sB2;
    const long long coff = (long long)zq * sC1 + (long long)zr * sC2;
    Ah += aoff; Al += aoff;
    Bh += boff; Bl += boff;
    if (Cf) Cf += coff;
    if (Ch) { Ch += coff; Cl += coff; }

    const int bm   = blockIdx.y * 128;
    const int bn   = blockIdx.x * 128;
    const int tid  = threadIdx.x;
    const int wid  = tid >> 5;
    const int lane = tid & 31;
    const int wm   = (wid & 1) * 64;
    const int wn   = (wid >> 1) * 32;

    const int lrow0 = tid >> 2;
    const int lrow1 = (tid + 256) >> 2;
    const int lc0   = tid & 3;

    const uint32_t uAh = smem_u32(sAh);
    const uint32_t uAl = smem_u32(sAl);
    const uint32_t uBh = smem_u32(sBh);
    const uint32_t uBl = smem_u32(sBl);

    const uint32_t aBase = (uint32_t)((wm + (lane & 15)) * ASTR + (lane >> 4) * 16);
    const uint32_t bBase = (uint32_t)((wn + (lane & 7) + ((lane >> 4) & 1) * 8) * ASTR
                                      + (lane & 8) * 2);

    float acc[4][4][4];
    #pragma unroll
    for (int mt = 0; mt < 4; mt++)
        #pragma unroll
        for (int nt = 0; nt < 4; nt++)
            #pragma unroll
            for (int i = 0; i < 4; i++) acc[mt][nt][i] = 0.f;

    uint4 pAh[2], pAl[2], pBh[2], pBl[2];
    {
        const long long ga0 = (long long)(bm + lrow0) * lda + lc0 * 8;
        const long long ga1 = (long long)(bm + lrow1) * lda + lc0 * 8;
        const long long gb0 = (long long)(bn + lrow0) * ldb + lc0 * 8;
        const long long gb1 = (long long)(bn + lrow1) * ldb + lc0 * 8;
        pAh[0] = *(const uint4*)(Ah + ga0); pAh[1] = *(const uint4*)(Ah + ga1);
        pAl[0] = *(const uint4*)(Al + ga0); pAl[1] = *(const uint4*)(Al + ga1);
        pBh[0] = *(const uint4*)(Bh + gb0); pBh[1] = *(const uint4*)(Bh + gb1);
        pBl[0] = *(const uint4*)(Bl + gb0); pBl[1] = *(const uint4*)(Bl + gb1);
    }

    const int nkb = K / KB_;
    for (int kb = 0; kb < nkb; kb++) {
        const int so0 = lrow0 * ASTR + lc0 * 16;
        const int so1 = lrow1 * ASTR + lc0 * 16;
        *(uint4*)(sAh + so0) = pAh[0]; *(uint4*)(sAh + so1) = pAh[1];
        *(uint4*)(sAl + so0) = pAl[0]; *(uint4*)(sAl + so1) = pAl[1];
        *(uint4*)(sBh + so0) = pBh[0]; *(uint4*)(sBh + so1) = pBh[1];
        *(uint4*)(sBl + so0) = pBl[0]; *(uint4*)(sBl + so1) = pBl[1];
        __syncthreads();

        if (kb + 1 < nkb) {
            const int kn = (kb + 1) * KB_;
            const long long ga0 = (long long)(bm + lrow0) * lda + kn + lc0 * 8;
            const long long ga1 = (long long)(bm + lrow1) * lda + kn + lc0 * 8;
            const long long gb0 = (long long)(bn + lrow0) * ldb + kn + lc0 * 8;
            const long long gb1 = (long long)(bn + lrow1) * ldb + kn + lc0 * 8;
            pAh[0] = *(const uint4*)(Ah + ga0); pAh[1] = *(const uint4*)(Ah + ga1);
            pAl[0] = *(const uint4*)(Al + ga0); pAl[1] = *(const uint4*)(Al + ga1);
            pBh[0] = *(const uint4*)(Bh + gb0); pBh[1] = *(const uint4*)(Bh + gb1);
            pBl[0] = *(const uint4*)(Bl + gb0); pBl[1] = *(const uint4*)(Bl + gb1);
        }

        #pragma unroll
        for (int ks = 0; ks < 2; ks++) {
            const uint32_t ksb = ks * 32;
            uint32_t ah[4][4], al[4][4];
            #pragma unroll
            for (int mt = 0; mt < 4; mt++) {
                ldsm_x4(ah[mt], uAh + aBase + mt * (16 * ASTR) + ksb);
                ldsm_x4(al[mt], uAl + aBase + mt * (16 * ASTR) + ksb);
            }
            uint32_t bh[2][4], bl[2][4];
            #pragma unroll
            for (int g = 0; g < 2; g++) {
                ldsm_x4(bh[g], uBh + bBase + g * (16 * ASTR) + ksb);
                ldsm_x4(bl[g], uBl + bBase + g * (16 * ASTR) + ksb);
            }
            #pragma unroll
            for (int mt = 0; mt < 4; mt++) {
                #pragma unroll
                for (int nt = 0; nt < 4; nt++) {
                    const uint32_t b0h = bh[nt >> 1][(nt & 1) * 2];
                    const uint32_t b1h = bh[nt >> 1][(nt & 1) * 2 + 1];
                    const uint32_t b0l = bl[nt >> 1][(nt & 1) * 2];
                    const uint32_t b1l = bl[nt >> 1][(nt & 1) * 2 + 1];
                    mma16816(acc[mt][nt], ah[mt], b0h, b1h);
                    mma16816(acc[mt][nt], ah[mt], b0l, b1l);
                    mma16816(acc[mt][nt], al[mt], b0h, b1h);
                }
            }
        }
        __syncthreads();
    }

    const int er = lane >> 2;
    const int ec = (lane & 3) * 2;
    #pragma unroll
    for (int mt = 0; mt < 4; mt++) {
        #pragma unroll
        for (int half = 0; half < 2; half++) {
            const int m = bm + wm + mt * 16 + er + half * 8;
            #pragma unroll
            for (int nt = 0; nt < 4; nt++) {
                const int n = bn + wn + nt * 8 + ec;
                float v0 = acc[mt][nt][half * 2 + 0] * alpha;
                float v1 = acc[mt][nt][half * 2 + 1] * alpha;
                if (bias) { v0 += __ldg(&bias[n]); v1 += __ldg(&bias[n + 1]); }
                if (resid) {
                    float2 rr = *(const float2*)&resid[(long long)m * ldr + n];
                    v0 += rr.x; v1 += rr.y;
                }
                if (relu) { v0 = fmaxf(v0, 0.f); v1 = fmaxf(v1, 0.f); }
                if (OUT_SPLIT) {
                    __nv_bfloat162 hi2 = __floats2bfloat162_rn(v0, v1);
                    float l0 = v0 - __bfloat162float(__low2bfloat16(hi2));
                    float l1 = v1 - __bfloat162float(__high2bfloat16(hi2));
                    __nv_bfloat162 lo2 = __floats2bfloat162_rn(l0, l1);
                    *(uint32_t*)&Ch[(long long)m * ldc + n] = *(uint32_t*)&hi2;
                    *(uint32_t*)&Cl[(long long)m * ldc + n] = *(uint32_t*)&lo2;
                } else {
                    *(float2*)&Cf[(long long)m * ldc + n] = make_float2(v0, v1);
                }
            }
        }
    }
}

// ---------------- reductions / layernorm ----------------
__device__ __forceinline__ float warp_sum(float v) {
    #pragma unroll
    for (int o = 16; o > 0; o >>= 1) v += __shfl_xor_sync(0xffffffffu, v, o);
    return v;
}
__device__ __forceinline__ float block_reduce_sum(float v) {
    __shared__ float sm2[32];
    __shared__ float res;
    int lane = threadIdx.x & 31;
    int wid  = threadIdx.x >> 5;
    v = warp_sum(v);
    __syncthreads();
    if (lane == 0) sm2[wid] = v;
    __syncthreads();
    if (wid == 0) {
        int nw = blockDim.x >> 5;
        float x = (lane < nw) ? sm2[lane] : 0.f;
        x = warp_sum(x);
        if (lane == 0) res = x;
    }
    __syncthreads();
    return res;
}
__global__ void ln_kernel(const float* __restrict__ x,
                          const float* __restrict__ g,
                          const float* __restrict__ b,
                          float* __restrict__ outf,
                          bf16* __restrict__ oh, bf16* __restrict__ ol)
{
    const int t = threadIdx.x;
    const long long base = (long long)blockIdx.x * E_;
    float v = x[base + t];
    float mean = block_reduce_sum(v) * (1.f / E_);
    float d = v - mean;
    float var = block_reduce_sum(d * d) * (1.f / E_);
    float r = d * rsqrtf(var + EPS_) * g[t] + b[t];
    if (outf) outf[base + t] = r;
    if (oh) {
        bf16 hi = __float2bfloat16(r);
        oh[base + t] = hi;
        ol[base + t] = __float2bfloat16(r - __bfloat162float(hi));
    }
}

// ---------------- prep kernels ----------------
__global__ void split_kernel(const float* __restrict__ in,
                             bf16* __restrict__ oh, bf16* __restrict__ ol, int n)
{
    int i = blockIdx.x * blockDim.x + threadIdx.x;
    if (i < n) {
        float f = in[i];
        bf16 hi = __float2bfloat16(f);
        oh[i] = hi;
        ol[i] = __float2bfloat16(f - __bfloat162float(hi));
    }
}

__device__ __forceinline__ void wsplit_tile(const float* W, int R, int C,
                                            bf16* oh, bf16* ol,
                                            int c0, int r0, int tx, int ty)
{
    __shared__ float t[32][33];
    #pragma unroll
    for (int j = 0; j < 4; j++) {
        int r = ty + 8 * j;
        t[r][tx] = W[(long long)(r0 + r) * C + c0 + tx];
    }
    __syncthreads();
    #pragma unroll
    for (int j = 0; j < 4; j++) {
        int r = ty + 8 * j;
        float f = t[tx][r];
        bf16 hi = __float2bfloat16(f);
        long long o = (long long)(c0 + r) * R + r0 + tx;
        oh[o] = hi;
        ol[o] = __float2bfloat16(f - __bfloat162float(hi));
    }
}

// QKV weights -> packed wqkvT (all three are [E][INNER] -> [INNER][E] at row z*2048)
__global__ void wsplit_qkv(const float* __restrict__ Wq, const float* __restrict__ Wk,
                           const float* __restrict__ Wv,
                           bf16* __restrict__ oh, bf16* __restrict__ ol)
{
    const float* W = (blockIdx.z == 0) ? Wq : (blockIdx.z == 1) ? Wk : Wv;
    bf16* ph = oh + (size_t)blockIdx.z * INNER_ * E_;
    bf16* pl = ol + (size_t)blockIdx.z * INNER_ * E_;
    wsplit_tile(W, E_, INNER_, ph, pl, blockIdx.x * 32, blockIdx.y * 32,
                threadIdx.x, threadIdx.y);
}

// Wo, W1, W2
__global__ void wsplit_misc(const float* __restrict__ Wo, const float* __restrict__ W1,
                            const float* __restrict__ W2,
                            bf16* __restrict__ woh, bf16* __restrict__ wol,
                            bf16* __restrict__ w1h, bf16* __restrict__ w1l,
                            bf16* __restrict__ w2h, bf16* __restrict__ w2l)
{
    const float* W; bf16 *ph, *pl; int R, C;
    if (blockIdx.z == 0)      { W = Wo; ph = woh; pl = wol; R = INNER_; C = E_; }
    else if (blockIdx.z == 1) { W = W1; ph = w1h; pl = w1l; R = E_; C = DFF_; }
    else                      { W = W2; ph = w2h; pl = w2l; R = DFF_; C = E_; }
    if ((int)blockIdx.x * 32 >= C || (int)blockIdx.y * 32 >= R) return;
    wsplit_tile(W, R, C, ph, pl, blockIdx.x * 32, blockIdx.y * 32,
                threadIdx.x, threadIdx.y);
}

// ---------------- V transpose (from packed qkv, col offset 4096) ----------------
__global__ void vtrans_kernel(const bf16* __restrict__ qkvh, const bf16* __restrict__ qkvl,
                              bf16* __restrict__ vth, bf16* __restrict__ vtl)
{
    __shared__ bf16 th[32][33];
    __shared__ bf16 tl[32][33];
    const int z = blockIdx.z;
    const int b = z / H_, h = z % H_;
    const int s0 = blockIdx.x * 32;
    const int d0 = blockIdx.y * 32;
    const int tx = threadIdx.x, ty = threadIdx.y;
    const long long ibase = (long long)b * S_ * QKVW_ + 4096 + (long long)h * DH_;
    const long long obase = (long long)z * DH_ * S_;
    #pragma unroll
    for (int j = 0; j < 4; j++) {
        int r = ty + 8 * j;
        long long ia = ibase + (long long)(s0 + r) * QKVW_ + d0 + tx;
        th[r][tx] = qkvh[ia];
        tl[r][tx] = qkvl[ia];
    }
    __syncthreads();
    #pragma unroll
    for (int j = 0; j < 4; j++) {
        int r = ty + 8 * j;
        long long oa = obase + (long long)(d0 + r) * S_ + s0 + tx;
        vth[oa] = th[tx][r];
        vtl[oa] = tl[tx][r];
    }
}

// ---------------- launch ----------------
extern "C" void kernel_launch(void* const* d_in, const int* in_sizes, int n_in,
                              void* d_out, int out_size)
{
    const float* x    = (const float*)d_in[0];
    const float* Wq   = (const float*)d_in[1];
    const float* Wk   = (const float*)d_in[2];
    const float* Wv   = (const float*)d_in[3];
    const float* Wo   = (const float*)d_in[4];
    const float* W1   = (const float*)d_in[5];
    const float* b1   = (const float*)d_in[6];
    const float* W2   = (const float*)d_in[7];
    const float* b2   = (const float*)d_in[8];
    const float* ln1g = (const float*)d_in[9];
    const float* ln1b = (const float*)d_in[10];
    const float* ln2g = (const float*)d_in[11];
    const float* ln2b = (const float*)d_in[12];

    #define SYM(p, s) p; cudaGetSymbolAddress((void**)&p, s)
    bf16 *SYM(xh, g_xh); bf16 *SYM(xl, g_xl);
    bf16 *SYM(wqkvh, g_wqkvT_h); bf16 *SYM(wqkvl, g_wqkvT_l);
    bf16 *SYM(woh, g_woT_h); bf16 *SYM(wol, g_woT_l);
    bf16 *SYM(w1h, g_w1T_h); bf16 *SYM(w1l, g_w1T_l);
    bf16 *SYM(w2h, g_w2T_h); bf16 *SYM(w2l, g_w2T_l);
    bf16 *SYM(qkvh, g_qkvh); bf16 *SYM(qkvl, g_qkvl);
    bf16 *SYM(vth, g_vth); bf16 *SYM(vtl, g_vtl);
    bf16 *SYM(oh, g_oh); bf16 *SYM(ol, g_ol);
    float *SYM(t1, g_t1); float *SYM(hf, g_hf);
    bf16 *SYM(hh, g_hh); bf16 *SYM(hl, g_hl);
    bf16 *SYM(ffh, g_ffh); bf16 *SYM(ffl, g_ffl);
    float *SYM(t2, g_t2);

    cudaFuncSetAttribute(flash_kernel, cudaFuncAttributeMaxDynamicSharedMemorySize, F_SMEM);

    const dim3 blk(256);
    const dim3 tblk(32, 8);

    // 1) x split
    split_kernel<<<(BSZ * E_ + 255) / 256, 256>>>(x, xh, xl, BSZ * E_);
    // 2) QKV weights -> packed transposed split
    { dim3 g(INNER_/32, E_/32, 3); wsplit_qkv<<<g, tblk>>>(Wq, Wk, Wv, wqkvh, wqkvl); }
    // 3) Wo/W1/W2
    { dim3 g(64, 64, 3); wsplit_misc<<<g, tblk>>>(Wo, W1, W2, woh, wol, w1h, w1l, w2h, w2l); }
    // 4) fused QKV projection: [4096,256] @ [256,6144]
    {
        dim3 grd(QKVW_/128, BSZ/128, 1);
        gemm_hmma3<1><<<grd, blk>>>(xh, xl, E_, wqkvh, wqkvl, E_,
            nullptr, qkvh, qkvl, QKVW_, E_, 1, 0,0, 0,0, 0,0,
            nullptr, nullptr, 0, 1.f, 0);
    }
    // 5) V^T per (b,h)
    { dim3 g(S_/32, DH_/32, B_*H_); vtrans_kernel<<<g, tblk>>>(qkvh, qkvl, vth, vtl); }
    // 6) fused flash attention  (launch #6 -> ncu capture window)
    {
        dim3 grd(S_/QBLK, B_*H_);
        flash_kernel<<<grd, blk, F_SMEM>>>(qkvh, qkvl, vth, vtl, oh, ol);
    }
    // 7) t1 = O @ Wo + x ; h = LN1
    {
        dim3 grd(E_/128, BSZ/128, 1);
        gemm_hmma3<0><<<grd, blk>>>(oh, ol, INNER_, woh, wol, INNER_,
            t1, nullptr, nullptr, E_, INNER_, 1, 0,0, 0,0, 0,0,
            nullptr, x, E_, 1.f, 0);
        ln_kernel<<<BSZ, 256>>>(t1, ln1g, ln1b, hf, hh, hl);
    }
    // 8) ff = relu(h @ W1 + b1)
    {
        dim3 grd(DFF_/128, BSZ/128, 1);
        gemm_hmma3<1><<<grd, blk>>>(hh, hl, E_, w1h, w1l, E_,
            nullptr, ffh, ffl, DFF_, E_, 1, 0,0, 0,0, 0,0,
            b1, nullptr, 0, 1.f, 1);
    }
    // 9) t2 = ff @ W2 + b2 + h ; out = LN2
    {
        dim3 grd(E_/128, BSZ/128, 1);
        gemm_hmma3<0><<<grd, blk>>>(ffh, ffl, DFF_, w2h, w2l, DFF_,
            t2, nullptr, nullptr, E_, DFF_, 1, 0,0, 0,0, 0,0,
            b2, hf, E_, 1.f, 0);
        ln_kernel<<<BSZ, 256>>>(t2, ln2g, ln2b, (float*)d_out, nullptr, nullptr);
    }
}

// round 8
// speedup vs baseline: 1.2130x; 1.2130x over previous
#include <cuda_runtime.h>
#include <cuda_bf16.h>
#include <cstdint>

#define B_     2
#define S_     2048
#define E_     256
#define H_     8
#define DH_    256
#define INNER_ 2048
#define QKVW_  (3*INNER_)   // 6144
#define DFF_   1024
#define BSZ    (B_*S_)
#define EPS_   1e-6f

typedef __nv_bfloat16 bf16;

// ---------------- device scratch ----------------
__device__ bf16  g_xh [(size_t)BSZ * E_];
__device__ bf16  g_xl [(size_t)BSZ * E_];
__device__ bf16  g_wqkvT_h[(size_t)QKVW_ * E_];
__device__ bf16  g_wqkvT_l[(size_t)QKVW_ * E_];
__device__ bf16  g_woT_h[(size_t)E_ * INNER_];
__device__ bf16  g_woT_l[(size_t)E_ * INNER_];
__device__ bf16  g_w1T_h[(size_t)DFF_ * E_];
__device__ bf16  g_w1T_l[(size_t)DFF_ * E_];
__device__ bf16  g_w2T_h[(size_t)E_ * DFF_];
__device__ bf16  g_w2T_l[(size_t)E_ * DFF_];
__device__ bf16  g_qkvh[(size_t)BSZ * QKVW_];     // q|k|v packed, ld=6144
__device__ bf16  g_qkvl[(size_t)BSZ * QKVW_];
__device__ bf16  g_vth[(size_t)BSZ * INNER_];     // V^T per (b,h): [B*H][DH][S]
__device__ bf16  g_vtl[(size_t)BSZ * INNER_];
__device__ bf16  g_oh [(size_t)BSZ * INNER_];
__device__ bf16  g_ol [(size_t)BSZ * INNER_];
__device__ float g_part[(size_t)4 * BSZ * E_];    // split-K partials
__device__ float g_hf [(size_t)BSZ * E_];
__device__ bf16  g_hh [(size_t)BSZ * E_];
__device__ bf16  g_hl [(size_t)BSZ * E_];
__device__ bf16  g_ffh[(size_t)BSZ * DFF_];
__device__ bf16  g_ffl[(size_t)BSZ * DFF_];

// ---------------- helpers ----------------
__device__ __forceinline__ uint32_t smem_u32(const void* p) {
    uint32_t a;
    asm("{ .reg .u64 t; cvta.to.shared.u64 t, %1; cvt.u32.u64 %0, t; }"
        : "=r"(a) : "l"(p));
    return a;
}
__device__ __forceinline__ void ldsm_x4(uint32_t* r, uint32_t a) {
    asm volatile("ldmatrix.sync.aligned.m8n8.x4.shared.b16 {%0,%1,%2,%3}, [%4];"
                 : "=r"(r[0]), "=r"(r[1]), "=r"(r[2]), "=r"(r[3]) : "r"(a));
}
__device__ __forceinline__ void mma16816(float* c, const uint32_t* a,
                                         uint32_t b0, uint32_t b1) {
    asm volatile(
        "mma.sync.aligned.m16n8k16.row.col.f32.bf16.bf16.f32 "
        "{%0,%1,%2,%3}, {%4,%5,%6,%7}, {%8,%9}, {%0,%1,%2,%3};"
        : "+f"(c[0]), "+f"(c[1]), "+f"(c[2]), "+f"(c[3])
        : "r"(a[0]), "r"(a[1]), "r"(a[2]), "r"(a[3]), "r"(b0), "r"(b1));
}
#define CP16(dst, src) \
    asm volatile("cp.async.cg.shared.global [%0], [%1], 16;" :: "r"(dst), "l"(src) : "memory")
#define CP_COMMIT  asm volatile("cp.async.commit_group;" ::: "memory")
#define CP_WAIT0   asm volatile("cp.async.wait_group 0;" ::: "memory")
#define CP_WAIT1   asm volatile("cp.async.wait_group 1;" ::: "memory")

__device__ __forceinline__ uint32_t packbf2(float x, float y) {
    __nv_bfloat162 t = __floats2bfloat162_rn(x, y);
    return *(uint32_t*)&t;
}

// ================= flash attention (round-6 structure, packed QKV input) ====
// grid (S_/128, B_*H_), 256 thr (8 warps x m16). Q hi/lo resident,
// K double-buffered (KVBLK=32), V^T single-buffered, staggered cp.async waits.
#define QBLK   128
#define KVBLK  32
#define NKVT   (S_/KVBLK)      // 64
#define FO_QL  65536
#define FO_K0  131072
#define FO_V   196608
#define F_SMEM 229376

__global__ void __launch_bounds__(256)
flash_kernel(const bf16* __restrict__ qkvh, const bf16* __restrict__ qkvl,
             const bf16* __restrict__ vth_g, const bf16* __restrict__ vtl_g,
             bf16* __restrict__ oh_g, bf16* __restrict__ ol_g)
{
    extern __shared__ __align__(128) char sm[];
    const uint32_t sb = smem_u32(sm);
    const int tid = threadIdx.x, wid = tid >> 5, lane = tid & 31;
    const int bh = blockIdx.y;
    const int b = bh >> 3, hd = bh & 7;
    const int q0 = blockIdx.x * QBLK;

    // ---- prologue: Q + K0 + V0 (one group) ----
    #pragma unroll
    for (int it = 0; it < 32; it++) {                 // Q: 8192 x 16B
        int c = tid + it * 256;
        int split = c >> 12; int cc = c & 4095;
        int row = cc >> 5, kc = cc & 31;
        const bf16* src = (split ? qkvl : qkvh)
            + ((size_t)(b * S_ + q0 + row) * QKVW_ + hd * 256 + kc * 8);
        CP16(sb + split * 65536 + row * 512 + (uint32_t)((kc ^ (row & 7)) << 4), src);
    }
    #pragma unroll
    for (int it = 0; it < 8; it++) {                  // K0: 2048 x 16B
        int c = tid + it * 256;
        int split = c >> 10; int cc = c & 1023;
        int row = cc >> 5, kc = cc & 31;
        const bf16* src = (split ? qkvl : qkvh)
            + ((size_t)(b * S_ + row) * QKVW_ + 2048 + hd * 256 + kc * 8);
        CP16(sb + FO_K0 + split * 16384 + row * 512 + (uint32_t)((kc ^ (row & 7)) << 4), src);
    }
    #pragma unroll
    for (int it = 0; it < 8; it++) {                  // V0: 2048 x 16B
        int c = tid + it * 256;
        int split = c >> 10; int cc = c & 1023;
        int row = cc >> 2, kc = cc & 3;
        const bf16* src = (split ? vtl_g : vth_g)
            + ((size_t)bh * DH_ * S_ + (size_t)row * S_ + kc * 8);
        CP16(sb + FO_V + split * 16384 + row * 64 + (uint32_t)((kc ^ ((row >> 1) & 3)) << 4), src);
    }
    CP_COMMIT;

    const int wm    = wid * 16;
    const int a_row = wm + (lane & 15);
    const uint32_t a_rowoff = (uint32_t)(a_row * 512);
    const int a_r7  = a_row & 7;
    const int a_hb  = lane >> 4;
    const int b_row = (lane & 7) + ((lane >> 4) & 1) * 8;
    const int b_kb  = (lane >> 3) & 1;

    float o[32][4];
    #pragma unroll
    for (int i = 0; i < 32; i++) { o[i][0]=0.f; o[i][1]=0.f; o[i][2]=0.f; o[i][3]=0.f; }
    float m0 = -1e30f, m1 = -1e30f, l0 = 0.f, l1 = 0.f;

    for (int i = 0; i < NKVT; i++) {
        if (i == 0) { CP_WAIT0; } else { CP_WAIT1; }
        __syncthreads();
        const uint32_t kbs = sb + FO_K0 + (uint32_t)((i & 1) * 32768);

        if (i + 1 < NKVT) {                            // issue K(i+1)
            const int kvn = (i + 1) * KVBLK;
            const uint32_t kdst = sb + FO_K0 + (uint32_t)(((i + 1) & 1) * 32768);
            #pragma unroll
            for (int it = 0; it < 8; it++) {
                int c = tid + it * 256;
                int split = c >> 10; int cc = c & 1023;
                int row = cc >> 5, kc = cc & 31;
                const bf16* src = (split ? qkvl : qkvh)
                    + ((size_t)(b * S_ + kvn + row) * QKVW_ + 2048 + hd * 256 + kc * 8);
                CP16(kdst + split * 16384 + row * 512 + (uint32_t)((kc ^ (row & 7)) << 4), src);
            }
            CP_COMMIT;
        }

        // ==== S = (Qh+Ql)(Kh+Kl)^T ====
        float s[4][4];
        #pragma unroll
        for (int nt = 0; nt < 4; nt++) { s[nt][0]=0.f; s[nt][1]=0.f; s[nt][2]=0.f; s[nt][3]=0.f; }
        #pragma unroll
        for (int ks = 0; ks < 16; ks++) {
            const uint32_t aq = a_rowoff + (uint32_t)((((2 * ks + a_hb) ^ a_r7) << 4));
            uint32_t ah4[4], al4[4];
            ldsm_x4(ah4, sb + aq);
            ldsm_x4(al4, sb + FO_QL + aq);
            uint32_t kh4[2][4], kl4[2][4];
            #pragma unroll
            for (int g2 = 0; g2 < 2; g2++) {
                const int row = g2 * 16 + b_row;
                const uint32_t off = (uint32_t)(row * 512 + (((2 * ks + b_kb) ^ (row & 7)) << 4));
                ldsm_x4(kh4[g2], kbs + off);
                ldsm_x4(kl4[g2], kbs + 16384 + off);
            }
            #pragma unroll
            for (int nt = 0; nt < 4; nt++) {
                mma16816(s[nt], ah4, kh4[nt >> 1][(nt & 1) * 2], kh4[nt >> 1][(nt & 1) * 2 + 1]);
                mma16816(s[nt], ah4, kl4[nt >> 1][(nt & 1) * 2], kl4[nt >> 1][(nt & 1) * 2 + 1]);
                mma16816(s[nt], al4, kh4[nt >> 1][(nt & 1) * 2], kh4[nt >> 1][(nt & 1) * 2 + 1]);
            }
        }

        // ==== online softmax (rows g=lane>>2, g+8) ====
        float mx0 = -1e30f, mx1 = -1e30f;
        #pragma unroll
        for (int nt = 0; nt < 4; nt++) {
            s[nt][0] *= 0.0625f; s[nt][1] *= 0.0625f;
            s[nt][2] *= 0.0625f; s[nt][3] *= 0.0625f;
            mx0 = fmaxf(mx0, fmaxf(s[nt][0], s[nt][1]));
            mx1 = fmaxf(mx1, fmaxf(s[nt][2], s[nt][3]));
        }
        mx0 = fmaxf(mx0, __shfl_xor_sync(0xffffffffu, mx0, 1));
        mx0 = fmaxf(mx0, __shfl_xor_sync(0xffffffffu, mx0, 2));
        mx1 = fmaxf(mx1, __shfl_xor_sync(0xffffffffu, mx1, 1));
        mx1 = fmaxf(mx1, __shfl_xor_sync(0xffffffffu, mx1, 2));
        const float mn0 = fmaxf(m0, mx0), mn1 = fmaxf(m1, mx1);
        const float sc0 = __expf(m0 - mn0), sc1 = __expf(m1 - mn1);
        m0 = mn0; m1 = mn1;
        l0 *= sc0; l1 *= sc1;
        if (sc0 != 1.f || sc1 != 1.f) {
            #pragma unroll
            for (int nt = 0; nt < 32; nt++) {
                o[nt][0] *= sc0; o[nt][1] *= sc0;
                o[nt][2] *= sc1; o[nt][3] *= sc1;
            }
        }
        float rs0 = 0.f, rs1 = 0.f;
        #pragma unroll
        for (int nt = 0; nt < 4; nt++) {
            s[nt][0] = __expf(s[nt][0] - m0);
            s[nt][1] = __expf(s[nt][1] - m0);
            s[nt][2] = __expf(s[nt][2] - m1);
            s[nt][3] = __expf(s[nt][3] - m1);
            rs0 += s[nt][0] + s[nt][1];
            rs1 += s[nt][2] + s[nt][3];
        }
        rs0 += __shfl_xor_sync(0xffffffffu, rs0, 1);
        rs0 += __shfl_xor_sync(0xffffffffu, rs0, 2);
        rs1 += __shfl_xor_sync(0xffffffffu, rs1, 1);
        rs1 += __shfl_xor_sync(0xffffffffu, rs1, 2);
        l0 += rs0; l1 += rs1;

        // P -> bf16 hi/lo A-fragments
        uint32_t pah[2][4], pal[2][4];
        #pragma unroll
        for (int ks = 0; ks < 2; ks++) {
            const int j0 = 2 * ks, j1 = 2 * ks + 1;
            pah[ks][0] = packbf2(s[j0][0], s[j0][1]);
            pah[ks][1] = packbf2(s[j0][2], s[j0][3]);
            pah[ks][2] = packbf2(s[j1][0], s[j1][1]);
            pah[ks][3] = packbf2(s[j1][2], s[j1][3]);
            __nv_bfloat162 h0 = *(__nv_bfloat162*)&pah[ks][0];
            __nv_bfloat162 h1 = *(__nv_bfloat162*)&pah[ks][1];
            __nv_bfloat162 h2 = *(__nv_bfloat162*)&pah[ks][2];
            __nv_bfloat162 h3 = *(__nv_bfloat162*)&pah[ks][3];
            pal[ks][0] = packbf2(s[j0][0] - __bfloat162float(__low2bfloat16(h0)),
                                 s[j0][1] - __bfloat162float(__high2bfloat16(h0)));
            pal[ks][1] = packbf2(s[j0][2] - __bfloat162float(__low2bfloat16(h1)),
                                 s[j0][3] - __bfloat162float(__high2bfloat16(h1)));
            pal[ks][2] = packbf2(s[j1][0] - __bfloat162float(__low2bfloat16(h2)),
                                 s[j1][1] - __bfloat162float(__high2bfloat16(h2)));
            pal[ks][3] = packbf2(s[j1][2] - __bfloat162float(__low2bfloat16(h3)),
                                 s[j1][3] - __bfloat162float(__high2bfloat16(h3)));
        }

        if (i + 1 < NKVT) { CP_WAIT1; } else { CP_WAIT0; }   // V(i) landed
        __syncthreads();

        // ==== O += P(hi/lo) @ V(hi/lo) ====
        #pragma unroll
        for (int half = 0; half < 2; half++) {
            #pragma unroll
            for (int ks = 0; ks < 2; ks++) {
                #pragma unroll
                for (int j2 = 0; j2 < 8; j2++) {
                    const int row = half * 128 + j2 * 16 + b_row;
                    const uint32_t voff = (uint32_t)(row * 64 +
                        (((2 * ks + b_kb) ^ ((row >> 1) & 3)) << 4));
                    const int nt = half * 16 + j2 * 2;
                    uint32_t vh4[4], vl4[4];
                    ldsm_x4(vh4, sb + FO_V + voff);
                    mma16816(o[nt],     pah[ks], vh4[0], vh4[1]);
                    mma16816(o[nt + 1], pah[ks], vh4[2], vh4[3]);
                    mma16816(o[nt],     pal[ks], vh4[0], vh4[1]);
                    mma16816(o[nt + 1], pal[ks], vh4[2], vh4[3]);
                    ldsm_x4(vl4, sb + FO_V + 16384 + voff);
                    mma16816(o[nt],     pah[ks], vl4[0], vl4[1]);
                    mma16816(o[nt + 1], pah[ks], vl4[2], vl4[3]);
                }
            }
        }
        __syncthreads();

        if (i + 1 < NKVT) {                            // issue V(i+1)
            const int kvn = (i + 1) * KVBLK;
            #pragma unroll
            for (int it = 0; it < 8; it++) {
                int c = tid + it * 256;
                int split = c >> 10; int cc = c & 1023;
                int row = cc >> 2, kc = cc & 3;
                const bf16* src = (split ? vtl_g : vth_g)
                    + ((size_t)bh * DH_ * S_ + (size_t)row * S_ + kvn + kc * 8);
                CP16(sb + FO_V + split * 16384 + row * 64 +
                     (uint32_t)((kc ^ ((row >> 1) & 3)) << 4), src);
            }
            CP_COMMIT;
        }
    }

    // ==== normalize + split-store O ====
    const float inv0 = 1.f / l0, inv1 = 1.f / l1;
    const int g  = lane >> 2;
    const int t2 = (lane & 3) * 2;
    const size_t base0 = (size_t)(b * S_ + q0 + wm + g) * INNER_ + hd * 256 + t2;
    const size_t base1 = base0 + (size_t)8 * INNER_;
    #pragma unroll
    for (int nt = 0; nt < 32; nt++) {
        float v0 = o[nt][0] * inv0, v1 = o[nt][1] * inv0;
        float v2 = o[nt][2] * inv1, v3 = o[nt][3] * inv1;
        uint32_t h0 = packbf2(v0, v1);
        uint32_t h2 = packbf2(v2, v3);
        __nv_bfloat162 hh0 = *(__nv_bfloat162*)&h0;
        __nv_bfloat162 hh2 = *(__nv_bfloat162*)&h2;
        uint32_t lo0 = packbf2(v0 - __bfloat162float(__low2bfloat16(hh0)),
                               v1 - __bfloat162float(__high2bfloat16(hh0)));
        uint32_t lo2 = packbf2(v2 - __bfloat162float(__low2bfloat16(hh2)),
                               v3 - __bfloat162float(__high2bfloat16(hh2)));
        *(uint32_t*)&oh_g[base0 + (size_t)nt * 8] = h0;
        *(uint32_t*)&ol_g[base0 + (size_t)nt * 8] = lo0;
        *(uint32_t*)&oh_g[base1 + (size_t)nt * 8] = h2;
        *(uint32_t*)&ol_g[base1 + (size_t)nt * 8] = lo2;
    }
}

// ---------------- bf16x3 HMMA GEMM (verified round 4) ----------------
#define KB_   32
#define ASTR  80

template<int OUT_SPLIT>
__global__ void __launch_bounds__(256)
gemm_hmma3(const bf16* __restrict__ Ah, const bf16* __restrict__ Al, int lda,
           const bf16* __restrict__ Bh, const bf16* __restrict__ Bl, int ldb,
           float* __restrict__ Cf, bf16* __restrict__ Ch, bf16* __restrict__ Cl, int ldc,
           int K, int zdiv,
           long long sA1, long long sA2,
           long long sB1, long long sB2,
           long long sC1, long long sC2,
           const float* __restrict__ bias,
           const float* __restrict__ resid, int ldr,
           float alpha, int relu)
{
    __shared__ __align__(16) char sAh[128 * ASTR];
    __shared__ __align__(16) char sAl[128 * ASTR];
    __shared__ __align__(16) char sBh[128 * ASTR];
    __shared__ __align__(16) char sBl[128 * ASTR];

    const int z  = blockIdx.z;
    const int zq = z / zdiv, zr = z % zdiv;
    const long long aoff = (long long)zq * sA1 + (long long)zr * sA2;
    const long long boff = (long long)zq * sB1 + (long long)zr * sB2;
    const long long coff = (long long)zq * sC1 + (long long)zr * sC2;
    Ah += aoff; Al += aoff;
    Bh += boff; Bl += boff;
    if (Cf) Cf += coff;
    if (Ch) { Ch += coff; Cl += coff; }

    const int bm   = blockIdx.y * 128;
    const int bn   = blockIdx.x * 128;
    const int tid  = threadIdx.x;
    const int wid  = tid >> 5;
    const int lane = tid & 31;
    const int wm   = (wid & 1) * 64;
    const int wn   = (wid >> 1) * 32;

    const int lrow0 = tid >> 2;
    const int lrow1 = (tid + 256) >> 2;
    const int lc0   = tid & 3;

    const uint32_t uAh = smem_u32(sAh);
    const uint32_t uAl = smem_u32(sAl);
    const uint32_t uBh = smem_u32(sBh);
    const uint32_t uBl = smem_u32(sBl);

    const uint32_t aBase = (uint32_t)((wm + (lane & 15)) * ASTR + (lane >> 4) * 16);
    const uint32_t bBase = (uint32_t)((wn + (lane & 7) + ((lane >> 4) & 1) * 8) * ASTR
                                      + (lane & 8) * 2);

    float acc[4][4][4];
    #pragma unroll
    for (int mt = 0; mt < 4; mt++)
        #pragma unroll
        for (int nt = 0; nt < 4; nt++)
            #pragma unroll
            for (int i = 0; i < 4; i++) acc[mt][nt][i] = 0.f;

    uint4 pAh[2], pAl[2], pBh[2], pBl[2];
    {
        const long long ga0 = (long long)(bm + lrow0) * lda + lc0 * 8;
        const long long ga1 = (long long)(bm + lrow1) * lda + lc0 * 8;
        const long long gb0 = (long long)(bn + lrow0) * ldb + lc0 * 8;
        const long long gb1 = (long long)(bn + lrow1) * ldb + lc0 * 8;
        pAh[0] = *(const uint4*)(Ah + ga0); pAh[1] = *(const uint4*)(Ah + ga1);
        pAl[0] = *(const uint4*)(Al + ga0); pAl[1] = *(const uint4*)(Al + ga1);
        pBh[0] = *(const uint4*)(Bh + gb0); pBh[1] = *(const uint4*)(Bh + gb1);
        pBl[0] = *(const uint4*)(Bl + gb0); pBl[1] = *(const uint4*)(Bl + gb1);
    }

    const int nkb = K / KB_;
    for (int kb = 0; kb < nkb; kb++) {
        const int so0 = lrow0 * ASTR + lc0 * 16;
        const int so1 = lrow1 * ASTR + lc0 * 16;
        *(uint4*)(sAh + so0) = pAh[0]; *(uint4*)(sAh + so1) = pAh[1];
        *(uint4*)(sAl + so0) = pAl[0]; *(uint4*)(sAl + so1) = pAl[1];
        *(uint4*)(sBh + so0) = pBh[0]; *(uint4*)(sBh + so1) = pBh[1];
        *(uint4*)(sBl + so0) = pBl[0]; *(uint4*)(sBl + so1) = pBl[1];
        __syncthreads();

        if (kb + 1 < nkb) {
            const int kn = (kb + 1) * KB_;
            const long long ga0 = (long long)(bm + lrow0) * lda + kn + lc0 * 8;
            const long long ga1 = (long long)(bm + lrow1) * lda + kn + lc0 * 8;
            const long long gb0 = (long long)(bn + lrow0) * ldb + kn + lc0 * 8;
            const long long gb1 = (long long)(bn + lrow1) * ldb + kn + lc0 * 8;
            pAh[0] = *(const uint4*)(Ah + ga0); pAh[1] = *(const uint4*)(Ah + ga1);
            pAl[0] = *(const uint4*)(Al + ga0); pAl[1] = *(const uint4*)(Al + ga1);
            pBh[0] = *(const uint4*)(Bh + gb0); pBh[1] = *(const uint4*)(Bh + gb1);
            pBl[0] = *(const uint4*)(Bl + gb0); pBl[1] = *(const uint4*)(Bl + gb1);
        }

        #pragma unroll
        for (int ks = 0; ks < 2; ks++) {
            const uint32_t ksb = ks * 32;
            uint32_t ah[4][4], al[4][4];
            #pragma unroll
            for (int mt = 0; mt < 4; mt++) {
                ldsm_x4(ah[mt], uAh + aBase + mt * (16 * ASTR) + ksb);
                ldsm_x4(al[mt], uAl + aBase + mt * (16 * ASTR) + ksb);
            }
            uint32_t bh[2][4], bl[2][4];
            #pragma unroll
            for (int g = 0; g < 2; g++) {
                ldsm_x4(bh[g], uBh + bBase + g * (16 * ASTR) + ksb);
                ldsm_x4(bl[g], uBl + bBase + g * (16 * ASTR) + ksb);
            }
            #pragma unroll
            for (int mt = 0; mt < 4; mt++) {
                #pragma unroll
                for (int nt = 0; nt < 4; nt++) {
                    const uint32_t b0h = bh[nt >> 1][(nt & 1) * 2];
                    const uint32_t b1h = bh[nt >> 1][(nt & 1) * 2 + 1];
                    const uint32_t b0l = bl[nt >> 1][(nt & 1) * 2];
                    const uint32_t b1l = bl[nt >> 1][(nt & 1) * 2 + 1];
                    mma16816(acc[mt][nt], ah[mt], b0h, b1h);
                    mma16816(acc[mt][nt], ah[mt], b0l, b1l);
                    mma16816(acc[mt][nt], al[mt], b0h, b1h);
                }
            }
        }
        __syncthreads();
    }

    const int er = lane >> 2;
    const int ec = (lane & 3) * 2;
    #pragma unroll
    for (int mt = 0; mt < 4; mt++) {
        #pragma unroll
        for (int half = 0; half < 2; half++) {
            const int m = bm + wm + mt * 16 + er + half * 8;
            #pragma unroll
            for (int nt = 0; nt < 4; nt++) {
                const int n = bn + wn + nt * 8 + ec;
                float v0 = acc[mt][nt][half * 2 + 0] * alpha;
                float v1 = acc[mt][nt][half * 2 + 1] * alpha;
                if (bias) { v0 += __ldg(&bias[n]); v1 += __ldg(&bias[n + 1]); }
                if (resid) {
                    float2 rr = *(const float2*)&resid[(long long)m * ldr + n];
                    v0 += rr.x; v1 += rr.y;
                }
                if (relu) { v0 = fmaxf(v0, 0.f); v1 = fmaxf(v1, 0.f); }
                if (OUT_SPLIT) {
                    __nv_bfloat162 hi2 = __floats2bfloat162_rn(v0, v1);
                    float l0 = v0 - __bfloat162float(__low2bfloat16(hi2));
                    float l1 = v1 - __bfloat162float(__high2bfloat16(hi2));
                    __nv_bfloat162 lo2 = __floats2bfloat162_rn(l0, l1);
                    *(uint32_t*)&Ch[(long long)m * ldc + n] = *(uint32_t*)&hi2;
                    *(uint32_t*)&Cl[(long long)m * ldc + n] = *(uint32_t*)&lo2;
                } else {
                    *(float2*)&Cf[(long long)m * ldc + n] = make_float2(v0, v1);
                }
            }
        }
    }
}

// ---------------- reductions / fused split-K reduce + layernorm ----------------
__device__ __forceinline__ float warp_sum(float v) {
    #pragma unroll
    for (int o = 16; o > 0; o >>= 1) v += __shfl_xor_sync(0xffffffffu, v, o);
    return v;
}
__device__ __forceinline__ float block_reduce_sum(float v) {
    __shared__ float sm2[32];
    __shared__ float res;
    int lane = threadIdx.x & 31;
    int wid  = threadIdx.x >> 5;
    v = warp_sum(v);
    __syncthreads();
    if (lane == 0) sm2[wid] = v;
    __syncthreads();
    if (wid == 0) {
        int nw = blockDim.x >> 5;
        float x = (lane < nw) ? sm2[lane] : 0.f;
        x = warp_sum(x);
        if (lane == 0) res = x;
    }
    __syncthreads();
    return res;
}

// sum 4 split-K partials (+bias) (+resid), LayerNorm, optional fp32 + split out
__global__ void ln_red_kernel(const float* __restrict__ part, long long pstride,
                              const float* __restrict__ bias,
                              const float* __restrict__ resid,
                              const float* __restrict__ g,
                              const float* __restrict__ b,
                              float* __restrict__ outf,
                              bf16* __restrict__ oh, bf16* __restrict__ ol)
{
    const int t = threadIdx.x;
    const long long base = (long long)blockIdx.x * E_ + t;
    float v = part[base] + part[base + pstride]
            + part[base + 2 * pstride] + part[base + 3 * pstride];
    if (bias) v += bias[t];
    v += resid[base];
    float mean = block_reduce_sum(v) * (1.f / E_);
    float d = v - mean;
    float var = block_reduce_sum(d * d) * (1.f / E_);
    float r = d * rsqrtf(var + EPS_) * g[t] + b[t];
    if (outf) outf[base] = r;
    if (oh) {
        bf16 hi = __float2bfloat16(r);
        oh[base] = hi;
        ol[base] = __float2bfloat16(r - __bfloat162float(hi));
    }
}

// ---------------- prep kernels ----------------
__global__ void split_kernel(const float* __restrict__ in,
                             bf16* __restrict__ oh, bf16* __restrict__ ol, int n)
{
    int i = blockIdx.x * blockDim.x + threadIdx.x;
    if (i < n) {
        float f = in[i];
        bf16 hi = __float2bfloat16(f);
        oh[i] = hi;
        ol[i] = __float2bfloat16(f - __bfloat162float(hi));
    }
}

__device__ __forceinline__ void wsplit_tile(const float* W, int R, int C,
                                            bf16* oh, bf16* ol,
                                            int c0, int r0, int tx, int ty)
{
    __shared__ float t[32][33];
    #pragma unroll
    for (int j = 0; j < 4; j++) {
        int r = ty + 8 * j;
        t[r][tx] = W[(long long)(r0 + r) * C + c0 + tx];
    }
    __syncthreads();
    #pragma unroll
    for (int j = 0; j < 4; j++) {
        int r = ty + 8 * j;
        float f = t[tx][r];
        bf16 hi = __float2bfloat16(f);
        long long o = (long long)(c0 + r) * R + r0 + tx;
        oh[o] = hi;
        ol[o] = __float2bfloat16(f - __bfloat162float(hi));
    }
}

__global__ void wsplit_qkv(const float* __restrict__ Wq, const float* __restrict__ Wk,
                           const float* __restrict__ Wv,
                           bf16* __restrict__ oh, bf16* __restrict__ ol)
{
    const float* W = (blockIdx.z == 0) ? Wq : (blockIdx.z == 1) ? Wk : Wv;
    bf16* ph = oh + (size_t)blockIdx.z * INNER_ * E_;
    bf16* pl = ol + (size_t)blockIdx.z * INNER_ * E_;
    wsplit_tile(W, E_, INNER_, ph, pl, blockIdx.x * 32, blockIdx.y * 32,
                threadIdx.x, threadIdx.y);
}

__global__ void wsplit_misc(const float* __restrict__ Wo, const float* __restrict__ W1,
                            const float* __restrict__ W2,
                            bf16* __restrict__ woh, bf16* __restrict__ wol,
                            bf16* __restrict__ w1h, bf16* __restrict__ w1l,
                            bf16* __restrict__ w2h, bf16* __restrict__ w2l)
{
    const float* W; bf16 *ph, *pl; int R, C;
    if (blockIdx.z == 0)      { W = Wo; ph = woh; pl = wol; R = INNER_; C = E_; }
    else if (blockIdx.z == 1) { W = W1; ph = w1h; pl = w1l; R = E_; C = DFF_; }
    else                      { W = W2; ph = w2h; pl = w2l; R = DFF_; C = E_; }
    if ((int)blockIdx.x * 32 >= C || (int)blockIdx.y * 32 >= R) return;
    wsplit_tile(W, R, C, ph, pl, blockIdx.x * 32, blockIdx.y * 32,
                threadIdx.x, threadIdx.y);
}

__global__ void vtrans_kernel(const bf16* __restrict__ qkvh, const bf16* __restrict__ qkvl,
                              bf16* __restrict__ vth, bf16* __restrict__ vtl)
{
    __shared__ bf16 th[32][33];
    __shared__ bf16 tl[32][33];
    const int z = blockIdx.z;
    const int b = z / H_, h = z % H_;
    const int s0 = blockIdx.x * 32;
    const int d0 = blockIdx.y * 32;
    const int tx = threadIdx.x, ty = threadIdx.y;
    const long long ibase = (long long)b * S_ * QKVW_ + 4096 + (long long)h * DH_;
    const long long obase = (long long)z * DH_ * S_;
    #pragma unroll
    for (int j = 0; j < 4; j++) {
        int r = ty + 8 * j;
        long long ia = ibase + (long long)(s0 + r) * QKVW_ + d0 + tx;
        th[r][tx] = qkvh[ia];
        tl[r][tx] = qkvl[ia];
    }
    __syncthreads();
    #pragma unroll
    for (int j = 0; j < 4; j++) {
        int r = ty + 8 * j;
        long long oa = obase + (long long)(d0 + r) * S_ + s0 + tx;
        vth[oa] = th[tx][r];
        vtl[oa] = tl[tx][r];
    }
}

// ---------------- launch ----------------
extern "C" void kernel_launch(void* const* d_in, const int* in_sizes, int n_in,
                              void* d_out, int out_size)
{
    const float* x    = (const float*)d_in[0];
    const float* Wq   = (const float*)d_in[1];
    const float* Wk   = (const float*)d_in[2];
    const float* Wv   = (const float*)d_in[3];
    const float* Wo   = (const float*)d_in[4];
    const float* W1   = (const float*)d_in[5];
    const float* b1   = (const float*)d_in[6];
    const float* W2   = (const float*)d_in[7];
    const float* b2   = (const float*)d_in[8];
    const float* ln1g = (const float*)d_in[9];
    const float* ln1b = (const float*)d_in[10];
    const float* ln2g = (const float*)d_in[11];
    const float* ln2b = (const float*)d_in[12];

    #define SYM(p, s) p; cudaGetSymbolAddress((void**)&p, s)
    bf16 *SYM(xh, g_xh); bf16 *SYM(xl, g_xl);
    bf16 *SYM(wqkvh, g_wqkvT_h); bf16 *SYM(wqkvl, g_wqkvT_l);
    bf16 *SYM(woh, g_woT_h); bf16 *SYM(wol, g_woT_l);
    bf16 *SYM(w1h, g_w1T_h); bf16 *SYM(w1l, g_w1T_l);
    bf16 *SYM(w2h, g_w2T_h); bf16 *SYM(w2l, g_w2T_l);
    bf16 *SYM(qkvh, g_qkvh); bf16 *SYM(qkvl, g_qkvl);
    bf16 *SYM(vth, g_vth); bf16 *SYM(vtl, g_vtl);
    bf16 *SYM(oh, g_oh); bf16 *SYM(ol, g_ol);
    float *SYM(part, g_part);
    float *SYM(hf, g_hf);
    bf16 *SYM(hh, g_hh); bf16 *SYM(hl, g_hl);
    bf16 *SYM(ffh, g_ffh); bf16 *SYM(ffl, g_ffl);

    cudaFuncSetAttribute(flash_kernel, cudaFuncAttributeMaxDynamicSharedMemorySize, F_SMEM);

    const dim3 blk(256);
    const dim3 tblk(32, 8);
    const long long psz = (long long)BSZ * E_;

    // 1) x split
    split_kernel<<<(BSZ * E_ + 255) / 256, 256>>>(x, xh, xl, BSZ * E_);
    // 2) QKV weights packed split
    { dim3 g(INNER_/32, E_/32, 3); wsplit_qkv<<<g, tblk>>>(Wq, Wk, Wv, wqkvh, wqkvl); }
    // 3) Wo/W1/W2
    { dim3 g(64, 64, 3); wsplit_misc<<<g, tblk>>>(Wo, W1, W2, woh, wol, w1h, w1l, w2h, w2l); }
    // 4) fused QKV projection
    {
        dim3 grd(QKVW_/128, BSZ/128, 1);
        gemm_hmma3<1><<<grd, blk>>>(xh, xl, E_, wqkvh, wqkvl, E_,
            nullptr, qkvh, qkvl, QKVW_, E_, 1, 0,0, 0,0, 0,0,
            nullptr, nullptr, 0, 1.f, 0);
    }
    // 5) V^T per (b,h)
    { dim3 g(S_/32, DH_/32, B_*H_); vtrans_kernel<<<g, tblk>>>(qkvh, qkvl, vth, vtl); }
    // 6) flash attention  (launch #6 -> ncu window)
    {
        dim3 grd(S_/QBLK, B_*H_);
        flash_kernel<<<grd, blk, F_SMEM>>>(qkvh, qkvl, vth, vtl, oh, ol);
    }
    // 7) Wo split-K x4 -> partials ; LN1 reduce (+x resid)
    {
        dim3 grd(E_/128, BSZ/128, 4);
        gemm_hmma3<0><<<grd, blk>>>(oh, ol, INNER_, woh, wol, INNER_,
            part, nullptr, nullptr, E_, INNER_/4, 4,
            0, 512, 0, 512, 0, psz,
            nullptr, nullptr, 0, 1.f, 0);
        ln_red_kernel<<<BSZ, 256>>>(part, psz, nullptr, x, ln1g, ln1b, hf, hh, hl);
    }
    // 8) ff = relu(h @ W1 + b1)
    {
        dim3 grd(DFF_/128, BSZ/128, 1);
        gemm_hmma3<1><<<grd, blk>>>(hh, hl, E_, w1h, w1l, E_,
            nullptr, ffh, ffl, DFF_, E_, 1, 0,0, 0,0, 0,0,
            b1, nullptr, 0, 1.f, 1);
    }
    // 9) FFN2 split-K x4 -> partials ; LN2 reduce (+b2 +h resid) -> out
    {
        dim3 grd(E_/128, BSZ/128, 4);
        gemm_hmma3<0><<<grd, blk>>>(ffh, ffl, DFF_, w2h, w2l, DFF_,
            part, nullptr, nullptr, E_, DFF_/4, 4,
            0, 256, 0, 256, 0, psz,
            nullptr, nullptr, 0, 1.f, 0);
        ln_red_kernel<<<BSZ, 256>>>(part, psz, b2, hf, ln2g, ln2b,
                                    (float*)d_out, nullptr, nullptr);
    }
}

// round 9
// speedup vs baseline: 1.5111x; 1.2458x over previous
#include <cuda_runtime.h>
#include <cuda_fp16.h>
#include <cstdint>

#define B_     2
#define S_     2048
#define E_     256
#define H_     8
#define DH_    256
#define INNER_ 2048
#define QKVW_  (3*INNER_)   // 6144
#define DFF_   1024
#define BSZ    (B_*S_)
#define EPS_   1e-6f

typedef __half h16;

// ---------------- device scratch ----------------
__device__ h16   g_xh [(size_t)BSZ * E_];
__device__ h16   g_wqkvT_h[(size_t)QKVW_ * E_];
__device__ h16   g_wqkvT_l[(size_t)QKVW_ * E_];
__device__ h16   g_woT_h[(size_t)E_ * INNER_];
__device__ h16   g_woT_l[(size_t)E_ * INNER_];
__device__ h16   g_w1T_h[(size_t)DFF_ * E_];
__device__ h16   g_w1T_l[(size_t)DFF_ * E_];
__device__ h16   g_w2T_h[(size_t)E_ * DFF_];
__device__ h16   g_w2T_l[(size_t)E_ * DFF_];
__device__ h16   g_qkvh[(size_t)BSZ * QKVW_];     // q|k|v packed, ld=6144
__device__ h16   g_qkvl[(size_t)BSZ * QKVW_];     // lo (K/V parts consumed)
__device__ h16   g_vth[(size_t)BSZ * INNER_];     // V^T per (b,h): [B*H][DH][S]
__device__ h16   g_vtl[(size_t)BSZ * INNER_];
__device__ h16   g_oh [(size_t)BSZ * INNER_];
__device__ float g_part[(size_t)4 * BSZ * E_];    // split-K partials
__device__ float g_hf [(size_t)BSZ * E_];
__device__ h16   g_hh [(size_t)BSZ * E_];
__device__ h16   g_ffh[(size_t)BSZ * DFF_];

// ---------------- helpers ----------------
__device__ __forceinline__ uint32_t smem_u32(const void* p) {
    uint32_t a;
    asm("{ .reg .u64 t; cvta.to.shared.u64 t, %1; cvt.u32.u64 %0, t; }"
        : "=r"(a) : "l"(p));
    return a;
}
__device__ __forceinline__ void ldsm_x4(uint32_t* r, uint32_t a) {
    asm volatile("ldmatrix.sync.aligned.m8n8.x4.shared.b16 {%0,%1,%2,%3}, [%4];"
                 : "=r"(r[0]), "=r"(r[1]), "=r"(r[2]), "=r"(r[3]) : "r"(a));
}
__device__ __forceinline__ void mma16816(float* c, const uint32_t* a,
                                         uint32_t b0, uint32_t b1) {
    asm volatile(
        "mma.sync.aligned.m16n8k16.row.col.f32.f16.f16.f32 "
        "{%0,%1,%2,%3}, {%4,%5,%6,%7}, {%8,%9}, {%0,%1,%2,%3};"
        : "+f"(c[0]), "+f"(c[1]), "+f"(c[2]), "+f"(c[3])
        : "r"(a[0]), "r"(a[1]), "r"(a[2]), "r"(a[3]), "r"(b0), "r"(b1));
}
#define CP16(dst, src) \
    asm volatile("cp.async.cg.shared.global [%0], [%1], 16;" :: "r"(dst), "l"(src) : "memory")
#define CP_COMMIT  asm volatile("cp.async.commit_group;" ::: "memory")
#define CP_WAIT0   asm volatile("cp.async.wait_group 0;" ::: "memory")
#define CP_WAIT1   asm volatile("cp.async.wait_group 1;" ::: "memory")

__device__ __forceinline__ uint32_t packh2(float x, float y) {
    __half2 t = __floats2half2_rn(x, y);
    return *(uint32_t*)&t;
}

// ================= flash attention =================
// grid (S_/128, B_*H_), 256 thr (8 warps x m16). Q hi resident (64KB),
// K and V hi/lo double-buffered (KVBLK=32), one cp.async group per iter.
#define QBLK   128
#define KVBLK  32
#define NKVT   (S_/KVBLK)      // 64
#define FO_K   65536           // 2 slots x 32768 (hi 16384 | lo 16384)
#define FO_V   131072          // 2 slots x 32768
#define F_SMEM 196608

__global__ void __launch_bounds__(256)
flash_kernel(const h16* __restrict__ qkvh, const h16* __restrict__ qkvl,
             const h16* __restrict__ vth_g, const h16* __restrict__ vtl_g,
             h16* __restrict__ oh_g)
{
    extern __shared__ __align__(128) char sm[];
    const uint32_t sb = smem_u32(sm);
    const int tid = threadIdx.x, wid = tid >> 5, lane = tid & 31;
    const int bh = blockIdx.y;
    const int b = bh >> 3, hd = bh & 7;
    const int q0 = blockIdx.x * QBLK;

    auto load_k = [&](int kv0, uint32_t slot) {      // 2048 x 16B
        #pragma unroll
        for (int it = 0; it < 8; it++) {
            int c = tid + it * 256;
            int split = c >> 10; int cc = c & 1023;
            int row = cc >> 5, kc = cc & 31;
            const h16* src = (split ? qkvl : qkvh)
                + ((size_t)(b * S_ + kv0 + row) * QKVW_ + 2048 + hd * 256 + kc * 8);
            CP16(slot + split * 16384 + row * 512 + (uint32_t)((kc ^ (row & 7)) << 4), src);
        }
    };
    auto load_v = [&](int kv0, uint32_t slot) {      // 2048 x 16B
        #pragma unroll
        for (int it = 0; it < 8; it++) {
            int c = tid + it * 256;
            int split = c >> 10; int cc = c & 1023;
            int row = cc >> 2, kc = cc & 3;
            const h16* src = (split ? vtl_g : vth_g)
                + ((size_t)bh * DH_ * S_ + (size_t)row * S_ + kv0 + kc * 8);
            CP16(slot + split * 16384 + row * 64 + (uint32_t)((kc ^ ((row >> 1) & 3)) << 4), src);
        }
    };

    // ---- prologue: G0 = {Q, K0, V0}, G1 = {K1, V1} ----
    #pragma unroll
    for (int it = 0; it < 16; it++) {                 // Q hi: 4096 x 16B
        int c = tid + it * 256;
        int row = c >> 5, kc = c & 31;
        const h16* src = qkvh
            + ((size_t)(b * S_ + q0 + row) * QKVW_ + hd * 256 + kc * 8);
        CP16(sb + row * 512 + (uint32_t)((kc ^ (row & 7)) << 4), src);
    }
    load_k(0, sb + FO_K);
    load_v(0, sb + FO_V);
    CP_COMMIT;
    load_k(KVBLK, sb + FO_K + 32768);
    load_v(KVBLK, sb + FO_V + 32768);
    CP_COMMIT;

    const int wm    = wid * 16;
    const int a_row = wm + (lane & 15);
    const uint32_t a_rowoff = (uint32_t)(a_row * 512);
    const int a_r7  = a_row & 7;
    const int a_hb  = lane >> 4;
    const int b_row = (lane & 7) + ((lane >> 4) & 1) * 8;
    const int b_kb  = (lane >> 3) & 1;

    float o[32][4];
    #pragma unroll
    for (int i = 0; i < 32; i++) { o[i][0]=0.f; o[i][1]=0.f; o[i][2]=0.f; o[i][3]=0.f; }
    float m0 = -1e30f, m1 = -1e30f, l0 = 0.f, l1 = 0.f;

    for (int i = 0; i < NKVT; i++) {
        if (i + 1 < NKVT) { CP_WAIT1; } else { CP_WAIT0; }   // K(i),V(i) ready
        __syncthreads();
        const uint32_t kbs = sb + FO_K + (uint32_t)((i & 1) * 32768);
        const uint32_t vbs = sb + FO_V + (uint32_t)((i & 1) * 32768);

        // ==== S = Qh (Kh+Kl)^T ====
        float s[4][4];
        #pragma unroll
        for (int nt = 0; nt < 4; nt++) { s[nt][0]=0.f; s[nt][1]=0.f; s[nt][2]=0.f; s[nt][3]=0.f; }
        #pragma unroll
        for (int ks = 0; ks < 16; ks++) {
            const uint32_t aq = a_rowoff + (uint32_t)((((2 * ks + a_hb) ^ a_r7) << 4));
            uint32_t ah4[4];
            ldsm_x4(ah4, sb + aq);
            uint32_t kh4[2][4], kl4[2][4];
            #pragma unroll
            for (int g2 = 0; g2 < 2; g2++) {
                const int row = g2 * 16 + b_row;
                const uint32_t off = (uint32_t)(row * 512 + (((2 * ks + b_kb) ^ (row & 7)) << 4));
                ldsm_x4(kh4[g2], kbs + off);
                ldsm_x4(kl4[g2], kbs + 16384 + off);
            }
            #pragma unroll
            for (int nt = 0; nt < 4; nt++) {
                mma16816(s[nt], ah4, kh4[nt >> 1][(nt & 1) * 2], kh4[nt >> 1][(nt & 1) * 2 + 1]);
                mma16816(s[nt], ah4, kl4[nt >> 1][(nt & 1) * 2], kl4[nt >> 1][(nt & 1) * 2 + 1]);
            }
        }

        // ==== online softmax (rows g=lane>>2, g+8) ====
        float mx0 = -1e30f, mx1 = -1e30f;
        #pragma unroll
        for (int nt = 0; nt < 4; nt++) {
            s[nt][0] *= 0.0625f; s[nt][1] *= 0.0625f;
            s[nt][2] *= 0.0625f; s[nt][3] *= 0.0625f;
            mx0 = fmaxf(mx0, fmaxf(s[nt][0], s[nt][1]));
            mx1 = fmaxf(mx1, fmaxf(s[nt][2], s[nt][3]));
        }
        mx0 = fmaxf(mx0, __shfl_xor_sync(0xffffffffu, mx0, 1));
        mx0 = fmaxf(mx0, __shfl_xor_sync(0xffffffffu, mx0, 2));
        mx1 = fmaxf(mx1, __shfl_xor_sync(0xffffffffu, mx1, 1));
        mx1 = fmaxf(mx1, __shfl_xor_sync(0xffffffffu, mx1, 2));
        const float mn0 = fmaxf(m0, mx0), mn1 = fmaxf(m1, mx1);
        const float sc0 = __expf(m0 - mn0), sc1 = __expf(m1 - mn1);
        m0 = mn0; m1 = mn1;
        l0 *= sc0; l1 *= sc1;
        if (sc0 != 1.f || sc1 != 1.f) {
            #pragma unroll
            for (int nt = 0; nt < 32; nt++) {
                o[nt][0] *= sc0; o[nt][1] *= sc0;
                o[nt][2] *= sc1; o[nt][3] *= sc1;
            }
        }
        float rs0 = 0.f, rs1 = 0.f;
        #pragma unroll
        for (int nt = 0; nt < 4; nt++) {
            s[nt][0] = __expf(s[nt][0] - m0);
            s[nt][1] = __expf(s[nt][1] - m0);
            s[nt][2] = __expf(s[nt][2] - m1);
            s[nt][3] = __expf(s[nt][3] - m1);
            rs0 += s[nt][0] + s[nt][1];
            rs1 += s[nt][2] + s[nt][3];
        }
        rs0 += __shfl_xor_sync(0xffffffffu, rs0, 1);
        rs0 += __shfl_xor_sync(0xffffffffu, rs0, 2);
        rs1 += __shfl_xor_sync(0xffffffffu, rs1, 1);
        rs1 += __shfl_xor_sync(0xffffffffu, rs1, 2);
        l0 += rs0; l1 += rs1;

        // P -> fp16 A-fragments (hi only)
        uint32_t pah[2][4];
        #pragma unroll
        for (int ks = 0; ks < 2; ks++) {
            const int j0 = 2 * ks, j1 = 2 * ks + 1;
            pah[ks][0] = packh2(s[j0][0], s[j0][1]);
            pah[ks][1] = packh2(s[j0][2], s[j0][3]);
            pah[ks][2] = packh2(s[j1][0], s[j1][1]);
            pah[ks][3] = packh2(s[j1][2], s[j1][3]);
        }

        // ==== O += P (Vh+Vl) ====
        #pragma unroll
        for (int half = 0; half < 2; half++) {
            #pragma unroll
            for (int ks = 0; ks < 2; ks++) {
                #pragma unroll
                for (int j2 = 0; j2 < 8; j2++) {
                    const int row = half * 128 + j2 * 16 + b_row;
                    const uint32_t voff = (uint32_t)(row * 64 +
                        (((2 * ks + b_kb) ^ ((row >> 1) & 3)) << 4));
                    const int nt = half * 16 + j2 * 2;
                    uint32_t vh4[4], vl4[4];
                    ldsm_x4(vh4, vbs + voff);
                    mma16816(o[nt],     pah[ks], vh4[0], vh4[1]);
                    mma16816(o[nt + 1], pah[ks], vh4[2], vh4[3]);
                    ldsm_x4(vl4, vbs + 16384 + voff);
                    mma16816(o[nt],     pah[ks], vl4[0], vl4[1]);
                    mma16816(o[nt + 1], pah[ks], vl4[2], vl4[3]);
                }
            }
        }
        __syncthreads();                   // all warps done with slot (i&1)

        if (i + 2 < NKVT) {                // refill freed slots, one group
            load_k((i + 2) * KVBLK, sb + FO_K + (uint32_t)((i & 1) * 32768));
            load_v((i + 2) * KVBLK, sb + FO_V + (uint32_t)((i & 1) * 32768));
            CP_COMMIT;
        }
    }

    // ==== normalize + store O (hi only) ====
    const float inv0 = 1.f / l0, inv1 = 1.f / l1;
    const int g  = lane >> 2;
    const int t2 = (lane & 3) * 2;
    const size_t base0 = (size_t)(b * S_ + q0 + wm + g) * INNER_ + hd * 256 + t2;
    const size_t base1 = base0 + (size_t)8 * INNER_;
    #pragma unroll
    for (int nt = 0; nt < 32; nt++) {
        *(uint32_t*)&oh_g[base0 + (size_t)nt * 8] = packh2(o[nt][0] * inv0, o[nt][1] * inv0);
        *(uint32_t*)&oh_g[base1 + (size_t)nt * 8] = packh2(o[nt][2] * inv1, o[nt][3] * inv1);
    }
}

// ---------------- fp16x2 HMMA GEMM: C = alpha * Ah @ (Bh+Bl)^T ----------------
#define KB_   32
#define ASTR  80

template<int OUT_SPLIT>
__global__ void __launch_bounds__(256)
gemm_hmma2(const h16* __restrict__ Ah, int lda,
           const h16* __restrict__ Bh, const h16* __restrict__ Bl, int ldb,
           float* __restrict__ Cf, h16* __restrict__ Ch, h16* __restrict__ Cl, int ldc,
           int K, int zdiv,
           long long sA1, long long sA2,
           long long sB1, long long sB2,
           long long sC1, long long sC2,
           const float* __restrict__ bias,
           float alpha, int relu)
{
    __shared__ __align__(16) char sA [128 * ASTR];
    __shared__ __align__(16) char sBh[128 * ASTR];
    __shared__ __align__(16) char sBl[128 * ASTR];

    const int z  = blockIdx.z;
    const int zq = z / zdiv, zr = z % zdiv;
    Ah += (long long)zq * sA1 + (long long)zr * sA2;
    Bh += (long long)zq * sB1 + (long long)zr * sB2;
    Bl += (long long)zq * sB1 + (long long)zr * sB2;
    const long long coff = (long long)zq * sC1 + (long long)zr * sC2;
    if (Cf) Cf += coff;
    if (Ch) Ch += coff;
    if (Cl) Cl += coff;

    const int bm   = blockIdx.y * 128;
    const int bn   = blockIdx.x * 128;
    const int tid  = threadIdx.x;
    const int wid  = tid >> 5;
    const int lane = tid & 31;
    const int wm   = (wid & 1) * 64;
    const int wn   = (wid >> 1) * 32;

    const int lrow0 = tid >> 2;
    const int lrow1 = (tid + 256) >> 2;
    const int lc0   = tid & 3;

    const uint32_t uA  = smem_u32(sA);
    const uint32_t uBh = smem_u32(sBh);
    const uint32_t uBl = smem_u32(sBl);

    const uint32_t aBase = (uint32_t)((wm + (lane & 15)) * ASTR + (lane >> 4) * 16);
    const uint32_t bBase = (uint32_t)((wn + (lane & 7) + ((lane >> 4) & 1) * 8) * ASTR
                                      + (lane & 8) * 2);

    float acc[4][4][4];
    #pragma unroll
    for (int mt = 0; mt < 4; mt++)
        #pragma unroll
        for (int nt = 0; nt < 4; nt++)
            #pragma unroll
            for (int i = 0; i < 4; i++) acc[mt][nt][i] = 0.f;

    uint4 pA[2], pBh[2], pBl[2];
    {
        const long long ga0 = (long long)(bm + lrow0) * lda + lc0 * 8;
        const long long ga1 = (long long)(bm + lrow1) * lda + lc0 * 8;
        const long long gb0 = (long long)(bn + lrow0) * ldb + lc0 * 8;
        const long long gb1 = (long long)(bn + lrow1) * ldb + lc0 * 8;
        pA[0]  = *(const uint4*)(Ah + ga0); pA[1]  = *(const uint4*)(Ah + ga1);
        pBh[0] = *(const uint4*)(Bh + gb0); pBh[1] = *(const uint4*)(Bh + gb1);
        pBl[0] = *(const uint4*)(Bl + gb0); pBl[1] = *(const uint4*)(Bl + gb1);
    }

    const int nkb = K / KB_;
    for (int kb = 0; kb < nkb; kb++) {
        const int so0 = lrow0 * ASTR + lc0 * 16;
        const int so1 = lrow1 * ASTR + lc0 * 16;
        *(uint4*)(sA  + so0) = pA[0];  *(uint4*)(sA  + so1) = pA[1];
        *(uint4*)(sBh + so0) = pBh[0]; *(uint4*)(sBh + so1) = pBh[1];
        *(uint4*)(sBl + so0) = pBl[0]; *(uint4*)(sBl + so1) = pBl[1];
        __syncthreads();

        if (kb + 1 < nkb) {
            const int kn = (kb + 1) * KB_;
            const long long ga0 = (long long)(bm + lrow0) * lda + kn + lc0 * 8;
            const long long ga1 = (long long)(bm + lrow1) * lda + kn + lc0 * 8;
            const long long gb0 = (long long)(bn + lrow0) * ldb + kn + lc0 * 8;
            const long long gb1 = (long long)(bn + lrow1) * ldb + kn + lc0 * 8;
            pA[0]  = *(const uint4*)(Ah + ga0); pA[1]  = *(const uint4*)(Ah + ga1);
            pBh[0] = *(const uint4*)(Bh + gb0); pBh[1] = *(const uint4*)(Bh + gb1);
            pBl[0] = *(const uint4*)(Bl + gb0); pBl[1] = *(const uint4*)(Bl + gb1);
        }

        #pragma unroll
        for (int ks = 0; ks < 2; ks++) {
            const uint32_t ksb = ks * 32;
            uint32_t ah[4][4];
            #pragma unroll
            for (int mt = 0; mt < 4; mt++)
                ldsm_x4(ah[mt], uA + aBase + mt * (16 * ASTR) + ksb);
            uint32_t bh[2][4], bl[2][4];
            #pragma unroll
            for (int g = 0; g < 2; g++) {
                ldsm_x4(bh[g], uBh + bBase + g * (16 * ASTR) + ksb);
                ldsm_x4(bl[g], uBl + bBase + g * (16 * ASTR) + ksb);
            }
            #pragma unroll
            for (int mt = 0; mt < 4; mt++) {
                #pragma unroll
                for (int nt = 0; nt < 4; nt++) {
                    mma16816(acc[mt][nt], ah[mt],
                             bh[nt >> 1][(nt & 1) * 2], bh[nt >> 1][(nt & 1) * 2 + 1]);
                    mma16816(acc[mt][nt], ah[mt],
                             bl[nt >> 1][(nt & 1) * 2], bl[nt >> 1][(nt & 1) * 2 + 1]);
                }
            }
        }
        __syncthreads();
    }

    const int er = lane >> 2;
    const int ec = (lane & 3) * 2;
    #pragma unroll
    for (int mt = 0; mt < 4; mt++) {
        #pragma unroll
        for (int half = 0; half < 2; half++) {
            const int m = bm + wm + mt * 16 + er + half * 8;
            #pragma unroll
            for (int nt = 0; nt < 4; nt++) {
                const int n = bn + wn + nt * 8 + ec;
                float v0 = acc[mt][nt][half * 2 + 0] * alpha;
                float v1 = acc[mt][nt][half * 2 + 1] * alpha;
                if (bias) { v0 += __ldg(&bias[n]); v1 += __ldg(&bias[n + 1]); }
                if (relu) { v0 = fmaxf(v0, 0.f); v1 = fmaxf(v1, 0.f); }
                if (OUT_SPLIT) {
                    __half2 hi2 = __floats2half2_rn(v0, v1);
                    *(uint32_t*)&Ch[(long long)m * ldc + n] = *(uint32_t*)&hi2;
                    if (Cl) {
                        float l0 = v0 - __half2float(__low2half(hi2));
                        float l1 = v1 - __half2float(__high2half(hi2));
                        __half2 lo2 = __floats2half2_rn(l0, l1);
                        *(uint32_t*)&Cl[(long long)m * ldc + n] = *(uint32_t*)&lo2;
                    }
                } else {
                    *(float2*)&Cf[(long long)m * ldc + n] = make_float2(v0, v1);
                }
            }
        }
    }
}

// ---------------- reductions / fused split-K reduce + layernorm ----------------
__device__ __forceinline__ float warp_sum(float v) {
    #pragma unroll
    for (int o = 16; o > 0; o >>= 1) v += __shfl_xor_sync(0xffffffffu, v, o);
    return v;
}
__device__ __forceinline__ float block_reduce_sum(float v) {
    __shared__ float sm2[32];
    __shared__ float res;
    int lane = threadIdx.x & 31;
    int wid  = threadIdx.x >> 5;
    v = warp_sum(v);
    __syncthreads();
    if (lane == 0) sm2[wid] = v;
    __syncthreads();
    if (wid == 0) {
        int nw = blockDim.x >> 5;
        float x = (lane < nw) ? sm2[lane] : 0.f;
        x = warp_sum(x);
        if (lane == 0) res = x;
    }
    __syncthreads();
    return res;
}

__global__ void ln_red_kernel(const float* __restrict__ part, long long pstride,
                              const float* __restrict__ bias,
                              const float* __restrict__ resid,
                              const float* __restrict__ g,
                              const float* __restrict__ b,
                              float* __restrict__ outf,
                              h16* __restrict__ oh)
{
    const int t = threadIdx.x;
    const long long base = (long long)blockIdx.x * E_ + t;
    float v = part[base] + part[base + pstride]
            + part[base + 2 * pstride] + part[base + 3 * pstride];
    if (bias) v += bias[t];
    v += resid[base];
    float mean = block_reduce_sum(v) * (1.f / E_);
    float d = v - mean;
    float var = block_reduce_sum(d * d) * (1.f / E_);
    float r = d * rsqrtf(var + EPS_) * g[t] + b[t];
    if (outf) outf[base] = r;
    if (oh) oh[base] = __float2half_rn(r);
}

// ---------------- prep kernels ----------------
__global__ void split_kernel(const float* __restrict__ in,
                             h16* __restrict__ oh, int n)
{
    int i = blockIdx.x * blockDim.x + threadIdx.x;
    if (i < n) oh[i] = __float2half_rn(in[i]);
}

__device__ __forceinline__ void wsplit_tile(const float* W, int R, int C,
                                            h16* oh, h16* ol,
                                            int c0, int r0, int tx, int ty)
{
    __shared__ float t[32][33];
    #pragma unroll
    for (int j = 0; j < 4; j++) {
        int r = ty + 8 * j;
        t[r][tx] = W[(long long)(r0 + r) * C + c0 + tx];
    }
    __syncthreads();
    #pragma unroll
    for (int j = 0; j < 4; j++) {
        int r = ty + 8 * j;
        float f = t[tx][r];
        h16 hi = __float2half_rn(f);
        long long o = (long long)(c0 + r) * R + r0 + tx;
        oh[o] = hi;
        ol[o] = __float2half_rn(f - __half2float(hi));
    }
}

__global__ void wsplit_qkv(const float* __restrict__ Wq, const float* __restrict__ Wk,
                           const float* __restrict__ Wv,
                           h16* __restrict__ oh, h16* __restrict__ ol)
{
    const float* W = (blockIdx.z == 0) ? Wq : (blockIdx.z == 1) ? Wk : Wv;
    h16* ph = oh + (size_t)blockIdx.z * INNER_ * E_;
    h16* pl = ol + (size_t)blockIdx.z * INNER_ * E_;
    wsplit_tile(W, E_, INNER_, ph, pl, blockIdx.x * 32, blockIdx.y * 32,
                threadIdx.x, threadIdx.y);
}

__global__ void wsplit_misc(const float* __restrict__ Wo, const float* __restrict__ W1,
                            const float* __restrict__ W2,
                            h16* __restrict__ woh, h16* __restrict__ wol,
                            h16* __restrict__ w1h, h16* __restrict__ w1l,
                            h16* __restrict__ w2h, h16* __restrict__ w2l)
{
    const float* W; h16 *ph, *pl; int R, C;
    if (blockIdx.z == 0)      { W = Wo; ph = woh; pl = wol; R = INNER_; C = E_; }
    else if (blockIdx.z == 1) { W = W1; ph = w1h; pl = w1l; R = E_; C = DFF_; }
    else                      { W = W2; ph = w2h; pl = w2l; R = DFF_; C = E_; }
    if ((int)blockIdx.x * 32 >= C || (int)blockIdx.y * 32 >= R) return;
    wsplit_tile(W, R, C, ph, pl, blockIdx.x * 32, blockIdx.y * 32,
                threadIdx.x, threadIdx.y);
}

__global__ void vtrans_kernel(const h16* __restrict__ qkvh, const h16* __restrict__ qkvl,
                              h16* __restrict__ vth, h16* __restrict__ vtl)
{
    __shared__ h16 th[32][33];
    __shared__ h16 tl[32][33];
    const int z = blockIdx.z;
    const int b = z / H_, h = z % H_;
    const int s0 = blockIdx.x * 32;
    const int d0 = blockIdx.y * 32;
    const int tx = threadIdx.x, ty = threadIdx.y;
    const long long ibase = (long long)b * S_ * QKVW_ + 4096 + (long long)h * DH_;
    const long long obase = (long long)z * DH_ * S_;
    #pragma unroll
    for (int j = 0; j < 4; j++) {
        int r = ty + 8 * j;
        long long ia = ibase + (long long)(s0 + r) * QKVW_ + d0 + tx;
        th[r][tx] = qkvh[ia];
        tl[r][tx] = qkvl[ia];
    }
    __syncthreads();
    #pragma unroll
    for (int j = 0; j < 4; j++) {
        int r = ty + 8 * j;
        long long oa = obase + (long long)(d0 + r) * S_ + s0 + tx;
        vth[oa] = th[tx][r];
        vtl[oa] = tl[tx][r];
    }
}

// ---------------- launch ----------------
extern "C" void kernel_launch(void* const* d_in, const int* in_sizes, int n_in,
                              void* d_out, int out_size)
{
    const float* x    = (const float*)d_in[0];
    const float* Wq   = (const float*)d_in[1];
    const float* Wk   = (const float*)d_in[2];
    const float* Wv   = (const float*)d_in[3];
    const float* Wo   = (const float*)d_in[4];
    const float* W1   = (const float*)d_in[5];
    const float* b1   = (const float*)d_in[6];
    const float* W2   = (const float*)d_in[7];
    const float* b2   = (const float*)d_in[8];
    const float* ln1g = (const float*)d_in[9];
    const float* ln1b = (const float*)d_in[10];
    const float* ln2g = (const float*)d_in[11];
    const float* ln2b = (const float*)d_in[12];

    #define SYM(p, s) p; cudaGetSymbolAddress((void**)&p, s)
    h16 *SYM(xh, g_xh);
    h16 *SYM(wqkvh, g_wqkvT_h); h16 *SYM(wqkvl, g_wqkvT_l);
    h16 *SYM(woh, g_woT_h); h16 *SYM(wol, g_woT_l);
    h16 *SYM(w1h, g_w1T_h); h16 *SYM(w1l, g_w1T_l);
    h16 *SYM(w2h, g_w2T_h); h16 *SYM(w2l, g_w2T_l);
    h16 *SYM(qkvh, g_qkvh); h16 *SYM(qkvl, g_qkvl);
    h16 *SYM(vth, g_vth); h16 *SYM(vtl, g_vtl);
    h16 *SYM(oh, g_oh);
    float *SYM(part, g_part);
    float *SYM(hf, g_hf);
    h16 *SYM(hh, g_hh);
    h16 *SYM(ffh, g_ffh);

    cudaFuncSetAttribute(flash_kernel, cudaFuncAttributeMaxDynamicSharedMemorySize, F_SMEM);

    const dim3 blk(256);
    const dim3 tblk(32, 8);
    const long long psz = (long long)BSZ * E_;

    // 1) x -> fp16 hi
    split_kernel<<<(BSZ * E_ + 255) / 256, 256>>>(x, xh, BSZ * E_);
    // 2) QKV weights packed split
    { dim3 g(INNER_/32, E_/32, 3); wsplit_qkv<<<g, tblk>>>(Wq, Wk, Wv, wqkvh, wqkvl); }
    // 3) Wo/W1/W2
    { dim3 g(64, 64, 3); wsplit_misc<<<g, tblk>>>(Wo, W1, W2, woh, wol, w1h, w1l, w2h, w2l); }
    // 4) fused QKV projection: [4096,256] @ [256,6144]
    {
        dim3 grd(QKVW_/128, BSZ/128, 1);
        gemm_hmma2<1><<<grd, blk>>>(xh, E_, wqkvh, wqkvl, E_,
            nullptr, qkvh, qkvl, QKVW_, E_, 1, 0,0, 0,0, 0,0,
            nullptr, 1.f, 0);
    }
    // 5) V^T per (b,h)
    { dim3 g(S_/32, DH_/32, B_*H_); vtrans_kernel<<<g, tblk>>>(qkvh, qkvl, vth, vtl); }
    // 6) flash attention
    {
        dim3 grd(S_/QBLK, B_*H_);
        flash_kernel<<<grd, blk, F_SMEM>>>(qkvh, qkvl, vth, vtl, oh);
    }
    // 7) Wo split-K x4 -> partials ; LN1 reduce (+x resid)
    {
        dim3 grd(E_/128, BSZ/128, 4);
        gemm_hmma2<0><<<grd, blk>>>(oh, INNER_, woh, wol, INNER_,
            part, nullptr, nullptr, E_, INNER_/4, 4,
            0, 512, 0, 512, 0, psz,
            nullptr, 1.f, 0);
        ln_red_kernel<<<BSZ, 256>>>(part, psz, nullptr, x, ln1g, ln1b, hf, hh);
    }
    // 8) ff = relu(h @ W1 + b1)  (hi only)
    {
        dim3 grd(DFF_/128, BSZ/128, 1);
        gemm_hmma2<1><<<grd, blk>>>(hh, E_, w1h, w1l, E_,
            nullptr, ffh, nullptr, DFF_, E_, 1, 0,0, 0,0, 0,0,
            b1, 1.f, 1);
    }
    // 9) FFN2 split-K x4 -> partials ; LN2 reduce (+b2 +h resid) -> out
    {
        dim3 grd(E_/128, BSZ/128, 4);
        gemm_hmma2<0><<<grd, blk>>>(ffh, DFF_, w2h, w2l, DFF_,
            part, nullptr, nullptr, E_, DFF_/4, 4,
            0, 256, 0, 256, 0, psz,
            nullptr, 1.f, 0);
        ln_red_kernel<<<BSZ, 256>>>(part, psz, b2, hf, ln2g, ln2b,
                                    (float*)d_out, nullptr);
    }
}

// round 10
// speedup vs baseline: 1.8533x; 1.2264x over previous
#include <cuda_runtime.h>
#include <cuda_fp16.h>
#include <cstdint>

#define B_     2
#define S_     2048
#define E_     256
#define H_     8
#define DH_    256
#define INNER_ 2048
#define QKVW_  (3*INNER_)   // 6144
#define DFF_   1024
#define BSZ    (B_*S_)
#define EPS_   1e-6f

typedef __half h16;

// ---------------- device scratch ----------------
__device__ h16   g_xh [(size_t)BSZ * E_];
__device__ h16   g_wqkvT_h[(size_t)QKVW_ * E_];
__device__ h16   g_wqkvT_l[(size_t)QKVW_ * E_];
__device__ h16   g_woT_h[(size_t)E_ * INNER_];
__device__ h16   g_woT_l[(size_t)E_ * INNER_];
__device__ h16   g_w1T_h[(size_t)DFF_ * E_];
__device__ h16   g_w1T_l[(size_t)DFF_ * E_];
__device__ h16   g_w2T_h[(size_t)E_ * DFF_];
__device__ h16   g_w2T_l[(size_t)E_ * DFF_];
__device__ h16   g_qkvh[(size_t)BSZ * QKVW_];     // q|k|v packed, ld=6144
__device__ h16   g_qkvl[(size_t)BSZ * QKVW_];     // lo (K part consumed)
__device__ h16   g_vth[(size_t)BSZ * INNER_];     // V^T per (b,h): [B*H][DH][S]
__device__ h16   g_oh [(size_t)BSZ * INNER_];
__device__ float g_part[(size_t)4 * BSZ * E_];    // split-K partials
__device__ float g_hf [(size_t)BSZ * E_];
__device__ h16   g_hh [(size_t)BSZ * E_];
__device__ h16   g_ffh[(size_t)BSZ * DFF_];

// ---------------- helpers ----------------
__device__ __forceinline__ uint32_t smem_u32(const void* p) {
    uint32_t a;
    asm("{ .reg .u64 t; cvta.to.shared.u64 t, %1; cvt.u32.u64 %0, t; }"
        : "=r"(a) : "l"(p));
    return a;
}
__device__ __forceinline__ void ldsm_x4(uint32_t* r, uint32_t a) {
    asm volatile("ldmatrix.sync.aligned.m8n8.x4.shared.b16 {%0,%1,%2,%3}, [%4];"
                 : "=r"(r[0]), "=r"(r[1]), "=r"(r[2]), "=r"(r[3]) : "r"(a));
}
__device__ __forceinline__ void mma16816(float* c, const uint32_t* a,
                                         uint32_t b0, uint32_t b1) {
    asm volatile(
        "mma.sync.aligned.m16n8k16.row.col.f32.f16.f16.f32 "
        "{%0,%1,%2,%3}, {%4,%5,%6,%7}, {%8,%9}, {%0,%1,%2,%3};"
        : "+f"(c[0]), "+f"(c[1]), "+f"(c[2]), "+f"(c[3])
        : "r"(a[0]), "r"(a[1]), "r"(a[2]), "r"(a[3]), "r"(b0), "r"(b1));
}
#define CP16(dst, src) \
    asm volatile("cp.async.cg.shared.global [%0], [%1], 16;" :: "r"(dst), "l"(src) : "memory")
#define CP_COMMIT  asm volatile("cp.async.commit_group;" ::: "memory")
#define CP_WAIT0   asm volatile("cp.async.wait_group 0;" ::: "memory")
#define CP_WAIT1   asm volatile("cp.async.wait_group 1;" ::: "memory")

__device__ __forceinline__ uint32_t packh2(float x, float y) {
    __half2 t = __floats2half2_rn(x, y);
    return *(uint32_t*)&t;
}

// ================= flash attention =================
// grid (S_/128, B_*H_), 256 thr (8 warps x m16). Q hi resident (64KB),
// K hi/lo + V hi double-buffered (KVBLK=32), one cp.async group per iter.
#define QBLK   128
#define KVBLK  32
#define NKVT   (S_/KVBLK)      // 64
#define FO_K   65536           // 2 slots x 32768 (hi 16384 | lo 16384)
#define FO_V   131072          // 2 slots x 16384 (hi only)
#define F_SMEM 163840

__global__ void __launch_bounds__(256)
flash_kernel(const h16* __restrict__ qkvh, const h16* __restrict__ qkvl,
             const h16* __restrict__ vth_g,
             h16* __restrict__ oh_g)
{
    extern __shared__ __align__(128) char sm[];
    const uint32_t sb = smem_u32(sm);
    const int tid = threadIdx.x, wid = tid >> 5, lane = tid & 31;
    const int bh = blockIdx.y;
    const int b = bh >> 3, hd = bh & 7;
    const int q0 = blockIdx.x * QBLK;

    auto load_k = [&](int kv0, uint32_t slot) {      // 2048 x 16B (hi+lo)
        #pragma unroll
        for (int it = 0; it < 8; it++) {
            int c = tid + it * 256;
            int split = c >> 10; int cc = c & 1023;
            int row = cc >> 5, kc = cc & 31;
            const h16* src = (split ? qkvl : qkvh)
                + ((size_t)(b * S_ + kv0 + row) * QKVW_ + 2048 + hd * 256 + kc * 8);
            CP16(slot + split * 16384 + row * 512 + (uint32_t)((kc ^ (row & 7)) << 4), src);
        }
    };
    auto load_v = [&](int kv0, uint32_t slot) {      // 1024 x 16B (hi only)
        #pragma unroll
        for (int it = 0; it < 4; it++) {
            int c = tid + it * 256;
            int row = c >> 2, kc = c & 3;
            const h16* src = vth_g
                + ((size_t)bh * DH_ * S_ + (size_t)row * S_ + kv0 + kc * 8);
            CP16(slot + row * 64 + (uint32_t)((kc ^ ((row >> 1) & 3)) << 4), src);
        }
    };

    // ---- prologue: G0 = {Q, K0, V0}, G1 = {K1, V1} ----
    #pragma unroll
    for (int it = 0; it < 16; it++) {                 // Q hi: 4096 x 16B
        int c = tid + it * 256;
        int row = c >> 5, kc = c & 31;
        const h16* src = qkvh
            + ((size_t)(b * S_ + q0 + row) * QKVW_ + hd * 256 + kc * 8);
        CP16(sb + row * 512 + (uint32_t)((kc ^ (row & 7)) << 4), src);
    }
    load_k(0, sb + FO_K);
    load_v(0, sb + FO_V);
    CP_COMMIT;
    load_k(KVBLK, sb + FO_K + 32768);
    load_v(KVBLK, sb + FO_V + 16384);
    CP_COMMIT;

    const int wm    = wid * 16;
    const int a_row = wm + (lane & 15);
    const uint32_t a_rowoff = (uint32_t)(a_row * 512);
    const int a_r7  = a_row & 7;
    const int a_hb  = lane >> 4;
    const int b_row = (lane & 7) + ((lane >> 4) & 1) * 8;
    const int b_kb  = (lane >> 3) & 1;

    float o[32][4];
    #pragma unroll
    for (int i = 0; i < 32; i++) { o[i][0]=0.f; o[i][1]=0.f; o[i][2]=0.f; o[i][3]=0.f; }
    float m0 = -1e30f, m1 = -1e30f, l0 = 0.f, l1 = 0.f;

    for (int i = 0; i < NKVT; i++) {
        if (i + 1 < NKVT) { CP_WAIT1; } else { CP_WAIT0; }   // K(i),V(i) ready
        __syncthreads();
        const uint32_t kbs = sb + FO_K + (uint32_t)((i & 1) * 32768);
        const uint32_t vbs = sb + FO_V + (uint32_t)((i & 1) * 16384);

        // ==== S = Qh (Kh+Kl)^T ====
        float s[4][4];
        #pragma unroll
        for (int nt = 0; nt < 4; nt++) { s[nt][0]=0.f; s[nt][1]=0.f; s[nt][2]=0.f; s[nt][3]=0.f; }
        #pragma unroll
        for (int ks = 0; ks < 16; ks++) {
            const uint32_t aq = a_rowoff + (uint32_t)((((2 * ks + a_hb) ^ a_r7) << 4));
            uint32_t ah4[4];
            ldsm_x4(ah4, sb + aq);
            uint32_t kh4[2][4], kl4[2][4];
            #pragma unroll
            for (int g2 = 0; g2 < 2; g2++) {
                const int row = g2 * 16 + b_row;
                const uint32_t off = (uint32_t)(row * 512 + (((2 * ks + b_kb) ^ (row & 7)) << 4));
                ldsm_x4(kh4[g2], kbs + off);
                ldsm_x4(kl4[g2], kbs + 16384 + off);
            }
            #pragma unroll
            for (int nt = 0; nt < 4; nt++) {
                mma16816(s[nt], ah4, kh4[nt >> 1][(nt & 1) * 2], kh4[nt >> 1][(nt & 1) * 2 + 1]);
                mma16816(s[nt], ah4, kl4[nt >> 1][(nt & 1) * 2], kl4[nt >> 1][(nt & 1) * 2 + 1]);
            }
        }

        // ==== online softmax (rows g=lane>>2, g+8) ====
        float mx0 = -1e30f, mx1 = -1e30f;
        #pragma unroll
        for (int nt = 0; nt < 4; nt++) {
            s[nt][0] *= 0.0625f; s[nt][1] *= 0.0625f;
            s[nt][2] *= 0.0625f; s[nt][3] *= 0.0625f;
            mx0 = fmaxf(mx0, fmaxf(s[nt][0], s[nt][1]));
            mx1 = fmaxf(mx1, fmaxf(s[nt][2], s[nt][3]));
        }
        mx0 = fmaxf(mx0, __shfl_xor_sync(0xffffffffu, mx0, 1));
        mx0 = fmaxf(mx0, __shfl_xor_sync(0xffffffffu, mx0, 2));
        mx1 = fmaxf(mx1, __shfl_xor_sync(0xffffffffu, mx1, 1));
        mx1 = fmaxf(mx1, __shfl_xor_sync(0xffffffffu, mx1, 2));
        const float mn0 = fmaxf(m0, mx0), mn1 = fmaxf(m1, mx1);
        const float sc0 = __expf(m0 - mn0), sc1 = __expf(m1 - mn1);
        m0 = mn0; m1 = mn1;
        l0 *= sc0; l1 *= sc1;
        if (sc0 != 1.f || sc1 != 1.f) {
            #pragma unroll
            for (int nt = 0; nt < 32; nt++) {
                o[nt][0] *= sc0; o[nt][1] *= sc0;
                o[nt][2] *= sc1; o[nt][3] *= sc1;
            }
        }
        float rs0 = 0.f, rs1 = 0.f;
        #pragma unroll
        for (int nt = 0; nt < 4; nt++) {
            s[nt][0] = __expf(s[nt][0] - m0);
            s[nt][1] = __expf(s[nt][1] - m0);
            s[nt][2] = __expf(s[nt][2] - m1);
            s[nt][3] = __expf(s[nt][3] - m1);
            rs0 += s[nt][0] + s[nt][1];
            rs1 += s[nt][2] + s[nt][3];
        }
        rs0 += __shfl_xor_sync(0xffffffffu, rs0, 1);
        rs0 += __shfl_xor_sync(0xffffffffu, rs0, 2);
        rs1 += __shfl_xor_sync(0xffffffffu, rs1, 1);
        rs1 += __shfl_xor_sync(0xffffffffu, rs1, 2);
        l0 += rs0; l1 += rs1;

        // P -> fp16 A-fragments
        uint32_t pah[2][4];
        #pragma unroll
        for (int ks = 0; ks < 2; ks++) {
            const int j0 = 2 * ks, j1 = 2 * ks + 1;
            pah[ks][0] = packh2(s[j0][0], s[j0][1]);
            pah[ks][1] = packh2(s[j0][2], s[j0][3]);
            pah[ks][2] = packh2(s[j1][0], s[j1][1]);
            pah[ks][3] = packh2(s[j1][2], s[j1][3]);
        }

        // ==== O += P @ Vh ====
        #pragma unroll
        for (int half = 0; half < 2; half++) {
            #pragma unroll
            for (int ks = 0; ks < 2; ks++) {
                #pragma unroll
                for (int j2 = 0; j2 < 8; j2++) {
                    const int row = half * 128 + j2 * 16 + b_row;
                    const uint32_t voff = (uint32_t)(row * 64 +
                        (((2 * ks + b_kb) ^ ((row >> 1) & 3)) << 4));
                    const int nt = half * 16 + j2 * 2;
                    uint32_t vh4[4];
                    ldsm_x4(vh4, vbs + voff);
                    mma16816(o[nt],     pah[ks], vh4[0], vh4[1]);
                    mma16816(o[nt + 1], pah[ks], vh4[2], vh4[3]);
                }
            }
        }
        __syncthreads();                   // all warps done with slot (i&1)

        if (i + 2 < NKVT) {                // refill freed slots, one group
            load_k((i + 2) * KVBLK, sb + FO_K + (uint32_t)((i & 1) * 32768));
            load_v((i + 2) * KVBLK, sb + FO_V + (uint32_t)((i & 1) * 16384));
            CP_COMMIT;
        }
    }

    // ==== normalize + store O ====
    const float inv0 = 1.f / l0, inv1 = 1.f / l1;
    const int g  = lane >> 2;
    const int t2 = (lane & 3) * 2;
    const size_t base0 = (size_t)(b * S_ + q0 + wm + g) * INNER_ + hd * 256 + t2;
    const size_t base1 = base0 + (size_t)8 * INNER_;
    #pragma unroll
    for (int nt = 0; nt < 32; nt++) {
        *(uint32_t*)&oh_g[base0 + (size_t)nt * 8] = packh2(o[nt][0] * inv0, o[nt][1] * inv0);
        *(uint32_t*)&oh_g[base1 + (size_t)nt * 8] = packh2(o[nt][2] * inv1, o[nt][3] * inv1);
    }
}

// ---------------- fp16x2 HMMA GEMM, cp.async 2-stage, 2 CTA/SM ----------------
// C = alpha * Ah @ (Bh+Bl)^T
#define KB_    32
#define ASTR   80
#define GTILE  (128 * ASTR)    // 10240 B per tile buffer

template<int OUT_SPLIT>
__global__ void __launch_bounds__(256, 2)
gemm_hmma2(const h16* __restrict__ Ah, int lda,
           const h16* __restrict__ Bh, const h16* __restrict__ Bl, int ldb,
           float* __restrict__ Cf, h16* __restrict__ Ch, h16* __restrict__ Cl, int ldc,
           int K, int zdiv,
           long long sA1, long long sA2,
           long long sB1, long long sB2,
           long long sC1, long long sC2,
           const float* __restrict__ bias,
           float alpha, int relu)
{
    __shared__ __align__(16) char sA [2 * GTILE];
    __shared__ __align__(16) char sBh[2 * GTILE];
    __shared__ __align__(16) char sBl[2 * GTILE];

    const int z  = blockIdx.z;
    const int zq = z / zdiv, zr = z % zdiv;
    Ah += (long long)zq * sA1 + (long long)zr * sA2;
    Bh += (long long)zq * sB1 + (long long)zr * sB2;
    Bl += (long long)zq * sB1 + (long long)zr * sB2;
    const long long coff = (long long)zq * sC1 + (long long)zr * sC2;
    if (Cf) Cf += coff;
    if (Ch) Ch += coff;
    if (Cl) Cl += coff;

    const int bm   = blockIdx.y * 128;
    const int bn   = blockIdx.x * 128;
    const int tid  = threadIdx.x;
    const int wid  = tid >> 5;
    const int lane = tid & 31;
    const int wm   = (wid & 1) * 64;
    const int wn   = (wid >> 1) * 32;

    const uint32_t uA  = smem_u32(sA);
    const uint32_t uBh = smem_u32(sBh);
    const uint32_t uBl = smem_u32(sBl);

    // loader: 512 chunks/tile, 2 per thread per tile
    const int lrow0 = tid >> 2;            // 0..63
    const int lrow1 = lrow0 + 64;
    const int lc0   = tid & 3;             // 16B chunk in 64B row
    const uint32_t so0 = (uint32_t)(lrow0 * ASTR + lc0 * 16);
    const uint32_t so1 = (uint32_t)(lrow1 * ASTR + lc0 * 16);

    auto load_tile = [&](int kb, int buf) {
        const int kn = kb * KB_ + lc0 * 8;
        const uint32_t off = (uint32_t)(buf * GTILE);
        const long long ga0 = (long long)(bm + lrow0) * lda + kn;
        const long long ga1 = (long long)(bm + lrow1) * lda + kn;
        const long long gb0 = (long long)(bn + lrow0) * ldb + kn;
        const long long gb1 = (long long)(bn + lrow1) * ldb + kn;
        CP16(uA  + off + so0, Ah + ga0);  CP16(uA  + off + so1, Ah + ga1);
        CP16(uBh + off + so0, Bh + gb0);  CP16(uBh + off + so1, Bh + gb1);
        CP16(uBl + off + so0, Bl + gb0);  CP16(uBl + off + so1, Bl + gb1);
    };

    const uint32_t aBase = (uint32_t)((wm + (lane & 15)) * ASTR + (lane >> 4) * 16);
    const uint32_t bBase = (uint32_t)((wn + (lane & 7) + ((lane >> 4) & 1) * 8) * ASTR
                                      + (lane & 8) * 2);

    float acc[4][4][4];
    #pragma unroll
    for (int mt = 0; mt < 4; mt++)
        #pragma unroll
        for (int nt = 0; nt < 4; nt++)
            #pragma unroll
            for (int i = 0; i < 4; i++) acc[mt][nt][i] = 0.f;

    const int nkb = K / KB_;
    load_tile(0, 0); CP_COMMIT;
    load_tile(1, 1); CP_COMMIT;

    for (int kb = 0; kb < nkb; kb++) {
        if (kb + 1 < nkb) { CP_WAIT1; } else { CP_WAIT0; }
        __syncthreads();
        const uint32_t boff = (uint32_t)((kb & 1) * GTILE);

        #pragma unroll
        for (int ks = 0; ks < 2; ks++) {
            const uint32_t ksb = ks * 32;
            uint32_t ah[4][4];
            #pragma unroll
            for (int mt = 0; mt < 4; mt++)
                ldsm_x4(ah[mt], uA + boff + aBase + mt * (16 * ASTR) + ksb);
            uint32_t bh[2][4], bl[2][4];
            #pragma unroll
            for (int g = 0; g < 2; g++) {
                ldsm_x4(bh[g], uBh + boff + bBase + g * (16 * ASTR) + ksb);
                ldsm_x4(bl[g], uBl + boff + bBase + g * (16 * ASTR) + ksb);
            }
            #pragma unroll
            for (int mt = 0; mt < 4; mt++) {
                #pragma unroll
                for (int nt = 0; nt < 4; nt++) {
                    mma16816(acc[mt][nt], ah[mt],
                             bh[nt >> 1][(nt & 1) * 2], bh[nt >> 1][(nt & 1) * 2 + 1]);
                    mma16816(acc[mt][nt], ah[mt],
                             bl[nt >> 1][(nt & 1) * 2], bl[nt >> 1][(nt & 1) * 2 + 1]);
                }
            }
        }
        __syncthreads();

        if (kb + 2 < nkb) { load_tile(kb + 2, kb & 1); CP_COMMIT; }
    }

    const int er = lane >> 2;
    const int ec = (lane & 3) * 2;
    #pragma unroll
    for (int mt = 0; mt < 4; mt++) {
        #pragma unroll
        for (int half = 0; half < 2; half++) {
            const int m = bm + wm + mt * 16 + er + half * 8;
            #pragma unroll
            for (int nt = 0; nt < 4; nt++) {
                const int n = bn + wn + nt * 8 + ec;
                float v0 = acc[mt][nt][half * 2 + 0] * alpha;
                float v1 = acc[mt][nt][half * 2 + 1] * alpha;
                if (bias) { v0 += __ldg(&bias[n]); v1 += __ldg(&bias[n + 1]); }
                if (relu) { v0 = fmaxf(v0, 0.f); v1 = fmaxf(v1, 0.f); }
                if (OUT_SPLIT) {
                    __half2 hi2 = __floats2half2_rn(v0, v1);
                    *(uint32_t*)&Ch[(long long)m * ldc + n] = *(uint32_t*)&hi2;
                    if (Cl) {
                        float l0 = v0 - __half2float(__low2half(hi2));
                        float l1 = v1 - __half2float(__high2half(hi2));
                        __half2 lo2 = __floats2half2_rn(l0, l1);
                        *(uint32_t*)&Cl[(long long)m * ldc + n] = *(uint32_t*)&lo2;
                    }
                } else {
                    *(float2*)&Cf[(long long)m * ldc + n] = make_float2(v0, v1);
                }
            }
        }
    }
}

// ---------------- reductions / fused split-K reduce + layernorm ----------------
__device__ __forceinline__ float warp_sum(float v) {
    #pragma unroll
    for (int o = 16; o > 0; o >>= 1) v += __shfl_xor_sync(0xffffffffu, v, o);
    return v;
}
__device__ __forceinline__ float block_reduce_sum(float v) {
    __shared__ float sm2[32];
    __shared__ float res;
    int lane = threadIdx.x & 31;
    int wid  = threadIdx.x >> 5;
    v = warp_sum(v);
    __syncthreads();
    if (lane == 0) sm2[wid] = v;
    __syncthreads();
    if (wid == 0) {
        int nw = blockDim.x >> 5;
        float x = (lane < nw) ? sm2[lane] : 0.f;
        x = warp_sum(x);
        if (lane == 0) res = x;
    }
    __syncthreads();
    return res;
}

__global__ void ln_red_kernel(const float* __restrict__ part, long long pstride,
                              const float* __restrict__ bias,
                              const float* __restrict__ resid,
                              const float* __restrict__ g,
                              const float* __restrict__ b,
                              float* __restrict__ outf,
                              h16* __restrict__ oh)
{
    const int t = threadIdx.x;
    const long long base = (long long)blockIdx.x * E_ + t;
    float v = part[base] + part[base + pstride]
            + part[base + 2 * pstride] + part[base + 3 * pstride];
    if (bias) v += bias[t];
    v += resid[base];
    float mean = block_reduce_sum(v) * (1.f / E_);
    float d = v - mean;
    float var = block_reduce_sum(d * d) * (1.f / E_);
    float r = d * rsqrtf(var + EPS_) * g[t] + b[t];
    if (outf) outf[base] = r;
    if (oh) oh[base] = __float2half_rn(r);
}

// ---------------- prep kernels ----------------
__global__ void split_kernel(const float* __restrict__ in,
                             h16* __restrict__ oh, int n)
{
    int i = blockIdx.x * blockDim.x + threadIdx.x;
    if (i < n) oh[i] = __float2half_rn(in[i]);
}

__device__ __forceinline__ void wsplit_tile(const float* W, int R, int C,
                                            h16* oh, h16* ol,
                                            int c0, int r0, int tx, int ty)
{
    __shared__ float t[32][33];
    #pragma unroll
    for (int j = 0; j < 4; j++) {
        int r = ty + 8 * j;
        t[r][tx] = W[(long long)(r0 + r) * C + c0 + tx];
    }
    __syncthreads();
    #pragma unroll
    for (int j = 0; j < 4; j++) {
        int r = ty + 8 * j;
        float f = t[tx][r];
        h16 hi = __float2half_rn(f);
        long long o = (long long)(c0 + r) * R + r0 + tx;
        oh[o] = hi;
        ol[o] = __float2half_rn(f - __half2float(hi));
    }
}

__global__ void wsplit_qkv(const float* __restrict__ Wq, const float* __restrict__ Wk,
                           const float* __restrict__ Wv,
                           h16* __restrict__ oh, h16* __restrict__ ol)
{
    const float* W = (blockIdx.z == 0) ? Wq : (blockIdx.z == 1) ? Wk : Wv;
    h16* ph = oh + (size_t)blockIdx.z * INNER_ * E_;
    h16* pl = ol + (size_t)blockIdx.z * INNER_ * E_;
    wsplit_tile(W, E_, INNER_, ph, pl, blockIdx.x * 32, blockIdx.y * 32,
                threadIdx.x, threadIdx.y);
}

__global__ void wsplit_misc(const float* __restrict__ Wo, const float* __restrict__ W1,
                            const float* __restrict__ W2,
                            h16* __restrict__ woh, h16* __restrict__ wol,
                            h16* __restrict__ w1h, h16* __restrict__ w1l,
                            h16* __restrict__ w2h, h16* __restrict__ w2l)
{
    const float* W; h16 *ph, *pl; int R, C;
    if (blockIdx.z == 0)      { W = Wo; ph = woh; pl = wol; R = INNER_; C = E_; }
    else if (blockIdx.z == 1) { W = W1; ph = w1h; pl = w1l; R = E_; C = DFF_; }
    else                      { W = W2; ph = w2h; pl = w2l; R = DFF_; C = E_; }
    if ((int)blockIdx.x * 32 >= C || (int)blockIdx.y * 32 >= R) return;
    wsplit_tile(W, R, C, ph, pl, blockIdx.x * 32, blockIdx.y * 32,
                threadIdx.x, threadIdx.y);
}

__global__ void vtrans_kernel(const h16* __restrict__ qkvh,
                              h16* __restrict__ vth)
{
    __shared__ h16 th[32][33];
    const int z = blockIdx.z;
    const int b = z / H_, h = z % H_;
    const int s0 = blockIdx.x * 32;
    const int d0 = blockIdx.y * 32;
    const int tx = threadIdx.x, ty = threadIdx.y;
    const long long ibase = (long long)b * S_ * QKVW_ + 4096 + (long long)h * DH_;
    const long long obase = (long long)z * DH_ * S_;
    #pragma unroll
    for (int j = 0; j < 4; j++) {
        int r = ty + 8 * j;
        th[r][tx] = qkvh[ibase + (long long)(s0 + r) * QKVW_ + d0 + tx];
    }
    __syncthreads();
    #pragma unroll
    for (int j = 0; j < 4; j++) {
        int r = ty + 8 * j;
        vth[obase + (long long)(d0 + r) * S_ + s0 + tx] = th[tx][r];
    }
}

// ---------------- launch ----------------
extern "C" void kernel_launch(void* const* d_in, const int* in_sizes, int n_in,
                              void* d_out, int out_size)
{
    const float* x    = (const float*)d_in[0];
    const float* Wq   = (const float*)d_in[1];
    const float* Wk   = (const float*)d_in[2];
    const float* Wv   = (const float*)d_in[3];
    const float* Wo   = (const float*)d_in[4];
    const float* W1   = (const float*)d_in[5];
    const float* b1   = (const float*)d_in[6];
    const float* W2   = (const float*)d_in[7];
    const float* b2   = (const float*)d_in[8];
    const float* ln1g = (const float*)d_in[9];
    const float* ln1b = (const float*)d_in[10];
    const float* ln2g = (const float*)d_in[11];
    const float* ln2b = (const float*)d_in[12];

    #define SYM(p, s) p; cudaGetSymbolAddress((void**)&p, s)
    h16 *SYM(xh, g_xh);
    h16 *SYM(wqkvh, g_wqkvT_h); h16 *SYM(wqkvl, g_wqkvT_l);
    h16 *SYM(woh, g_woT_h); h16 *SYM(wol, g_woT_l);
    h16 *SYM(w1h, g_w1T_h); h16 *SYM(w1l, g_w1T_l);
    h16 *SYM(w2h, g_w2T_h); h16 *SYM(w2l, g_w2T_l);
    h16 *SYM(qkvh, g_qkvh); h16 *SYM(qkvl, g_qkvl);
    h16 *SYM(vth, g_vth);
    h16 *SYM(oh, g_oh);
    float *SYM(part, g_part);
    float *SYM(hf, g_hf);
    h16 *SYM(hh, g_hh);
    h16 *SYM(ffh, g_ffh);

    cudaFuncSetAttribute(flash_kernel, cudaFuncAttributeMaxDynamicSharedMemorySize, F_SMEM);

    const dim3 blk(256);
    const dim3 tblk(32, 8);
    const long long psz = (long long)BSZ * E_;

    // 1) x -> fp16 hi
    split_kernel<<<(BSZ * E_ + 255) / 256, 256>>>(x, xh, BSZ * E_);
    // 2) QKV weights packed split
    { dim3 g(INNER_/32, E_/32, 3); wsplit_qkv<<<g, tblk>>>(Wq, Wk, Wv, wqkvh, wqkvl); }
    // 3) Wo/W1/W2
    { dim3 g(64, 64, 3); wsplit_misc<<<g, tblk>>>(Wo, W1, W2, woh, wol, w1h, w1l, w2h, w2l); }
    // 4) fused QKV projection: [4096,256] @ [256,6144]
    {
        dim3 grd(QKVW_/128, BSZ/128, 1);
        gemm_hmma2<1><<<grd, blk>>>(xh, E_, wqkvh, wqkvl, E_,
            nullptr, qkvh, qkvl, QKVW_, E_, 1, 0,0, 0,0, 0,0,
            nullptr, 1.f, 0);
    }
    // 5) V^T per (b,h) (hi only)
    { dim3 g(S_/32, DH_/32, B_*H_); vtrans_kernel<<<g, tblk>>>(qkvh, vth); }
    // 6) flash attention
    {
        dim3 grd(S_/QBLK, B_*H_);
        flash_kernel<<<grd, blk, F_SMEM>>>(qkvh, qkvl, vth, oh);
    }
    // 7) Wo split-K x4 -> partials ; LN1 reduce (+x resid)
    {
        dim3 grd(E_/128, BSZ/128, 4);
        gemm_hmma2<0><<<grd, blk>>>(oh, INNER_, woh, wol, INNER_,
            part, nullptr, nullptr, E_, INNER_/4, 4,
            0, 512, 0, 512, 0, psz,
            nullptr, 1.f, 0);
        ln_red_kernel<<<BSZ, 256>>>(part, psz, nullptr, x, ln1g, ln1b, hf, hh);
    }
    // 8) ff = relu(h @ W1 + b1)
    {
        dim3 grd(DFF_/128, BSZ/128, 1);
        gemm_hmma2<1><<<grd, blk>>>(hh, E_, w1h, w1l, E_,
            nullptr, ffh, nullptr, DFF_, E_, 1, 0,0, 0,0, 0,0,
            b1, 1.f, 1);
    }
    // 9) FFN2 split-K x4 -> partials ; LN2 reduce (+b2 +h resid) -> out
    {
        dim3 grd(E_/128, BSZ/128, 4);
        gemm_hmma2<0><<<grd, blk>>>(ffh, DFF_, w2h, w2l, DFF_,
            part, nullptr, nullptr, E_, DFF_/4, 4,
            0, 256, 0, 256, 0, psz,
            nullptr, 1.f, 0);
        ln_red_kernel<<<BSZ, 256>>>(part, psz, b2, hf, ln2g, ln2b,
                                    (float*)d_out, nullptr);
    }
}

// round 11
// speedup vs baseline: 2.2487x; 1.2134x over previous
#include <cuda_runtime.h>
#include <cuda_fp16.h>
#include <cstdint>

#define B_     2
#define S_     2048
#define E_     256
#define H_     8
#define DH_    256
#define INNER_ 2048
#define QKVW_  (3*INNER_)   // 6144
#define DFF_   1024
#define BSZ    (B_*S_)
#define EPS_   1e-6f

typedef __half h16;

// ---------------- device scratch ----------------
__device__ h16   g_xh [(size_t)BSZ * E_];
__device__ h16   g_wqkvT_h[(size_t)QKVW_ * E_];
__device__ h16   g_wqkvT_l[(size_t)QKVW_ * E_];
__device__ h16   g_woT_h[(size_t)E_ * INNER_];
__device__ h16   g_woT_l[(size_t)E_ * INNER_];
__device__ h16   g_w1T_h[(size_t)DFF_ * E_];
__device__ h16   g_w1T_l[(size_t)DFF_ * E_];
__device__ h16   g_w2T_h[(size_t)E_ * DFF_];
__device__ h16   g_w2T_l[(size_t)E_ * DFF_];
__device__ h16   g_qkvh[(size_t)BSZ * QKVW_];     // q|k|v packed, ld=6144 (fp16 hi only)
__device__ h16   g_vth[(size_t)BSZ * INNER_];     // V^T per (b,h): [B*H][DH][S]
__device__ h16   g_oh [(size_t)BSZ * INNER_];
__device__ float g_part[(size_t)4 * BSZ * E_];    // split-K partials
__device__ float g_hf [(size_t)BSZ * E_];
__device__ h16   g_hh [(size_t)BSZ * E_];
__device__ h16   g_ffh[(size_t)BSZ * DFF_];

// ---------------- helpers ----------------
__device__ __forceinline__ uint32_t smem_u32(const void* p) {
    uint32_t a;
    asm("{ .reg .u64 t; cvta.to.shared.u64 t, %1; cvt.u32.u64 %0, t; }"
        : "=r"(a) : "l"(p));
    return a;
}
__device__ __forceinline__ void ldsm_x4(uint32_t* r, uint32_t a) {
    asm volatile("ldmatrix.sync.aligned.m8n8.x4.shared.b16 {%0,%1,%2,%3}, [%4];"
                 : "=r"(r[0]), "=r"(r[1]), "=r"(r[2]), "=r"(r[3]) : "r"(a));
}
__device__ __forceinline__ void mma16816(float* c, const uint32_t* a,
                                         uint32_t b0, uint32_t b1) {
    asm volatile(
        "mma.sync.aligned.m16n8k16.row.col.f32.f16.f16.f32 "
        "{%0,%1,%2,%3}, {%4,%5,%6,%7}, {%8,%9}, {%0,%1,%2,%3};"
        : "+f"(c[0]), "+f"(c[1]), "+f"(c[2]), "+f"(c[3])
        : "r"(a[0]), "r"(a[1]), "r"(a[2]), "r"(a[3]), "r"(b0), "r"(b1));
}
#define CP16(dst, src) \
    asm volatile("cp.async.cg.shared.global [%0], [%1], 16;" :: "r"(dst), "l"(src) : "memory")
#define CP_COMMIT  asm volatile("cp.async.commit_group;" ::: "memory")
#define CP_WAIT0   asm volatile("cp.async.wait_group 0;" ::: "memory")
#define CP_WAIT1   asm volatile("cp.async.wait_group 1;" ::: "memory")

__device__ __forceinline__ uint32_t packh2(float x, float y) {
    __half2 t = __floats2half2_rn(x, y);
    return *(uint32_t*)&t;
}

// ================= flash attention =================
// grid (S_/128, B_*H_), 256 thr (8 warps x m16). Q resident (64KB),
// K + V (fp16 hi) double-buffered (KVBLK=32), one cp.async group per iter.
#define QBLK   128
#define KVBLK  32
#define NKVT   (S_/KVBLK)      // 64
#define FO_K   65536           // 2 slots x 16384
#define FO_V   98304           // 2 slots x 16384
#define F_SMEM 131072

__global__ void __launch_bounds__(256)
flash_kernel(const h16* __restrict__ qkvh,
             const h16* __restrict__ vth_g,
             h16* __restrict__ oh_g)
{
    extern __shared__ __align__(128) char sm[];
    const uint32_t sb = smem_u32(sm);
    const int tid = threadIdx.x, wid = tid >> 5, lane = tid & 31;
    const int bh = blockIdx.y;
    const int b = bh >> 3, hd = bh & 7;
    const int q0 = blockIdx.x * QBLK;

    auto load_k = [&](int kv0, uint32_t slot) {      // 1024 x 16B
        #pragma unroll
        for (int it = 0; it < 4; it++) {
            int c = tid + it * 256;
            int row = c >> 5, kc = c & 31;
            const h16* src = qkvh
                + ((size_t)(b * S_ + kv0 + row) * QKVW_ + 2048 + hd * 256 + kc * 8);
            CP16(slot + row * 512 + (uint32_t)((kc ^ (row & 7)) << 4), src);
        }
    };
    auto load_v = [&](int kv0, uint32_t slot) {      // 1024 x 16B
        #pragma unroll
        for (int it = 0; it < 4; it++) {
            int c = tid + it * 256;
            int row = c >> 2, kc = c & 3;
            const h16* src = vth_g
                + ((size_t)bh * DH_ * S_ + (size_t)row * S_ + kv0 + kc * 8);
            CP16(slot + row * 64 + (uint32_t)((kc ^ ((row >> 1) & 3)) << 4), src);
        }
    };

    // ---- prologue: G0 = {Q, K0, V0}, G1 = {K1, V1} ----
    #pragma unroll
    for (int it = 0; it < 16; it++) {                 // Q: 4096 x 16B
        int c = tid + it * 256;
        int row = c >> 5, kc = c & 31;
        const h16* src = qkvh
            + ((size_t)(b * S_ + q0 + row) * QKVW_ + hd * 256 + kc * 8);
        CP16(sb + row * 512 + (uint32_t)((kc ^ (row & 7)) << 4), src);
    }
    load_k(0, sb + FO_K);
    load_v(0, sb + FO_V);
    CP_COMMIT;
    load_k(KVBLK, sb + FO_K + 16384);
    load_v(KVBLK, sb + FO_V + 16384);
    CP_COMMIT;

    const int wm    = wid * 16;
    const int a_row = wm + (lane & 15);
    const uint32_t a_rowoff = (uint32_t)(a_row * 512);
    const int a_r7  = a_row & 7;
    const int a_hb  = lane >> 4;
    const int b_row = (lane & 7) + ((lane >> 4) & 1) * 8;
    const int b_kb  = (lane >> 3) & 1;

    float o[32][4];
    #pragma unroll
    for (int i = 0; i < 32; i++) { o[i][0]=0.f; o[i][1]=0.f; o[i][2]=0.f; o[i][3]=0.f; }
    float m0 = -1e30f, m1 = -1e30f, l0 = 0.f, l1 = 0.f;

    for (int i = 0; i < NKVT; i++) {
        if (i + 1 < NKVT) { CP_WAIT1; } else { CP_WAIT0; }   // K(i),V(i) ready
        __syncthreads();
        const uint32_t kbs = sb + FO_K + (uint32_t)((i & 1) * 16384);
        const uint32_t vbs = sb + FO_V + (uint32_t)((i & 1) * 16384);

        // ==== S = Qh Kh^T ====
        float s[4][4];
        #pragma unroll
        for (int nt = 0; nt < 4; nt++) { s[nt][0]=0.f; s[nt][1]=0.f; s[nt][2]=0.f; s[nt][3]=0.f; }
        #pragma unroll
        for (int ks = 0; ks < 16; ks++) {
            const uint32_t aq = a_rowoff + (uint32_t)((((2 * ks + a_hb) ^ a_r7) << 4));
            uint32_t ah4[4];
            ldsm_x4(ah4, sb + aq);
            uint32_t kh4[2][4];
            #pragma unroll
            for (int g2 = 0; g2 < 2; g2++) {
                const int row = g2 * 16 + b_row;
                const uint32_t off = (uint32_t)(row * 512 + (((2 * ks + b_kb) ^ (row & 7)) << 4));
                ldsm_x4(kh4[g2], kbs + off);
            }
            #pragma unroll
            for (int nt = 0; nt < 4; nt++)
                mma16816(s[nt], ah4, kh4[nt >> 1][(nt & 1) * 2], kh4[nt >> 1][(nt & 1) * 2 + 1]);
        }

        // ==== online softmax (rows g=lane>>2, g+8) ====
        float mx0 = -1e30f, mx1 = -1e30f;
        #pragma unroll
        for (int nt = 0; nt < 4; nt++) {
            s[nt][0] *= 0.0625f; s[nt][1] *= 0.0625f;
            s[nt][2] *= 0.0625f; s[nt][3] *= 0.0625f;
            mx0 = fmaxf(mx0, fmaxf(s[nt][0], s[nt][1]));
            mx1 = fmaxf(mx1, fmaxf(s[nt][2], s[nt][3]));
        }
        mx0 = fmaxf(mx0, __shfl_xor_sync(0xffffffffu, mx0, 1));
        mx0 = fmaxf(mx0, __shfl_xor_sync(0xffffffffu, mx0, 2));
        mx1 = fmaxf(mx1, __shfl_xor_sync(0xffffffffu, mx1, 1));
        mx1 = fmaxf(mx1, __shfl_xor_sync(0xffffffffu, mx1, 2));
        const float mn0 = fmaxf(m0, mx0), mn1 = fmaxf(m1, mx1);
        const float sc0 = __expf(m0 - mn0), sc1 = __expf(m1 - mn1);
        m0 = mn0; m1 = mn1;
        l0 *= sc0; l1 *= sc1;
        if (sc0 != 1.f || sc1 != 1.f) {
            #pragma unroll
            for (int nt = 0; nt < 32; nt++) {
                o[nt][0] *= sc0; o[nt][1] *= sc0;
                o[nt][2] *= sc1; o[nt][3] *= sc1;
            }
        }
        float rs0 = 0.f, rs1 = 0.f;
        #pragma unroll
        for (int nt = 0; nt < 4; nt++) {
            s[nt][0] = __expf(s[nt][0] - m0);
            s[nt][1] = __expf(s[nt][1] - m0);
            s[nt][2] = __expf(s[nt][2] - m1);
            s[nt][3] = __expf(s[nt][3] - m1);
            rs0 += s[nt][0] + s[nt][1];
            rs1 += s[nt][2] + s[nt][3];
        }
        rs0 += __shfl_xor_sync(0xffffffffu, rs0, 1);
        rs0 += __shfl_xor_sync(0xffffffffu, rs0, 2);
        rs1 += __shfl_xor_sync(0xffffffffu, rs1, 1);
        rs1 += __shfl_xor_sync(0xffffffffu, rs1, 2);
        l0 += rs0; l1 += rs1;

        // P -> fp16 A-fragments
        uint32_t pah[2][4];
        #pragma unroll
        for (int ks = 0; ks < 2; ks++) {
            const int j0 = 2 * ks, j1 = 2 * ks + 1;
            pah[ks][0] = packh2(s[j0][0], s[j0][1]);
            pah[ks][1] = packh2(s[j0][2], s[j0][3]);
            pah[ks][2] = packh2(s[j1][0], s[j1][1]);
            pah[ks][3] = packh2(s[j1][2], s[j1][3]);
        }

        // ==== O += P @ Vh ====
        #pragma unroll
        for (int half = 0; half < 2; half++) {
            #pragma unroll
            for (int ks = 0; ks < 2; ks++) {
                #pragma unroll
                for (int j2 = 0; j2 < 8; j2++) {
                    const int row = half * 128 + j2 * 16 + b_row;
                    const uint32_t voff = (uint32_t)(row * 64 +
                        (((2 * ks + b_kb) ^ ((row >> 1) & 3)) << 4));
                    const int nt = half * 16 + j2 * 2;
                    uint32_t vh4[4];
                    ldsm_x4(vh4, vbs + voff);
                    mma16816(o[nt],     pah[ks], vh4[0], vh4[1]);
                    mma16816(o[nt + 1], pah[ks], vh4[2], vh4[3]);
                }
            }
        }
        __syncthreads();                   // all warps done with slot (i&1)

        if (i + 2 < NKVT) {                // refill freed slots, one group
            load_k((i + 2) * KVBLK, sb + FO_K + (uint32_t)((i & 1) * 16384));
            load_v((i + 2) * KVBLK, sb + FO_V + (uint32_t)((i & 1) * 16384));
            CP_COMMIT;
        }
    }

    // ==== normalize + store O ====
    const float inv0 = 1.f / l0, inv1 = 1.f / l1;
    const int g  = lane >> 2;
    const int t2 = (lane & 3) * 2;
    const size_t base0 = (size_t)(b * S_ + q0 + wm + g) * INNER_ + hd * 256 + t2;
    const size_t base1 = base0 + (size_t)8 * INNER_;
    #pragma unroll
    for (int nt = 0; nt < 32; nt++) {
        *(uint32_t*)&oh_g[base0 + (size_t)nt * 8] = packh2(o[nt][0] * inv0, o[nt][1] * inv0);
        *(uint32_t*)&oh_g[base1 + (size_t)nt * 8] = packh2(o[nt][2] * inv1, o[nt][3] * inv1);
    }
}

// ---------------- fp16x2 HMMA GEMM, cp.async 2-stage, 2 CTA/SM ----------------
// C = alpha * Ah @ (Bh+Bl)^T
#define KB_    32
#define ASTR   80
#define GTILE  (128 * ASTR)    // 10240 B per tile buffer

template<int OUT_SPLIT>
__global__ void __launch_bounds__(256, 2)
gemm_hmma2(const h16* __restrict__ Ah, int lda,
           const h16* __restrict__ Bh, const h16* __restrict__ Bl, int ldb,
           float* __restrict__ Cf, h16* __restrict__ Ch, h16* __restrict__ Cl, int ldc,
           int K, int zdiv,
           long long sA1, long long sA2,
           long long sB1, long long sB2,
           long long sC1, long long sC2,
           const float* __restrict__ bias,
           float alpha, int relu)
{
    __shared__ __align__(16) char sA [2 * GTILE];
    __shared__ __align__(16) char sBh[2 * GTILE];
    __shared__ __align__(16) char sBl[2 * GTILE];

    const int z  = blockIdx.z;
    const int zq = z / zdiv, zr = z % zdiv;
    Ah += (long long)zq * sA1 + (long long)zr * sA2;
    Bh += (long long)zq * sB1 + (long long)zr * sB2;
    Bl += (long long)zq * sB1 + (long long)zr * sB2;
    const long long coff = (long long)zq * sC1 + (long long)zr * sC2;
    if (Cf) Cf += coff;
    if (Ch) Ch += coff;
    if (Cl) Cl += coff;

    const int bm   = blockIdx.y * 128;
    const int bn   = blockIdx.x * 128;
    const int tid  = threadIdx.x;
    const int wid  = tid >> 5;
    const int lane = tid & 31;
    const int wm   = (wid & 1) * 64;
    const int wn   = (wid >> 1) * 32;

    const uint32_t uA  = smem_u32(sA);
    const uint32_t uBh = smem_u32(sBh);
    const uint32_t uBl = smem_u32(sBl);

    const int lrow0 = tid >> 2;
    const int lrow1 = lrow0 + 64;
    const int lc0   = tid & 3;
    const uint32_t so0 = (uint32_t)(lrow0 * ASTR + lc0 * 16);
    const uint32_t so1 = (uint32_t)(lrow1 * ASTR + lc0 * 16);

    auto load_tile = [&](int kb, int buf) {
        const int kn = kb * KB_ + lc0 * 8;
        const uint32_t off = (uint32_t)(buf * GTILE);
        const long long ga0 = (long long)(bm + lrow0) * lda + kn;
        const long long ga1 = (long long)(bm + lrow1) * lda + kn;
        const long long gb0 = (long long)(bn + lrow0) * ldb + kn;
        const long long gb1 = (long long)(bn + lrow1) * ldb + kn;
        CP16(uA  + off + so0, Ah + ga0);  CP16(uA  + off + so1, Ah + ga1);
        CP16(uBh + off + so0, Bh + gb0);  CP16(uBh + off + so1, Bh + gb1);
        CP16(uBl + off + so0, Bl + gb0);  CP16(uBl + off + so1, Bl + gb1);
    };

    const uint32_t aBase = (uint32_t)((wm + (lane & 15)) * ASTR + (lane >> 4) * 16);
    const uint32_t bBase = (uint32_t)((wn + (lane & 7) + ((lane >> 4) & 1) * 8) * ASTR
                                      + (lane & 8) * 2);

    float acc[4][4][4];
    #pragma unroll
    for (int mt = 0; mt < 4; mt++)
        #pragma unroll
        for (int nt = 0; nt < 4; nt++)
            #pragma unroll
            for (int i = 0; i < 4; i++) acc[mt][nt][i] = 0.f;

    const int nkb = K / KB_;
    load_tile(0, 0); CP_COMMIT;
    load_tile(1, 1); CP_COMMIT;

    for (int kb = 0; kb < nkb; kb++) {
        if (kb + 1 < nkb) { CP_WAIT1; } else { CP_WAIT0; }
        __syncthreads();
        const uint32_t boff = (uint32_t)((kb & 1) * GTILE);

        #pragma unroll
        for (int ks = 0; ks < 2; ks++) {
            const uint32_t ksb = ks * 32;
            uint32_t ah[4][4];
            #pragma unroll
            for (int mt = 0; mt < 4; mt++)
                ldsm_x4(ah[mt], uA + boff + aBase + mt * (16 * ASTR) + ksb);
            uint32_t bh[2][4], bl[2][4];
            #pragma unroll
            for (int g = 0; g < 2; g++) {
                ldsm_x4(bh[g], uBh + boff + bBase + g * (16 * ASTR) + ksb);
                ldsm_x4(bl[g], uBl + boff + bBase + g * (16 * ASTR) + ksb);
            }
            #pragma unroll
            for (int mt = 0; mt < 4; mt++) {
                #pragma unroll
                for (int nt = 0; nt < 4; nt++) {
                    mma16816(acc[mt][nt], ah[mt],
                             bh[nt >> 1][(nt & 1) * 2], bh[nt >> 1][(nt & 1) * 2 + 1]);
                    mma16816(acc[mt][nt], ah[mt],
                             bl[nt >> 1][(nt & 1) * 2], bl[nt >> 1][(nt & 1) * 2 + 1]);
                }
            }
        }
        __syncthreads();

        if (kb + 2 < nkb) { load_tile(kb + 2, kb & 1); CP_COMMIT; }
    }

    const int er = lane >> 2;
    const int ec = (lane & 3) * 2;
    #pragma unroll
    for (int mt = 0; mt < 4; mt++) {
        #pragma unroll
        for (int half = 0; half < 2; half++) {
            const int m = bm + wm + mt * 16 + er + half * 8;
            #pragma unroll
            for (int nt = 0; nt < 4; nt++) {
                const int n = bn + wn + nt * 8 + ec;
                float v0 = acc[mt][nt][half * 2 + 0] * alpha;
                float v1 = acc[mt][nt][half * 2 + 1] * alpha;
                if (bias) { v0 += __ldg(&bias[n]); v1 += __ldg(&bias[n + 1]); }
                if (relu) { v0 = fmaxf(v0, 0.f); v1 = fmaxf(v1, 0.f); }
                if (OUT_SPLIT) {
                    __half2 hi2 = __floats2half2_rn(v0, v1);
                    *(uint32_t*)&Ch[(long long)m * ldc + n] = *(uint32_t*)&hi2;
                    if (Cl) {
                        float l0 = v0 - __half2float(__low2half(hi2));
                        float l1 = v1 - __half2float(__high2half(hi2));
                        __half2 lo2 = __floats2half2_rn(l0, l1);
                        *(uint32_t*)&Cl[(long long)m * ldc + n] = *(uint32_t*)&lo2;
                    }
                } else {
                    *(float2*)&Cf[(long long)m * ldc + n] = make_float2(v0, v1);
                }
            }
        }
    }
}

// ---------------- reductions / fused split-K reduce + layernorm ----------------
__device__ __forceinline__ float warp_sum(float v) {
    #pragma unroll
    for (int o = 16; o > 0; o >>= 1) v += __shfl_xor_sync(0xffffffffu, v, o);
    return v;
}
__device__ __forceinline__ float block_reduce_sum(float v) {
    __shared__ float sm2[32];
    __shared__ float res;
    int lane = threadIdx.x & 31;
    int wid  = threadIdx.x >> 5;
    v = warp_sum(v);
    __syncthreads();
    if (lane == 0) sm2[wid] = v;
    __syncthreads();
    if (wid == 0) {
        int nw = blockDim.x >> 5;
        float x = (lane < nw) ? sm2[lane] : 0.f;
        x = warp_sum(x);
        if (lane == 0) res = x;
    }
    __syncthreads();
    return res;
}

__global__ void ln_red_kernel(const float* __restrict__ part, long long pstride,
                              const float* __restrict__ bias,
                              const float* __restrict__ resid,
                              const float* __restrict__ g,
                              const float* __restrict__ b,
                              float* __restrict__ outf,
                              h16* __restrict__ oh)
{
    const int t = threadIdx.x;
    const long long base = (long long)blockIdx.x * E_ + t;
    float v = part[base] + part[base + pstride]
            + part[base + 2 * pstride] + part[base + 3 * pstride];
    if (bias) v += bias[t];
    v += resid[base];
    float mean = block_reduce_sum(v) * (1.f / E_);
    float d = v - mean;
    float var = block_reduce_sum(d * d) * (1.f / E_);
    float r = d * rsqrtf(var + EPS_) * g[t] + b[t];
    if (outf) outf[base] = r;
    if (oh) oh[base] = __float2half_rn(r);
}

// ---------------- prep kernels ----------------
__global__ void split_kernel(const float* __restrict__ in,
                             h16* __restrict__ oh, int n)
{
    int i = blockIdx.x * blockDim.x + threadIdx.x;
    if (i < n) oh[i] = __float2half_rn(in[i]);
}

__device__ __forceinline__ void wsplit_tile(const float* W, int R, int C,
                                            h16* oh, h16* ol,
                                            int c0, int r0, int tx, int ty)
{
    __shared__ float t[32][33];
    #pragma unroll
    for (int j = 0; j < 4; j++) {
        int r = ty + 8 * j;
        t[r][tx] = W[(long long)(r0 + r) * C + c0 + tx];
    }
    __syncthreads();
    #pragma unroll
    for (int j = 0; j < 4; j++) {
        int r = ty + 8 * j;
        float f = t[tx][r];
        h16 hi = __float2half_rn(f);
        long long o = (long long)(c0 + r) * R + r0 + tx;
        oh[o] = hi;
        ol[o] = __float2half_rn(f - __half2float(hi));
    }
}

__global__ void wsplit_qkv(const float* __restrict__ Wq, const float* __restrict__ Wk,
                           const float* __restrict__ Wv,
                           h16* __restrict__ oh, h16* __restrict__ ol)
{
    const float* W = (blockIdx.z == 0) ? Wq : (blockIdx.z == 1) ? Wk : Wv;
    h16* ph = oh + (size_t)blockIdx.z * INNER_ * E_;
    h16* pl = ol + (size_t)blockIdx.z * INNER_ * E_;
    wsplit_tile(W, E_, INNER_, ph, pl, blockIdx.x * 32, blockIdx.y * 32,
                threadIdx.x, threadIdx.y);
}

__global__ void wsplit_misc(const float* __restrict__ Wo, const float* __restrict__ W1,
                            const float* __restrict__ W2,
                            h16* __restrict__ woh, h16* __restrict__ wol,
                            h16* __restrict__ w1h, h16* __restrict__ w1l,
                            h16* __restrict__ w2h, h16* __restrict__ w2l)
{
    const float* W; h16 *ph, *pl; int R, C;
    if (blockIdx.z == 0)      { W = Wo; ph = woh; pl = wol; R = INNER_; C = E_; }
    else if (blockIdx.z == 1) { W = W1; ph = w1h; pl = w1l; R = E_; C = DFF_; }
    else                      { W = W2; ph = w2h; pl = w2l; R = DFF_; C = E_; }
    if ((int)blockIdx.x * 32 >= C || (int)blockIdx.y * 32 >= R) return;
    wsplit_tile(W, R, C, ph, pl, blockIdx.x * 32, blockIdx.y * 32,
                threadIdx.x, threadIdx.y);
}

__global__ void vtrans_kernel(const h16* __restrict__ qkvh,
                              h16* __restrict__ vth)
{
    __shared__ h16 th[32][33];
    const int z = blockIdx.z;
    const int b = z / H_, h = z % H_;
    const int s0 = blockIdx.x * 32;
    const int d0 = blockIdx.y * 32;
    const int tx = threadIdx.x, ty = threadIdx.y;
    const long long ibase = (long long)b * S_ * QKVW_ + 4096 + (long long)h * DH_;
    const long long obase = (long long)z * DH_ * S_;
    #pragma unroll
    for (int j = 0; j < 4; j++) {
        int r = ty + 8 * j;
        th[r][tx] = qkvh[ibase + (long long)(s0 + r) * QKVW_ + d0 + tx];
    }
    __syncthreads();
    #pragma unroll
    for (int j = 0; j < 4; j++) {
        int r = ty + 8 * j;
        vth[obase + (long long)(d0 + r) * S_ + s0 + tx] = th[tx][r];
    }
}

// ---------------- launch ----------------
extern "C" void kernel_launch(void* const* d_in, const int* in_sizes, int n_in,
                              void* d_out, int out_size)
{
    const float* x    = (const float*)d_in[0];
    const float* Wq   = (const float*)d_in[1];
    const float* Wk   = (const float*)d_in[2];
    const float* Wv   = (const float*)d_in[3];
    const float* Wo   = (const float*)d_in[4];
    const float* W1   = (const float*)d_in[5];
    const float* b1   = (const float*)d_in[6];
    const float* W2   = (const float*)d_in[7];
    const float* b2   = (const float*)d_in[8];
    const float* ln1g = (const float*)d_in[9];
    const float* ln1b = (const float*)d_in[10];
    const float* ln2g = (const float*)d_in[11];
    const float* ln2b = (const float*)d_in[12];

    #define SYM(p, s) p; cudaGetSymbolAddress((void**)&p, s)
    h16 *SYM(xh, g_xh);
    h16 *SYM(wqkvh, g_wqkvT_h); h16 *SYM(wqkvl, g_wqkvT_l);
    h16 *SYM(woh, g_woT_h); h16 *SYM(wol, g_woT_l);
    h16 *SYM(w1h, g_w1T_h); h16 *SYM(w1l, g_w1T_l);
    h16 *SYM(w2h, g_w2T_h); h16 *SYM(w2l, g_w2T_l);
    h16 *SYM(qkvh, g_qkvh);
    h16 *SYM(vth, g_vth);
    h16 *SYM(oh, g_oh);
    float *SYM(part, g_part);
    float *SYM(hf, g_hf);
    h16 *SYM(hh, g_hh);
    h16 *SYM(ffh, g_ffh);

    cudaFuncSetAttribute(flash_kernel, cudaFuncAttributeMaxDynamicSharedMemorySize, F_SMEM);

    const dim3 blk(256);
    const dim3 tblk(32, 8);
    const long long psz = (long long)BSZ * E_;

    // 1) x -> fp16
    split_kernel<<<(BSZ * E_ + 255) / 256, 256>>>(x, xh, BSZ * E_);
    // 2) QKV weights packed split
    { dim3 g(INNER_/32, E_/32, 3); wsplit_qkv<<<g, tblk>>>(Wq, Wk, Wv, wqkvh, wqkvl); }
    // 3) Wo/W1/W2
    { dim3 g(64, 64, 3); wsplit_misc<<<g, tblk>>>(Wo, W1, W2, woh, wol, w1h, w1l, w2h, w2l); }
    // 4) fused QKV projection: [4096,256] @ [256,6144] (hi output only)
    {
        dim3 grd(QKVW_/128, BSZ/128, 1);
        gemm_hmma2<1><<<grd, blk>>>(xh, E_, wqkvh, wqkvl, E_,
            nullptr, qkvh, nullptr, QKVW_, E_, 1, 0,0, 0,0, 0,0,
            nullptr, 1.f, 0);
    }
    // 5) V^T per (b,h)
    { dim3 g(S_/32, DH_/32, B_*H_); vtrans_kernel<<<g, tblk>>>(qkvh, vth); }
    // 6) flash attention (single-fp16 QK^T, PV)
    {
        dim3 grd(S_/QBLK, B_*H_);
        flash_kernel<<<grd, blk, F_SMEM>>>(qkvh, vth, oh);
    }
    // 7) Wo split-K x4 -> partials ; LN1 reduce (+x resid)
    {
        dim3 grd(E_/128, BSZ/128, 4);
        gemm_hmma2<0><<<grd, blk>>>(oh, INNER_, woh, wol, INNER_,
            part, nullptr, nullptr, E_, INNER_/4, 4,
            0, 512, 0, 512, 0, psz,
            nullptr, 1.f, 0);
        ln_red_kernel<<<BSZ, 256>>>(part, psz, nullptr, x, ln1g, ln1b, hf, hh);
    }
    // 8) ff = relu(h @ W1 + b1)
    {
        dim3 grd(DFF_/128, BSZ/128, 1);
        gemm_hmma2<1><<<grd, blk>>>(hh, E_, w1h, w1l, E_,
            nullptr, ffh, nullptr, DFF_, E_, 1, 0,0, 0,0, 0,0,
            b1, 1.f, 1);
    }
    // 9) FFN2 split-K x4 -> partials ; LN2 reduce (+b2 +h resid) -> out
    {
        dim3 grd(E_/128, BSZ/128, 4);
        gemm_hmma2<0><<<grd, blk>>>(ffh, DFF_, w2h, w2l, DFF_,
            part, nullptr, nullptr, E_, DFF_/4, 4,
            0, 256, 0, 256, 0, psz,
            nullptr, 1.f, 0);
        ln_red_kernel<<<BSZ, 256>>>(part, psz, b2, hf, ln2g, ln2b,
                                    (float*)d_out, nullptr);
    }
}

// round 12
// speedup vs baseline: 2.4773x; 1.1017x over previous
#include <cuda_runtime.h>
#include <cuda_fp16.h>
#include <cstdint>

#define B_     2
#define S_     2048
#define E_     256
#define H_     8
#define DH_    256
#define INNER_ 2048
#define QKVW_  (3*INNER_)   // 6144
#define DFF_   1024
#define BSZ    (B_*S_)
#define EPS_   1e-6f

typedef __half h16;

// ---------------- device scratch ----------------
__device__ h16   g_xh [(size_t)BSZ * E_];
__device__ h16   g_wqkvT[(size_t)QKVW_ * E_];
__device__ h16   g_woT [(size_t)E_ * INNER_];
__device__ h16   g_w1T [(size_t)DFF_ * E_];
__device__ h16   g_w2T [(size_t)E_ * DFF_];
__device__ h16   g_qkvh[(size_t)BSZ * QKVW_];     // q|k|v packed, ld=6144
__device__ h16   g_vth[(size_t)BSZ * INNER_];     // V^T per (b,h): [B*H][DH][S]
__device__ h16   g_oh [(size_t)BSZ * INNER_];
__device__ float g_part[(size_t)4 * BSZ * E_];    // split-K partials
__device__ float g_hf [(size_t)BSZ * E_];
__device__ h16   g_hh [(size_t)BSZ * E_];
__device__ h16   g_ffh[(size_t)BSZ * DFF_];

// ---------------- helpers ----------------
__device__ __forceinline__ uint32_t smem_u32(const void* p) {
    uint32_t a;
    asm("{ .reg .u64 t; cvta.to.shared.u64 t, %1; cvt.u32.u64 %0, t; }"
        : "=r"(a) : "l"(p));
    return a;
}
__device__ __forceinline__ void ldsm_x4(uint32_t* r, uint32_t a) {
    asm volatile("ldmatrix.sync.aligned.m8n8.x4.shared.b16 {%0,%1,%2,%3}, [%4];"
                 : "=r"(r[0]), "=r"(r[1]), "=r"(r[2]), "=r"(r[3]) : "r"(a));
}
__device__ __forceinline__ void mma16816(float* c, const uint32_t* a,
                                         uint32_t b0, uint32_t b1) {
    asm volatile(
        "mma.sync.aligned.m16n8k16.row.col.f32.f16.f16.f32 "
        "{%0,%1,%2,%3}, {%4,%5,%6,%7}, {%8,%9}, {%0,%1,%2,%3};"
        : "+f"(c[0]), "+f"(c[1]), "+f"(c[2]), "+f"(c[3])
        : "r"(a[0]), "r"(a[1]), "r"(a[2]), "r"(a[3]), "r"(b0), "r"(b1));
}
#define CP16(dst, src) \
    asm volatile("cp.async.cg.shared.global [%0], [%1], 16;" :: "r"(dst), "l"(src) : "memory")
#define CP_COMMIT  asm volatile("cp.async.commit_group;" ::: "memory")
#define CP_WAIT0   asm volatile("cp.async.wait_group 0;" ::: "memory")
#define CP_WAIT1   asm volatile("cp.async.wait_group 1;" ::: "memory")

__device__ __forceinline__ uint32_t packh2(float x, float y) {
    __half2 t = __floats2half2_rn(x, y);
    return *(uint32_t*)&t;
}

// ================= flash attention (unchanged from round 11) =================
#define QBLK   128
#define KVBLK  32
#define NKVT   (S_/KVBLK)      // 64
#define FO_K   65536           // 2 slots x 16384
#define FO_V   98304           // 2 slots x 16384
#define F_SMEM 131072

__global__ void __launch_bounds__(256)
flash_kernel(const h16* __restrict__ qkvh,
             const h16* __restrict__ vth_g,
             h16* __restrict__ oh_g)
{
    extern __shared__ __align__(128) char sm[];
    const uint32_t sb = smem_u32(sm);
    const int tid = threadIdx.x, wid = tid >> 5, lane = tid & 31;
    const int bh = blockIdx.y;
    const int b = bh >> 3, hd = bh & 7;
    const int q0 = blockIdx.x * QBLK;

    auto load_k = [&](int kv0, uint32_t slot) {
        #pragma unroll
        for (int it = 0; it < 4; it++) {
            int c = tid + it * 256;
            int row = c >> 5, kc = c & 31;
            const h16* src = qkvh
                + ((size_t)(b * S_ + kv0 + row) * QKVW_ + 2048 + hd * 256 + kc * 8);
            CP16(slot + row * 512 + (uint32_t)((kc ^ (row & 7)) << 4), src);
        }
    };
    auto load_v = [&](int kv0, uint32_t slot) {
        #pragma unroll
        for (int it = 0; it < 4; it++) {
            int c = tid + it * 256;
            int row = c >> 2, kc = c & 3;
            const h16* src = vth_g
                + ((size_t)bh * DH_ * S_ + (size_t)row * S_ + kv0 + kc * 8);
            CP16(slot + row * 64 + (uint32_t)((kc ^ ((row >> 1) & 3)) << 4), src);
        }
    };

    #pragma unroll
    for (int it = 0; it < 16; it++) {                 // Q: 4096 x 16B
        int c = tid + it * 256;
        int row = c >> 5, kc = c & 31;
        const h16* src = qkvh
            + ((size_t)(b * S_ + q0 + row) * QKVW_ + hd * 256 + kc * 8);
        CP16(sb + row * 512 + (uint32_t)((kc ^ (row & 7)) << 4), src);
    }
    load_k(0, sb + FO_K);
    load_v(0, sb + FO_V);
    CP_COMMIT;
    load_k(KVBLK, sb + FO_K + 16384);
    load_v(KVBLK, sb + FO_V + 16384);
    CP_COMMIT;

    const int wm    = wid * 16;
    const int a_row = wm + (lane & 15);
    const uint32_t a_rowoff = (uint32_t)(a_row * 512);
    const int a_r7  = a_row & 7;
    const int a_hb  = lane >> 4;
    const int b_row = (lane & 7) + ((lane >> 4) & 1) * 8;
    const int b_kb  = (lane >> 3) & 1;

    float o[32][4];
    #pragma unroll
    for (int i = 0; i < 32; i++) { o[i][0]=0.f; o[i][1]=0.f; o[i][2]=0.f; o[i][3]=0.f; }
    float m0 = -1e30f, m1 = -1e30f, l0 = 0.f, l1 = 0.f;

    for (int i = 0; i < NKVT; i++) {
        if (i + 1 < NKVT) { CP_WAIT1; } else { CP_WAIT0; }
        __syncthreads();
        const uint32_t kbs = sb + FO_K + (uint32_t)((i & 1) * 16384);
        const uint32_t vbs = sb + FO_V + (uint32_t)((i & 1) * 16384);

        float s[4][4];
        #pragma unroll
        for (int nt = 0; nt < 4; nt++) { s[nt][0]=0.f; s[nt][1]=0.f; s[nt][2]=0.f; s[nt][3]=0.f; }
        #pragma unroll
        for (int ks = 0; ks < 16; ks++) {
            const uint32_t aq = a_rowoff + (uint32_t)((((2 * ks + a_hb) ^ a_r7) << 4));
            uint32_t ah4[4];
            ldsm_x4(ah4, sb + aq);
            uint32_t kh4[2][4];
            #pragma unroll
            for (int g2 = 0; g2 < 2; g2++) {
                const int row = g2 * 16 + b_row;
                const uint32_t off = (uint32_t)(row * 512 + (((2 * ks + b_kb) ^ (row & 7)) << 4));
                ldsm_x4(kh4[g2], kbs + off);
            }
            #pragma unroll
            for (int nt = 0; nt < 4; nt++)
                mma16816(s[nt], ah4, kh4[nt >> 1][(nt & 1) * 2], kh4[nt >> 1][(nt & 1) * 2 + 1]);
        }

        float mx0 = -1e30f, mx1 = -1e30f;
        #pragma unroll
        for (int nt = 0; nt < 4; nt++) {
            s[nt][0] *= 0.0625f; s[nt][1] *= 0.0625f;
            s[nt][2] *= 0.0625f; s[nt][3] *= 0.0625f;
            mx0 = fmaxf(mx0, fmaxf(s[nt][0], s[nt][1]));
            mx1 = fmaxf(mx1, fmaxf(s[nt][2], s[nt][3]));
        }
        mx0 = fmaxf(mx0, __shfl_xor_sync(0xffffffffu, mx0, 1));
        mx0 = fmaxf(mx0, __shfl_xor_sync(0xffffffffu, mx0, 2));
        mx1 = fmaxf(mx1, __shfl_xor_sync(0xffffffffu, mx1, 1));
        mx1 = fmaxf(mx1, __shfl_xor_sync(0xffffffffu, mx1, 2));
        const float mn0 = fmaxf(m0, mx0), mn1 = fmaxf(m1, mx1);
        const float sc0 = __expf(m0 - mn0), sc1 = __expf(m1 - mn1);
        m0 = mn0; m1 = mn1;
        l0 *= sc0; l1 *= sc1;
        if (sc0 != 1.f || sc1 != 1.f) {
            #pragma unroll
            for (int nt = 0; nt < 32; nt++) {
                o[nt][0] *= sc0; o[nt][1] *= sc0;
                o[nt][2] *= sc1; o[nt][3] *= sc1;
            }
        }
        float rs0 = 0.f, rs1 = 0.f;
        #pragma unroll
        for (int nt = 0; nt < 4; nt++) {
            s[nt][0] = __expf(s[nt][0] - m0);
            s[nt][1] = __expf(s[nt][1] - m0);
            s[nt][2] = __expf(s[nt][2] - m1);
            s[nt][3] = __expf(s[nt][3] - m1);
            rs0 += s[nt][0] + s[nt][1];
            rs1 += s[nt][2] + s[nt][3];
        }
        rs0 += __shfl_xor_sync(0xffffffffu, rs0, 1);
        rs0 += __shfl_xor_sync(0xffffffffu, rs0, 2);
        rs1 += __shfl_xor_sync(0xffffffffu, rs1, 1);
        rs1 += __shfl_xor_sync(0xffffffffu, rs1, 2);
        l0 += rs0; l1 += rs1;

        uint32_t pah[2][4];
        #pragma unroll
        for (int ks = 0; ks < 2; ks++) {
            const int j0 = 2 * ks, j1 = 2 * ks + 1;
            pah[ks][0] = packh2(s[j0][0], s[j0][1]);
            pah[ks][1] = packh2(s[j0][2], s[j0][3]);
            pah[ks][2] = packh2(s[j1][0], s[j1][1]);
            pah[ks][3] = packh2(s[j1][2], s[j1][3]);
        }

        #pragma unroll
        for (int half = 0; half < 2; half++) {
            #pragma unroll
            for (int ks = 0; ks < 2; ks++) {
                #pragma unroll
                for (int j2 = 0; j2 < 8; j2++) {
                    const int row = half * 128 + j2 * 16 + b_row;
                    const uint32_t voff = (uint32_t)(row * 64 +
                        (((2 * ks + b_kb) ^ ((row >> 1) & 3)) << 4));
                    const int nt = half * 16 + j2 * 2;
                    uint32_t vh4[4];
                    ldsm_x4(vh4, vbs + voff);
                    mma16816(o[nt],     pah[ks], vh4[0], vh4[1]);
                    mma16816(o[nt + 1], pah[ks], vh4[2], vh4[3]);
                }
            }
        }
        __syncthreads();

        if (i + 2 < NKVT) {
            load_k((i + 2) * KVBLK, sb + FO_K + (uint32_t)((i & 1) * 16384));
            load_v((i + 2) * KVBLK, sb + FO_V + (uint32_t)((i & 1) * 16384));
            CP_COMMIT;
        }
    }

    const float inv0 = 1.f / l0, inv1 = 1.f / l1;
    const int g  = lane >> 2;
    const int t2 = (lane & 3) * 2;
    const size_t base0 = (size_t)(b * S_ + q0 + wm + g) * INNER_ + hd * 256 + t2;
    const size_t base1 = base0 + (size_t)8 * INNER_;
    #pragma unroll
    for (int nt = 0; nt < 32; nt++) {
        *(uint32_t*)&oh_g[base0 + (size_t)nt * 8] = packh2(o[nt][0] * inv0, o[nt][1] * inv0);
        *(uint32_t*)&oh_g[base1 + (size_t)nt * 8] = packh2(o[nt][2] * inv1, o[nt][3] * inv1);
    }
}

// ---------------- pure fp16 HMMA GEMM, cp.async 2-stage, 2 CTA/SM ----------------
// C = alpha * A @ B^T
#define KB_    32
#define ASTR   80
#define GTILE  (128 * ASTR)    // 10240 B per tile buffer

template<int OUT_HALF>
__global__ void __launch_bounds__(256, 2)
gemm_hmma1(const h16* __restrict__ Ah, int lda,
           const h16* __restrict__ Bh, int ldb,
           float* __restrict__ Cf, h16* __restrict__ Ch, int ldc,
           int K, int zdiv,
           long long sA1, long long sA2,
           long long sB1, long long sB2,
           long long sC1, long long sC2,
           const float* __restrict__ bias,
           float alpha, int relu)
{
    __shared__ __align__(16) char sA [2 * GTILE];
    __shared__ __align__(16) char sB [2 * GTILE];

    const int z  = blockIdx.z;
    const int zq = z / zdiv, zr = z % zdiv;
    Ah += (long long)zq * sA1 + (long long)zr * sA2;
    Bh += (long long)zq * sB1 + (long long)zr * sB2;
    const long long coff = (long long)zq * sC1 + (long long)zr * sC2;
    if (Cf) Cf += coff;
    if (Ch) Ch += coff;

    const int bm   = blockIdx.y * 128;
    const int bn   = blockIdx.x * 128;
    const int tid  = threadIdx.x;
    const int wid  = tid >> 5;
    const int lane = tid & 31;
    const int wm   = (wid & 1) * 64;
    const int wn   = (wid >> 1) * 32;

    const uint32_t uA = smem_u32(sA);
    const uint32_t uB = smem_u32(sB);

    const int lrow0 = tid >> 2;
    const int lrow1 = lrow0 + 64;
    const int lc0   = tid & 3;
    const uint32_t so0 = (uint32_t)(lrow0 * ASTR + lc0 * 16);
    const uint32_t so1 = (uint32_t)(lrow1 * ASTR + lc0 * 16);

    auto load_tile = [&](int kb, int buf) {
        const int kn = kb * KB_ + lc0 * 8;
        const uint32_t off = (uint32_t)(buf * GTILE);
        CP16(uA + off + so0, Ah + (long long)(bm + lrow0) * lda + kn);
        CP16(uA + off + so1, Ah + (long long)(bm + lrow1) * lda + kn);
        CP16(uB + off + so0, Bh + (long long)(bn + lrow0) * ldb + kn);
        CP16(uB + off + so1, Bh + (long long)(bn + lrow1) * ldb + kn);
    };

    const uint32_t aBase = (uint32_t)((wm + (lane & 15)) * ASTR + (lane >> 4) * 16);
    const uint32_t bBase = (uint32_t)((wn + (lane & 7) + ((lane >> 4) & 1) * 8) * ASTR
                                      + (lane & 8) * 2);

    float acc[4][4][4];
    #pragma unroll
    for (int mt = 0; mt < 4; mt++)
        #pragma unroll
        for (int nt = 0; nt < 4; nt++)
            #pragma unroll
            for (int i = 0; i < 4; i++) acc[mt][nt][i] = 0.f;

    const int nkb = K / KB_;
    load_tile(0, 0); CP_COMMIT;
    load_tile(1, 1); CP_COMMIT;

    for (int kb = 0; kb < nkb; kb++) {
        if (kb + 1 < nkb) { CP_WAIT1; } else { CP_WAIT0; }
        __syncthreads();
        const uint32_t boff = (uint32_t)((kb & 1) * GTILE);

        #pragma unroll
        for (int ks = 0; ks < 2; ks++) {
            const uint32_t ksb = ks * 32;
            uint32_t ah[4][4];
            #pragma unroll
            for (int mt = 0; mt < 4; mt++)
                ldsm_x4(ah[mt], uA + boff + aBase + mt * (16 * ASTR) + ksb);
            uint32_t bh[2][4];
            #pragma unroll
            for (int g = 0; g < 2; g++)
                ldsm_x4(bh[g], uB + boff + bBase + g * (16 * ASTR) + ksb);
            #pragma unroll
            for (int mt = 0; mt < 4; mt++)
                #pragma unroll
                for (int nt = 0; nt < 4; nt++)
                    mma16816(acc[mt][nt], ah[mt],
                             bh[nt >> 1][(nt & 1) * 2], bh[nt >> 1][(nt & 1) * 2 + 1]);
        }
        __syncthreads();

        if (kb + 2 < nkb) { load_tile(kb + 2, kb & 1); CP_COMMIT; }
    }

    const int er = lane >> 2;
    const int ec = (lane & 3) * 2;
    #pragma unroll
    for (int mt = 0; mt < 4; mt++) {
        #pragma unroll
        for (int half = 0; half < 2; half++) {
            const int m = bm + wm + mt * 16 + er + half * 8;
            #pragma unroll
            for (int nt = 0; nt < 4; nt++) {
                const int n = bn + wn + nt * 8 + ec;
                float v0 = acc[mt][nt][half * 2 + 0] * alpha;
                float v1 = acc[mt][nt][half * 2 + 1] * alpha;
                if (bias) { v0 += __ldg(&bias[n]); v1 += __ldg(&bias[n + 1]); }
                if (relu) { v0 = fmaxf(v0, 0.f); v1 = fmaxf(v1, 0.f); }
                if (OUT_HALF) {
                    *(uint32_t*)&Ch[(long long)m * ldc + n] = packh2(v0, v1);
                } else {
                    *(float2*)&Cf[(long long)m * ldc + n] = make_float2(v0, v1);
                }
            }
        }
    }
}

// ---------------- reductions / fused split-K reduce + layernorm ----------------
__device__ __forceinline__ float warp_sum(float v) {
    #pragma unroll
    for (int o = 16; o > 0; o >>= 1) v += __shfl_xor_sync(0xffffffffu, v, o);
    return v;
}
__device__ __forceinline__ float block_reduce_sum(float v) {
    __shared__ float sm2[32];
    __shared__ float res;
    int lane = threadIdx.x & 31;
    int wid  = threadIdx.x >> 5;
    v = warp_sum(v);
    __syncthreads();
    if (lane == 0) sm2[wid] = v;
    __syncthreads();
    if (wid == 0) {
        int nw = blockDim.x >> 5;
        float x = (lane < nw) ? sm2[lane] : 0.f;
        x = warp_sum(x);
        if (lane == 0) res = x;
    }
    __syncthreads();
    return res;
}

__global__ void ln_red_kernel(const float* __restrict__ part, long long pstride,
                              const float* __restrict__ bias,
                              const float* __restrict__ resid,
                              const float* __restrict__ g,
                              const float* __restrict__ b,
                              float* __restrict__ outf,
                              h16* __restrict__ oh)
{
    const int t = threadIdx.x;
    const long long base = (long long)blockIdx.x * E_ + t;
    float v = part[base] + part[base + pstride]
            + part[base + 2 * pstride] + part[base + 3 * pstride];
    if (bias) v += bias[t];
    v += resid[base];
    float mean = block_reduce_sum(v) * (1.f / E_);
    float d = v - mean;
    float var = block_reduce_sum(d * d) * (1.f / E_);
    float r = d * rsqrtf(var + EPS_) * g[t] + b[t];
    if (outf) outf[base] = r;
    if (oh) oh[base] = __float2half_rn(r);
}

// ---------------- prep kernels ----------------
__global__ void split_kernel(const float* __restrict__ in,
                             h16* __restrict__ oh, int n)
{
    int i = blockIdx.x * blockDim.x + threadIdx.x;
    if (i < n) oh[i] = __float2half_rn(in[i]);
}

__device__ __forceinline__ void wconv_tile(const float* W, int R, int C,
                                           h16* oh, int c0, int r0, int tx, int ty)
{
    __shared__ float t[32][33];
    #pragma unroll
    for (int j = 0; j < 4; j++) {
        int r = ty + 8 * j;
        t[r][tx] = W[(long long)(r0 + r) * C + c0 + tx];
    }
    __syncthreads();
    #pragma unroll
    for (int j = 0; j < 4; j++) {
        int r = ty + 8 * j;
        oh[(long long)(c0 + r) * R + r0 + tx] = __float2half_rn(t[tx][r]);
    }
}

__global__ void wconv_qkv(const float* __restrict__ Wq, const float* __restrict__ Wk,
                          const float* __restrict__ Wv, h16* __restrict__ oh)
{
    const float* W = (blockIdx.z == 0) ? Wq : (blockIdx.z == 1) ? Wk : Wv;
    h16* ph = oh + (size_t)blockIdx.z * INNER_ * E_;
    wconv_tile(W, E_, INNER_, ph, blockIdx.x * 32, blockIdx.y * 32,
               threadIdx.x, threadIdx.y);
}

__global__ void wconv_misc(const float* __restrict__ Wo, const float* __restrict__ W1,
                           const float* __restrict__ W2,
                           h16* __restrict__ woT, h16* __restrict__ w1T,
                           h16* __restrict__ w2T)
{
    const float* W; h16* ph; int R, C;
    if (blockIdx.z == 0)      { W = Wo; ph = woT; R = INNER_; C = E_; }
    else if (blockIdx.z == 1) { W = W1; ph = w1T; R = E_; C = DFF_; }
    else                      { W = W2; ph = w2T; R = DFF_; C = E_; }
    if ((int)blockIdx.x * 32 >= C || (int)blockIdx.y * 32 >= R) return;
    wconv_tile(W, R, C, ph, blockIdx.x * 32, blockIdx.y * 32,
               threadIdx.x, threadIdx.y);
}

__global__ void vtrans_kernel(const h16* __restrict__ qkvh,
                              h16* __restrict__ vth)
{
    __shared__ h16 th[32][33];
    const int z = blockIdx.z;
    const int b = z / H_, h = z % H_;
    const int s0 = blockIdx.x * 32;
    const int d0 = blockIdx.y * 32;
    const int tx = threadIdx.x, ty = threadIdx.y;
    const long long ibase = (long long)b * S_ * QKVW_ + 4096 + (long long)h * DH_;
    const long long obase = (long long)z * DH_ * S_;
    #pragma unroll
    for (int j = 0; j < 4; j++) {
        int r = ty + 8 * j;
        th[r][tx] = qkvh[ibase + (long long)(s0 + r) * QKVW_ + d0 + tx];
    }
    __syncthreads();
    #pragma unroll
    for (int j = 0; j < 4; j++) {
        int r = ty + 8 * j;
        vth[obase + (long long)(d0 + r) * S_ + s0 + tx] = th[tx][r];
    }
}

// ---------------- launch ----------------
extern "C" void kernel_launch(void* const* d_in, const int* in_sizes, int n_in,
                              void* d_out, int out_size)
{
    const float* x    = (const float*)d_in[0];
    const float* Wq   = (const float*)d_in[1];
    const float* Wk   = (const float*)d_in[2];
    const float* Wv   = (const float*)d_in[3];
    const float* Wo   = (const float*)d_in[4];
    const float* W1   = (const float*)d_in[5];
    const float* b1   = (const float*)d_in[6];
    const float* W2   = (const float*)d_in[7];
    const float* b2   = (const float*)d_in[8];
    const float* ln1g = (const float*)d_in[9];
    const float* ln1b = (const float*)d_in[10];
    const float* ln2g = (const float*)d_in[11];
    const float* ln2b = (const float*)d_in[12];

    #define SYM(p, s) p; cudaGetSymbolAddress((void**)&p, s)
    h16 *SYM(xh, g_xh);
    h16 *SYM(wqkv, g_wqkvT);
    h16 *SYM(woT, g_woT);
    h16 *SYM(w1T, g_w1T);
    h16 *SYM(w2T, g_w2T);
    h16 *SYM(qkvh, g_qkvh);
    h16 *SYM(vth, g_vth);
    h16 *SYM(oh, g_oh);
    float *SYM(part, g_part);
    float *SYM(hf, g_hf);
    h16 *SYM(hh, g_hh);
    h16 *SYM(ffh, g_ffh);

    cudaFuncSetAttribute(flash_kernel, cudaFuncAttributeMaxDynamicSharedMemorySize, F_SMEM);

    const dim3 blk(256);
    const dim3 tblk(32, 8);
    const long long psz = (long long)BSZ * E_;

    // 1) x -> fp16
    split_kernel<<<(BSZ * E_ + 255) / 256, 256>>>(x, xh, BSZ * E_);
    // 2) QKV weights packed convert-transpose
    { dim3 g(INNER_/32, E_/32, 3); wconv_qkv<<<g, tblk>>>(Wq, Wk, Wv, wqkv); }
    // 3) Wo/W1/W2
    { dim3 g(64, 64, 3); wconv_misc<<<g, tblk>>>(Wo, W1, W2, woT, w1T, w2T); }
    // 4) fused QKV projection: [4096,256] @ [256,6144]
    {
        dim3 grd(QKVW_/128, BSZ/128, 1);
        gemm_hmma1<1><<<grd, blk>>>(xh, E_, wqkv, E_,
            nullptr, qkvh, QKVW_, E_, 1, 0,0, 0,0, 0,0,
            nullptr, 1.f, 0);
    }
    // 5) V^T per (b,h)
    { dim3 g(S_/32, DH_/32, B_*H_); vtrans_kernel<<<g, tblk>>>(qkvh, vth); }
    // 6) flash attention
    {
        dim3 grd(S_/QBLK, B_*H_);
        flash_kernel<<<grd, blk, F_SMEM>>>(qkvh, vth, oh);
    }
    // 7) Wo split-K x4 -> partials ; LN1 reduce (+x resid)
    {
        dim3 grd(E_/128, BSZ/128, 4);
        gemm_hmma1<0><<<grd, blk>>>(oh, INNER_, woT, INNER_,
            part, nullptr, E_, INNER_/4, 4,
            0, 512, 0, 512, 0, psz,
            nullptr, 1.f, 0);
        ln_red_kernel<<<BSZ, 256>>>(part, psz, nullptr, x, ln1g, ln1b, hf, hh);
    }
    // 8) ff = relu(h @ W1 + b1)
    {
        dim3 grd(DFF_/128, BSZ/128, 1);
        gemm_hmma1<1><<<grd, blk>>>(hh, E_, w1T, E_,
            nullptr, ffh, DFF_, E_, 1, 0,0, 0,0, 0,0,
            b1, 1.f, 1);
    }
    // 9) FFN2 split-K x4 -> partials ; LN2 reduce (+b2 +h resid) -> out
    {
        dim3 grd(E_/128, BSZ/128, 4);
        gemm_hmma1<0><<<grd, blk>>>(ffh, DFF_, w2T, DFF_,
            part, nullptr, E_, DFF_/4, 4,
            0, 256, 0, 256, 0, psz,
            nullptr, 1.f, 0);
        ln_red_kernel<<<BSZ, 256>>>(part, psz, b2, hf, ln2g, ln2b,
                                    (float*)d_out, nullptr);
    }
}

// round 13
// speedup vs baseline: 2.9327x; 1.1838x over previous
#include <cuda_runtime.h>
#include <cuda_fp16.h>
#include <cstdint>

#define B_     2
#define S_     2048
#define E_     256
#define H_     8
#define DH_    256
#define INNER_ 2048
#define QKVW_  (3*INNER_)   // 6144
#define DFF_   1024
#define BSZ    (B_*S_)
#define EPS_   1e-6f

typedef __half h16;

// ---------------- device scratch ----------------
__device__ h16   g_xh [(size_t)BSZ * E_];
__device__ h16   g_wqkvT[(size_t)QKVW_ * E_];
__device__ h16   g_woT [(size_t)E_ * INNER_];
__device__ h16   g_w1T [(size_t)DFF_ * E_];
__device__ h16   g_w2T [(size_t)E_ * DFF_];
__device__ h16   g_qkvh[(size_t)BSZ * QKVW_];     // q|k|v packed, ld=6144
__device__ h16   g_vth[(size_t)BSZ * INNER_];     // V^T per (b,h): [B*H][DH][S]
__device__ h16   g_oh [(size_t)BSZ * INNER_];
__device__ float g_part[(size_t)4 * BSZ * E_];    // split-K partials
__device__ float g_hf [(size_t)BSZ * E_];
__device__ h16   g_hh [(size_t)BSZ * E_];
__device__ h16   g_ffh[(size_t)BSZ * DFF_];

// ---------------- helpers ----------------
__device__ __forceinline__ uint32_t smem_u32(const void* p) {
    uint32_t a;
    asm("{ .reg .u64 t; cvta.to.shared.u64 t, %1; cvt.u32.u64 %0, t; }"
        : "=r"(a) : "l"(p));
    return a;
}
__device__ __forceinline__ void ldsm_x4(uint32_t* r, uint32_t a) {
    asm volatile("ldmatrix.sync.aligned.m8n8.x4.shared.b16 {%0,%1,%2,%3}, [%4];"
                 : "=r"(r[0]), "=r"(r[1]), "=r"(r[2]), "=r"(r[3]) : "r"(a));
}
__device__ __forceinline__ void mma16816(float* c, const uint32_t* a,
                                         uint32_t b0, uint32_t b1) {
    asm volatile(
        "mma.sync.aligned.m16n8k16.row.col.f32.f16.f16.f32 "
        "{%0,%1,%2,%3}, {%4,%5,%6,%7}, {%8,%9}, {%0,%1,%2,%3};"
        : "+f"(c[0]), "+f"(c[1]), "+f"(c[2]), "+f"(c[3])
        : "r"(a[0]), "r"(a[1]), "r"(a[2]), "r"(a[3]), "r"(b0), "r"(b1));
}
#define CP16(dst, src) \
    asm volatile("cp.async.cg.shared.global [%0], [%1], 16;" :: "r"(dst), "l"(src) : "memory")
#define CP_COMMIT  asm volatile("cp.async.commit_group;" ::: "memory")
#define CP_WAIT0   asm volatile("cp.async.wait_group 0;" ::: "memory")
#define CP_WAIT1   asm volatile("cp.async.wait_group 1;" ::: "memory")

__device__ __forceinline__ uint32_t packh2(float x, float y) {
    __half2 t = __floats2half2_rn(x, y);
    return *(uint32_t*)&t;
}

// ================= flash attention, KVBLK=64 =================
// grid (S_/128, B_*H_), 256 thr (8 warps x m16). Q resident (64KB),
// K + V double-buffered at 32KB slots, one cp.async group per iter.
#define QBLK   128
#define KVBLK  64
#define NKVT   (S_/KVBLK)      // 32
#define FO_K   65536           // 2 slots x 32768
#define FO_V   131072          // 2 slots x 32768
#define F_SMEM 196608

__global__ void __launch_bounds__(256)
flash_kernel(const h16* __restrict__ qkvh,
             const h16* __restrict__ vth_g,
             h16* __restrict__ oh_g)
{
    extern __shared__ __align__(128) char sm[];
    const uint32_t sb = smem_u32(sm);
    const int tid = threadIdx.x, wid = tid >> 5, lane = tid & 31;
    const int bh = blockIdx.y;
    const int b = bh >> 3, hd = bh & 7;
    const int q0 = blockIdx.x * QBLK;

    auto load_k = [&](int kv0, uint32_t slot) {      // 64 rows x 512B
        #pragma unroll
        for (int it = 0; it < 8; it++) {
            int c = tid + it * 256;
            int row = c >> 5, kc = c & 31;
            const h16* src = qkvh
                + ((size_t)(b * S_ + kv0 + row) * QKVW_ + 2048 + hd * 256 + kc * 8);
            CP16(slot + row * 512 + (uint32_t)((kc ^ (row & 7)) << 4), src);
        }
    };
    auto load_v = [&](int kv0, uint32_t slot) {      // 256 rows x 128B
        #pragma unroll
        for (int it = 0; it < 8; it++) {
            int c = tid + it * 256;
            int row = c >> 3, kc = c & 7;
            const h16* src = vth_g
                + ((size_t)bh * DH_ * S_ + (size_t)row * S_ + kv0 + kc * 8);
            CP16(slot + row * 128 + (uint32_t)((kc ^ (row & 7)) << 4), src);
        }
    };

    #pragma unroll
    for (int it = 0; it < 16; it++) {                 // Q: 128 rows x 512B
        int c = tid + it * 256;
        int row = c >> 5, kc = c & 31;
        const h16* src = qkvh
            + ((size_t)(b * S_ + q0 + row) * QKVW_ + hd * 256 + kc * 8);
        CP16(sb + row * 512 + (uint32_t)((kc ^ (row & 7)) << 4), src);
    }
    load_k(0, sb + FO_K);
    load_v(0, sb + FO_V);
    CP_COMMIT;
    load_k(KVBLK, sb + FO_K + 32768);
    load_v(KVBLK, sb + FO_V + 32768);
    CP_COMMIT;

    const int wm    = wid * 16;
    const int a_row = wm + (lane & 15);
    const uint32_t a_rowoff = (uint32_t)(a_row * 512);
    const int a_r7  = a_row & 7;
    const int a_hb  = lane >> 4;
    const int b_row = (lane & 7) + ((lane >> 4) & 1) * 8;
    const int b_kb  = (lane >> 3) & 1;

    float o[32][4];
    #pragma unroll
    for (int i = 0; i < 32; i++) { o[i][0]=0.f; o[i][1]=0.f; o[i][2]=0.f; o[i][3]=0.f; }
    float m0 = -1e30f, m1 = -1e30f, l0 = 0.f, l1 = 0.f;

    for (int i = 0; i < NKVT; i++) {
        if (i + 1 < NKVT) { CP_WAIT1; } else { CP_WAIT0; }   // K(i),V(i) ready
        __syncthreads();
        const uint32_t kbs = sb + FO_K + (uint32_t)((i & 1) * 32768);
        const uint32_t vbs = sb + FO_V + (uint32_t)((i & 1) * 32768);

        // ==== S[16 x 64] = Qh Kh^T ====
        float s[8][4];
        #pragma unroll
        for (int nt = 0; nt < 8; nt++) { s[nt][0]=0.f; s[nt][1]=0.f; s[nt][2]=0.f; s[nt][3]=0.f; }
        #pragma unroll
        for (int ks = 0; ks < 16; ks++) {
            const uint32_t aq = a_rowoff + (uint32_t)((((2 * ks + a_hb) ^ a_r7) << 4));
            uint32_t ah4[4];
            ldsm_x4(ah4, sb + aq);
            uint32_t kh4[4][4];
            #pragma unroll
            for (int g2 = 0; g2 < 4; g2++) {
                const int row = g2 * 16 + b_row;
                const uint32_t off = (uint32_t)(row * 512 + (((2 * ks + b_kb) ^ (row & 7)) << 4));
                ldsm_x4(kh4[g2], kbs + off);
            }
            #pragma unroll
            for (int nt = 0; nt < 8; nt++)
                mma16816(s[nt], ah4, kh4[nt >> 1][(nt & 1) * 2], kh4[nt >> 1][(nt & 1) * 2 + 1]);
        }

        // ==== online softmax (rows g=lane>>2, g+8) ====
        float mx0 = -1e30f, mx1 = -1e30f;
        #pragma unroll
        for (int nt = 0; nt < 8; nt++) {
            s[nt][0] *= 0.0625f; s[nt][1] *= 0.0625f;
            s[nt][2] *= 0.0625f; s[nt][3] *= 0.0625f;
            mx0 = fmaxf(mx0, fmaxf(s[nt][0], s[nt][1]));
            mx1 = fmaxf(mx1, fmaxf(s[nt][2], s[nt][3]));
        }
        mx0 = fmaxf(mx0, __shfl_xor_sync(0xffffffffu, mx0, 1));
        mx0 = fmaxf(mx0, __shfl_xor_sync(0xffffffffu, mx0, 2));
        mx1 = fmaxf(mx1, __shfl_xor_sync(0xffffffffu, mx1, 1));
        mx1 = fmaxf(mx1, __shfl_xor_sync(0xffffffffu, mx1, 2));
        const float mn0 = fmaxf(m0, mx0), mn1 = fmaxf(m1, mx1);
        const float sc0 = __expf(m0 - mn0), sc1 = __expf(m1 - mn1);
        m0 = mn0; m1 = mn1;
        l0 *= sc0; l1 *= sc1;
        if (sc0 != 1.f || sc1 != 1.f) {
            #pragma unroll
            for (int nt = 0; nt < 32; nt++) {
                o[nt][0] *= sc0; o[nt][1] *= sc0;
                o[nt][2] *= sc1; o[nt][3] *= sc1;
            }
        }
        float rs0 = 0.f, rs1 = 0.f;
        #pragma unroll
        for (int nt = 0; nt < 8; nt++) {
            s[nt][0] = __expf(s[nt][0] - m0);
            s[nt][1] = __expf(s[nt][1] - m0);
            s[nt][2] = __expf(s[nt][2] - m1);
            s[nt][3] = __expf(s[nt][3] - m1);
            rs0 += s[nt][0] + s[nt][1];
            rs1 += s[nt][2] + s[nt][3];
        }
        rs0 += __shfl_xor_sync(0xffffffffu, rs0, 1);
        rs0 += __shfl_xor_sync(0xffffffffu, rs0, 2);
        rs1 += __shfl_xor_sync(0xffffffffu, rs1, 1);
        rs1 += __shfl_xor_sync(0xffffffffu, rs1, 2);
        l0 += rs0; l1 += rs1;

        // P -> fp16 A-fragments (k64 = 4 k16 steps)
        uint32_t pah[4][4];
        #pragma unroll
        for (int ks = 0; ks < 4; ks++) {
            const int j0 = 2 * ks, j1 = 2 * ks + 1;
            pah[ks][0] = packh2(s[j0][0], s[j0][1]);
            pah[ks][1] = packh2(s[j0][2], s[j0][3]);
            pah[ks][2] = packh2(s[j1][0], s[j1][1]);
            pah[ks][3] = packh2(s[j1][2], s[j1][3]);
        }

        // ==== O += P @ Vh over dh=256 ====
        #pragma unroll
        for (int j2 = 0; j2 < 16; j2++) {
            const int row = j2 * 16 + b_row;
            const uint32_t vrow = (uint32_t)(row * 128);
            const int r7 = row & 7;
            #pragma unroll
            for (int ks = 0; ks < 4; ks++) {
                uint32_t vh4[4];
                ldsm_x4(vh4, vbs + vrow + (uint32_t)((((2 * ks + b_kb) ^ r7) << 4)));
                mma16816(o[j2 * 2],     pah[ks], vh4[0], vh4[1]);
                mma16816(o[j2 * 2 + 1], pah[ks], vh4[2], vh4[3]);
            }
        }
        __syncthreads();

        if (i + 2 < NKVT) {
            load_k((i + 2) * KVBLK, sb + FO_K + (uint32_t)((i & 1) * 32768));
            load_v((i + 2) * KVBLK, sb + FO_V + (uint32_t)((i & 1) * 32768));
            CP_COMMIT;
        }
    }

    const float inv0 = 1.f / l0, inv1 = 1.f / l1;
    const int g  = lane >> 2;
    const int t2 = (lane & 3) * 2;
    const size_t base0 = (size_t)(b * S_ + q0 + wm + g) * INNER_ + hd * 256 + t2;
    const size_t base1 = base0 + (size_t)8 * INNER_;
    #pragma unroll
    for (int nt = 0; nt < 32; nt++) {
        *(uint32_t*)&oh_g[base0 + (size_t)nt * 8] = packh2(o[nt][0] * inv0, o[nt][1] * inv0);
        *(uint32_t*)&oh_g[base1 + (size_t)nt * 8] = packh2(o[nt][2] * inv1, o[nt][3] * inv1);
    }
}

// ---------------- pure fp16 HMMA GEMM, KB=64, cp.async 2-stage, 2 CTA/SM ------
// C = alpha * A @ B^T
#define KB_    64
#define ASTR   144
#define GTILE  (128 * ASTR)       // 18432 B
#define G_SMEM (4 * GTILE)        // 73728 B (A:2 + B:2)

template<int OUT_HALF>
__global__ void __launch_bounds__(256, 2)
gemm_hmma1(const h16* __restrict__ Ah, int lda,
           const h16* __restrict__ Bh, int ldb,
           float* __restrict__ Cf, h16* __restrict__ Ch, int ldc,
           int K, int zdiv,
           long long sA1, long long sA2,
           long long sB1, long long sB2,
           long long sC1, long long sC2,
           const float* __restrict__ bias,
           float alpha, int relu)
{
    extern __shared__ __align__(16) char gsm[];
    const uint32_t uA = smem_u32(gsm);
    const uint32_t uB = uA + 2 * GTILE;

    const int z  = blockIdx.z;
    const int zq = z / zdiv, zr = z % zdiv;
    Ah += (long long)zq * sA1 + (long long)zr * sA2;
    Bh += (long long)zq * sB1 + (long long)zr * sB2;
    const long long coff = (long long)zq * sC1 + (long long)zr * sC2;
    if (Cf) Cf += coff;
    if (Ch) Ch += coff;

    const int bm   = blockIdx.y * 128;
    const int bn   = blockIdx.x * 128;
    const int tid  = threadIdx.x;
    const int wid  = tid >> 5;
    const int lane = tid & 31;
    const int wm   = (wid & 1) * 64;
    const int wn   = (wid >> 1) * 32;

    auto load_tile = [&](int kb, int buf) {
        const uint32_t off = (uint32_t)(buf * GTILE);
        #pragma unroll
        for (int it = 0; it < 4; it++) {
            int c = tid + it * 256;
            int row = c >> 3, kc = c & 7;
            const uint32_t so = (uint32_t)(row * ASTR + kc * 16);
            const int kn = kb * KB_ + kc * 8;
            CP16(uA + off + so, Ah + (long long)(bm + row) * lda + kn);
            CP16(uB + off + so, Bh + (long long)(bn + row) * ldb + kn);
        }
    };

    const uint32_t aBase = (uint32_t)((wm + (lane & 15)) * ASTR + (lane >> 4) * 16);
    const uint32_t bBase = (uint32_t)((wn + (lane & 7) + ((lane >> 4) & 1) * 8) * ASTR
                                      + (lane & 8) * 2);

    float acc[4][4][4];
    #pragma unroll
    for (int mt = 0; mt < 4; mt++)
        #pragma unroll
        for (int nt = 0; nt < 4; nt++)
            #pragma unroll
            for (int i = 0; i < 4; i++) acc[mt][nt][i] = 0.f;

    const int nkb = K / KB_;
    load_tile(0, 0); CP_COMMIT;
    load_tile(1, 1); CP_COMMIT;

    for (int kb = 0; kb < nkb; kb++) {
        if (kb + 1 < nkb) { CP_WAIT1; } else { CP_WAIT0; }
        __syncthreads();
        const uint32_t boff = (uint32_t)((kb & 1) * GTILE);

        #pragma unroll
        for (int ks = 0; ks < 4; ks++) {
            const uint32_t ksb = ks * 32;
            uint32_t ah[4][4];
            #pragma unroll
            for (int mt = 0; mt < 4; mt++)
                ldsm_x4(ah[mt], uA + boff + aBase + mt * (16 * ASTR) + ksb);
            uint32_t bh[2][4];
            #pragma unroll
            for (int g = 0; g < 2; g++)
                ldsm_x4(bh[g], uB + boff + bBase + g * (16 * ASTR) + ksb);
            #pragma unroll
            for (int mt = 0; mt < 4; mt++)
                #pragma unroll
                for (int nt = 0; nt < 4; nt++)
                    mma16816(acc[mt][nt], ah[mt],
                             bh[nt >> 1][(nt & 1) * 2], bh[nt >> 1][(nt & 1) * 2 + 1]);
        }
        __syncthreads();

        if (kb + 2 < nkb) { load_tile(kb + 2, kb & 1); CP_COMMIT; }
    }

    const int er = lane >> 2;
    const int ec = (lane & 3) * 2;
    #pragma unroll
    for (int mt = 0; mt < 4; mt++) {
        #pragma unroll
        for (int half = 0; half < 2; half++) {
            const int m = bm + wm + mt * 16 + er + half * 8;
            #pragma unroll
            for (int nt = 0; nt < 4; nt++) {
                const int n = bn + wn + nt * 8 + ec;
                float v0 = acc[mt][nt][half * 2 + 0] * alpha;
                float v1 = acc[mt][nt][half * 2 + 1] * alpha;
                if (bias) { v0 += __ldg(&bias[n]); v1 += __ldg(&bias[n + 1]); }
                if (relu) { v0 = fmaxf(v0, 0.f); v1 = fmaxf(v1, 0.f); }
                if (OUT_HALF) {
                    *(uint32_t*)&Ch[(long long)m * ldc + n] = packh2(v0, v1);
                } else {
                    *(float2*)&Cf[(long long)m * ldc + n] = make_float2(v0, v1);
                }
            }
        }
    }
}

// ---------------- warp-per-row split-K reduce + layernorm ----------------
__device__ __forceinline__ float warp_sum(float v) {
    #pragma unroll
    for (int o = 16; o > 0; o >>= 1) v += __shfl_xor_sync(0xffffffffu, v, o);
    return v;
}

__global__ void ln_red_kernel(const float* __restrict__ part, long long pstride,
                              const float* __restrict__ bias,
                              const float* __restrict__ resid,
                              const float* __restrict__ g,
                              const float* __restrict__ b,
                              float* __restrict__ outf,
                              h16* __restrict__ oh)
{
    const int lane = threadIdx.x & 31;
    const int warp = threadIdx.x >> 5;
    const long long row  = (long long)blockIdx.x * 8 + warp;
    const long long base = row * E_;

    float v[8];
    float sum = 0.f;
    #pragma unroll
    for (int j = 0; j < 8; j++) {
        const long long idx = base + lane + j * 32;
        float t = part[idx] + part[idx + pstride]
                + part[idx + 2 * pstride] + part[idx + 3 * pstride];
        if (bias) t += bias[lane + j * 32];
        t += resid[idx];
        v[j] = t;
        sum += t;
    }
    const float mean = warp_sum(sum) * (1.f / E_);
    float vs = 0.f;
    #pragma unroll
    for (int j = 0; j < 8; j++) {
        v[j] -= mean;
        vs += v[j] * v[j];
    }
    const float inv = rsqrtf(warp_sum(vs) * (1.f / E_) + EPS_);
    #pragma unroll
    for (int j = 0; j < 8; j++) {
        const int col = lane + j * 32;
        const float r = v[j] * inv * g[col] + b[col];
        if (outf) outf[base + col] = r;
        if (oh) oh[base + col] = __float2half_rn(r);
    }
}

// ---------------- prep kernels ----------------
__global__ void split_kernel(const float* __restrict__ in,
                             h16* __restrict__ oh, int n)
{
    int i = blockIdx.x * blockDim.x + threadIdx.x;
    if (i < n) oh[i] = __float2half_rn(in[i]);
}

__device__ __forceinline__ void wconv_tile(const float* W, int R, int C,
                                           h16* oh, int c0, int r0, int tx, int ty)
{
    __shared__ float t[32][33];
    #pragma unroll
    for (int j = 0; j < 4; j++) {
        int r = ty + 8 * j;
        t[r][tx] = W[(long long)(r0 + r) * C + c0 + tx];
    }
    __syncthreads();
    #pragma unroll
    for (int j = 0; j < 4; j++) {
        int r = ty + 8 * j;
        oh[(long long)(c0 + r) * R + r0 + tx] = __float2half_rn(t[tx][r]);
    }
}

__global__ void wconv_qkv(const float* __restrict__ Wq, const float* __restrict__ Wk,
                          const float* __restrict__ Wv, h16* __restrict__ oh)
{
    const float* W = (blockIdx.z == 0) ? Wq : (blockIdx.z == 1) ? Wk : Wv;
    h16* ph = oh + (size_t)blockIdx.z * INNER_ * E_;
    wconv_tile(W, E_, INNER_, ph, blockIdx.x * 32, blockIdx.y * 32,
               threadIdx.x, threadIdx.y);
}

__global__ void wconv_misc(const float* __restrict__ Wo, const float* __restrict__ W1,
                           const float* __restrict__ W2,
                           h16* __restrict__ woT, h16* __restrict__ w1T,
                           h16* __restrict__ w2T)
{
    const float* W; h16* ph; int R, C;
    if (blockIdx.z == 0)      { W = Wo; ph = woT; R = INNER_; C = E_; }
    else if (blockIdx.z == 1) { W = W1; ph = w1T; R = E_; C = DFF_; }
    else                      { W = W2; ph = w2T; R = DFF_; C = E_; }
    if ((int)blockIdx.x * 32 >= C || (int)blockIdx.y * 32 >= R) return;
    wconv_tile(W, R, C, ph, blockIdx.x * 32, blockIdx.y * 32,
               threadIdx.x, threadIdx.y);
}

__global__ void vtrans_kernel(const h16* __restrict__ qkvh,
                              h16* __restrict__ vth)
{
    __shared__ h16 th[32][33];
    const int z = blockIdx.z;
    const int b = z / H_, h = z % H_;
    const int s0 = blockIdx.x * 32;
    const int d0 = blockIdx.y * 32;
    const int tx = threadIdx.x, ty = threadIdx.y;
    const long long ibase = (long long)b * S_ * QKVW_ + 4096 + (long long)h * DH_;
    const long long obase = (long long)z * DH_ * S_;
    #pragma unroll
    for (int j = 0; j < 4; j++) {
        int r = ty + 8 * j;
        th[r][tx] = qkvh[ibase + (long long)(s0 + r) * QKVW_ + d0 + tx];
    }
    __syncthreads();
    #pragma unroll
    for (int j = 0; j < 4; j++) {
        int r = ty + 8 * j;
        vth[obase + (long long)(d0 + r) * S_ + s0 + tx] = th[tx][r];
    }
}

// ---------------- launch ----------------
extern "C" void kernel_launch(void* const* d_in, const int* in_sizes, int n_in,
                              void* d_out, int out_size)
{
    const float* x    = (const float*)d_in[0];
    const float* Wq   = (const float*)d_in[1];
    const float* Wk   = (const float*)d_in[2];
    const float* Wv   = (const float*)d_in[3];
    const float* Wo   = (const float*)d_in[4];
    const float* W1   = (const float*)d_in[5];
    const float* b1   = (const float*)d_in[6];
    const float* W2   = (const float*)d_in[7];
    const float* b2   = (const float*)d_in[8];
    const float* ln1g = (const float*)d_in[9];
    const float* ln1b = (const float*)d_in[10];
    const float* ln2g = (const float*)d_in[11];
    const float* ln2b = (const float*)d_in[12];

    #define SYM(p, s) p; cudaGetSymbolAddress((void**)&p, s)
    h16 *SYM(xh, g_xh);
    h16 *SYM(wqkv, g_wqkvT);
    h16 *SYM(woT, g_woT);
    h16 *SYM(w1T, g_w1T);
    h16 *SYM(w2T, g_w2T);
    h16 *SYM(qkvh, g_qkvh);
    h16 *SYM(vth, g_vth);
    h16 *SYM(oh, g_oh);
    float *SYM(part, g_part);
    float *SYM(hf, g_hf);
    h16 *SYM(hh, g_hh);
    h16 *SYM(ffh, g_ffh);

    cudaFuncSetAttribute(flash_kernel, cudaFuncAttributeMaxDynamicSharedMemorySize, F_SMEM);
    cudaFuncSetAttribute(gemm_hmma1<0>, cudaFuncAttributeMaxDynamicSharedMemorySize, G_SMEM);
    cudaFuncSetAttribute(gemm_hmma1<1>, cudaFuncAttributeMaxDynamicSharedMemorySize, G_SMEM);

    const dim3 blk(256);
    const dim3 tblk(32, 8);
    const long long psz = (long long)BSZ * E_;

    // 1) x -> fp16
    split_kernel<<<(BSZ * E_ + 255) / 256, 256>>>(x, xh, BSZ * E_);
    // 2) QKV weights packed convert-transpose
    { dim3 g(INNER_/32, E_/32, 3); wconv_qkv<<<g, tblk>>>(Wq, Wk, Wv, wqkv); }
    // 3) Wo/W1/W2
    { dim3 g(64, 64, 3); wconv_misc<<<g, tblk>>>(Wo, W1, W2, woT, w1T, w2T); }
    // 4) fused QKV projection: [4096,256] @ [256,6144]
    {
        dim3 grd(QKVW_/128, BSZ/128, 1);
        gemm_hmma1<1><<<grd, blk, G_SMEM>>>(xh, E_, wqkv, E_,
            nullptr, qkvh, QKVW_, E_, 1, 0,0, 0,0, 0,0,
            nullptr, 1.f, 0);
    }
    // 5) V^T per (b,h)
    { dim3 g(S_/32, DH_/32, B_*H_); vtrans_kernel<<<g, tblk>>>(qkvh, vth); }
    // 6) flash attention
    {
        dim3 grd(S_/QBLK, B_*H_);
        flash_kernel<<<grd, blk, F_SMEM>>>(qkvh, vth, oh);
    }
    // 7) Wo split-K x4 -> partials ; LN1 reduce (+x resid)
    {
        dim3 grd(E_/128, BSZ/128, 4);
        gemm_hmma1<0><<<grd, blk, G_SMEM>>>(oh, INNER_, woT, INNER_,
            part, nullptr, E_, INNER_/4, 4,
            0, 512, 0, 512, 0, psz,
            nullptr, 1.f, 0);
        ln_red_kernel<<<BSZ/8, 256>>>(part, psz, nullptr, x, ln1g, ln1b, hf, hh);
    }
    // 8) ff = relu(h @ W1 + b1)
    {
        dim3 grd(DFF_/128, BSZ/128, 1);
        gemm_hmma1<1><<<grd, blk, G_SMEM>>>(hh, E_, w1T, E_,
            nullptr, ffh, DFF_, E_, 1, 0,0, 0,0, 0,0,
            b1, 1.f, 1);
    }
    // 9) FFN2 split-K x4 -> partials ; LN2 reduce (+b2 +h resid) -> out
    {
        dim3 grd(E_/128, BSZ/128, 4);
        gemm_hmma1<0><<<grd, blk, G_SMEM>>>(ffh, DFF_, w2T, DFF_,
            part, nullptr, E_, DFF_/4, 4,
            0, 256, 0, 256, 0, psz,
            nullptr, 1.f, 0);
        ln_red_kernel<<<BSZ/8, 256>>>(part, psz, b2, hf, ln2g, ln2b,
                                      (float*)d_out, nullptr);
    }
}